// round 9
// baseline (speedup 1.0000x reference)
#include <cuda_runtime.h>
#include <cuda_bf16.h>
#include <math.h>
#include <stdint.h>

#define B_ 64
#define T_ 512
#define H_ 1024
#define E_ 512
#define V_ 32000
#define M_BT (B_ * T_)        // 32768

// ---------------- scratch (device globals; no allocation allowed) ----------------
__device__ float g_rnn_in[B_ * (E_ + H_)];        // [64, 1536]
__device__ float g_bias_aT[H_ * B_];              // [1024, 64]
__device__ float g_scores[M_BT];
__device__ float g_cat2[B_ * 2 * H_];             // [h_new | context]
__device__ float g_part_bias[8 * B_ * H_];
__device__ float g_part_gi[8 * B_ * 3 * H_];
__device__ float g_part_gh[8 * B_ * 3 * H_];
__device__ __nv_bfloat16 g_w_hi[H_ * H_];         // 2 MB
__device__ __nv_bfloat16 g_w_lo[H_ * H_];         // 2 MB

// ======================= helpers =======================
__device__ __forceinline__ uint32_t smem_u32(const void* p) {
    uint32_t a;
    asm("{ .reg .u64 t; cvta.to.shared.u64 t, %1; cvt.u32.u64 %0, t; }" : "=r"(a) : "l"(p));
    return a;
}
#define CP_ASYNC16(dst, src) \
    asm volatile("cp.async.cg.shared.global [%0], [%1], 16;" :: "r"(dst), "l"(src))
#define CP_COMMIT() asm volatile("cp.async.commit_group;" ::: "memory")
#define CP_WAIT2() asm volatile("cp.async.wait_group 2;" ::: "memory")
#define CP_WAIT1() asm volatile("cp.async.wait_group 1;" ::: "memory")
#define CP_WAIT0() asm volatile("cp.async.wait_group 0;" ::: "memory")

__device__ __forceinline__ void ldmx4(uint32_t* r, uint32_t addr) {
    asm volatile("ldmatrix.sync.aligned.m8n8.x4.shared.b16 {%0,%1,%2,%3}, [%4];"
                 : "=r"(r[0]), "=r"(r[1]), "=r"(r[2]), "=r"(r[3]) : "r"(addr));
}
__device__ __forceinline__ void mma16816(float* d, const uint32_t* a, uint32_t b0, uint32_t b1) {
    asm volatile("mma.sync.aligned.m16n8k16.row.col.f32.bf16.bf16.f32 "
                 "{%0,%1,%2,%3}, {%4,%5,%6,%7}, {%8,%9}, {%0,%1,%2,%3};"
                 : "+f"(d[0]), "+f"(d[1]), "+f"(d[2]), "+f"(d[3])
                 : "r"(a[0]), "r"(a[1]), "r"(a[2]), "r"(a[3]), "r"(b0), "r"(b1));
}
// fp32 quad -> bf16 hi/lo quads (8 bytes each)
__device__ __forceinline__ void cvt_hl(float4 x, uint2* hq, uint2* lq) {
    __align__(8) __nv_bfloat16 h[4];
    __align__(8) __nv_bfloat16 l[4];
    float xs[4] = {x.x, x.y, x.z, x.w};
    #pragma unroll
    for (int j = 0; j < 4; j++) {
        h[j] = __float2bfloat16(xs[j]);
        l[j] = __float2bfloat16(xs[j] - __bfloat162float(h[j]));
    }
    *hq = *reinterpret_cast<uint2*>(h);
    *lq = *reinterpret_cast<uint2*>(l);
}

// ======================= tiling constants =======================
#define KSTEP 32
#define ROWB 80
#define TILE_A (128 * ROWB)           // 10240
// energy: B via cp.async (4 stages), A fp32->bf16 inline (2 stages)
#define EN_B_STAGE (2 * TILE_A)       // 20480 (whi|wlo)
#define EN_ABUF_OFF (4 * EN_B_STAGE)  // 81920
#define EN_ABUF_SZ (2 * TILE_A)       // 20480 (ahi|alo)
#define EN_RED_OFF (EN_ABUF_OFF + 2 * EN_ABUF_SZ)   // 122880
#define SMEM_ENERGY (EN_RED_OFF + 512 * 4)          // 124928
// fc: BN=64, all operands fp32->bf16 inline, 2 stages
#define FC_T (64 * ROWB)              // 5120
#define FC_AHI 0
#define FC_ALO FC_T
#define FC_BHI (2 * FC_T)
#define FC_BLO (3 * FC_T)
#define FC_STAGE (4 * FC_T)           // 20480
#define SMEM_FC (2 * FC_STAGE)        // 40960

// ---------------- split attn_W[:, H:] -> bf16 hi/lo (2 MB, cheap) ----------------
__global__ void split_w_k(const float* __restrict__ attnW,
                          __nv_bfloat16* __restrict__ hi,
                          __nv_bfloat16* __restrict__ lo) {
    int i = blockIdx.x * blockDim.x + threadIdx.x;   // < H_*H_/4
    int r = i >> 8;
    int k4 = i & 255;
    const float4* src = reinterpret_cast<const float4*>(attnW + (size_t)r * (2 * H_) + H_) + k4;
    uint2 h, l;
    cvt_hl(*src, &h, &l);
    *reinterpret_cast<uint2*>(hi + 4 * (size_t)i) = h;
    *reinterpret_cast<uint2*>(lo + 4 * (size_t)i) = l;
}

// ---------------- embedding gather ----------------
__global__ void gather_emb_k(const int* __restrict__ x,
                             const float* __restrict__ embW,
                             float* __restrict__ rnn_in) {
    int b = blockIdx.x;
    int row = x[b];
    for (int e = threadIdx.x; e < E_; e += blockDim.x)
        rnn_in[b * (E_ + H_) + e] = embW[(size_t)row * E_ + e];
}

// ---------------- K-split M=64 GEMM ----------------
__global__ void gemm_m64_ks(const float* __restrict__ A, int lda,
                            const float* __restrict__ W, int ldw,
                            float* __restrict__ Cp, int ldc, int kc) {
    __shared__ float As[16][64];
    __shared__ float Ws[16][64];
    const int tid = threadIdx.x;
    const int n0 = blockIdx.x * 64;
    const int kk0 = blockIdx.y * kc;
    const int lrow = tid >> 2;
    const int kq = (tid & 3) * 4;
    const int ty = tid >> 4;
    const int tx = tid & 15;

    float acc[4][4] = {};
    for (int kk = kk0; kk < kk0 + kc; kk += 16) {
        float4 av = *(const float4*)&A[lrow * lda + kk + kq];
        float4 wv = *(const float4*)&W[(size_t)(n0 + lrow) * ldw + kk + kq];
        __syncthreads();
        As[kq + 0][lrow] = av.x; As[kq + 1][lrow] = av.y;
        As[kq + 2][lrow] = av.z; As[kq + 3][lrow] = av.w;
        Ws[kq + 0][lrow] = wv.x; Ws[kq + 1][lrow] = wv.y;
        Ws[kq + 2][lrow] = wv.z; Ws[kq + 3][lrow] = wv.w;
        __syncthreads();
        #pragma unroll
        for (int k = 0; k < 16; k++) {
            float4 a = *(const float4*)&As[k][ty * 4];
            float4 w = *(const float4*)&Ws[k][tx * 4];
            float af[4] = {a.x, a.y, a.z, a.w};
            float wf[4] = {w.x, w.y, w.z, w.w};
            #pragma unroll
            for (int i = 0; i < 4; i++)
                #pragma unroll
                for (int j = 0; j < 4; j++)
                    acc[i][j] = fmaf(af[i], wf[j], acc[i][j]);
        }
    }
    #pragma unroll
    for (int i = 0; i < 4; i++) {
        int m = blockIdx.y * 64 + ty * 4 + i;
        #pragma unroll
        for (int j = 0; j < 4; j++)
            Cp[(size_t)m * ldc + n0 + tx * 4 + j] = acc[i][j];
    }
}

// ---------------- bias partial reduce + transpose ----------------
__global__ void bias_redT_k(const float* __restrict__ part,
                            const float* __restrict__ attb,
                            float* __restrict__ biasT) {
    int idx = blockIdx.x * 256 + threadIdx.x;
    int b = idx >> 10, h = idx & 1023;
    float s = attb[h];
    #pragma unroll
    for (int ks = 0; ks < 8; ks++)
        s += part[(size_t)((ks << 6) + b) * H_ + h];
    biasT[h * B_ + b] = s;
}

// ---------------- energy GEMM (enc fp32 converted inline) ----------------
__global__ void __launch_bounds__(256, 1)
energy_mma_k(const float* __restrict__ enc,
             const __nv_bfloat16* __restrict__ whi, const __nv_bfloat16* __restrict__ wlo,
             const float* __restrict__ biasT, const float* __restrict__ v,
             float* __restrict__ scores) {
    extern __shared__ char sm[];
    const uint32_t sb = smem_u32(sm);
    float* red = (float*)(sm + EN_RED_OFF);

    const int tid = threadIdx.x;
    const int wid = tid >> 5;
    const int lane = tid & 31;
    const int m0 = blockIdx.x * 128;
    const int mw = wid >> 2;
    const int nw = wid & 3;

    const int a_l = lane & 15;
    const int a_kh = (lane >> 4) << 3;
    const int b_nb = (lane & 7) + ((lane >> 4) << 3);
    const int b_kh = ((lane >> 3) & 1) << 3;
    const int g = lane >> 2;
    const int t2 = (lane & 3) << 1;

    float acc[4][4][4];
    float rowsum[8];
    #pragma unroll
    for (int i = 0; i < 8; i++) rowsum[i] = 0.f;

    const int total_it = 8 * 32;
    // A (enc fp32) load map: 128 rows x 8 fp32-quads = 1024 chunks, 4 per thread
    const int ar[4] = {tid >> 3, (tid + 256) >> 3, (tid + 512) >> 3, (tid + 768) >> 3};
    const int ac = tid & 7;
    float4 Ar[4];

    #define EN_LDGA(it_) do {                                                       \
        int kb_ = ((it_) & 31) * KSTEP;                                             \
        _Pragma("unroll")                                                           \
        for (int j = 0; j < 4; j++)                                                 \
            Ar[j] = *(const float4*)&enc[(size_t)(m0 + ar[j]) * H_ + kb_ + ac * 4]; \
    } while (0)

    #define EN_STSA(it_) do {                                                       \
        char* ab_ = sm + EN_ABUF_OFF + ((it_) & 1) * EN_ABUF_SZ;                    \
        _Pragma("unroll")                                                           \
        for (int j = 0; j < 4; j++) {                                               \
            uint2 hq_, lq_;                                                         \
            cvt_hl(Ar[j], &hq_, &lq_);                                              \
            *reinterpret_cast<uint2*>(ab_ + ar[j] * ROWB + ac * 8) = hq_;           \
            *reinterpret_cast<uint2*>(ab_ + TILE_A + ar[j] * ROWB + ac * 8) = lq_;  \
        }                                                                           \
    } while (0)

    #define EN_CPB(it_) do {                                                        \
        int chunk_ = (it_) >> 5;                                                    \
        int kb_ = ((it_) & 31) * KSTEP;                                             \
        uint32_t stg_ = sb + ((it_) & 3) * EN_B_STAGE;                              \
        _Pragma("unroll")                                                           \
        for (int j = 0; j < 4; j++) {                                               \
            int id = tid + (j << 8);                                                \
            int tl = id >> 9; int cc = id & 511; int r = cc >> 2; int c = cc & 3;   \
            const __nv_bfloat16* gw = tl ? wlo : whi;                               \
            CP_ASYNC16(stg_ + tl * TILE_A + r * ROWB + c * 16,                      \
                       gw + (size_t)(chunk_ * 128 + r) * H_ + kb_ + c * 8);         \
        }                                                                           \
        CP_COMMIT();                                                                \
    } while (0)

    EN_LDGA(0);
    EN_CPB(0);
    EN_CPB(1);

    for (int it = 0; it < total_it; it++) {
        const int kt = it & 31;
        const int chunk = it >> 5;
        if (kt == 0) {
            #pragma unroll
            for (int mt = 0; mt < 4; mt++)
                #pragma unroll
                for (int nt = 0; nt < 4; nt++)
                    #pragma unroll
                    for (int k = 0; k < 4; k++) acc[mt][nt][k] = 0.f;
        }
        __syncthreads();            // all reads of Abuf[it&1] (iter it-2) + B stage done
        EN_STSA(it);
        if (it + 1 < total_it) EN_LDGA(it + 1);
        if (it + 2 < total_it) { EN_CPB(it + 2); CP_WAIT2(); }
        else if (it + 1 < total_it) { CP_WAIT1(); }
        else { CP_WAIT0(); }
        __syncthreads();            // A STS + B arrival visible to all warps

        const uint32_t aHiB = sb + EN_ABUF_OFF + (it & 1) * EN_ABUF_SZ;
        const uint32_t aLoB = aHiB + TILE_A;
        const uint32_t bHiB = sb + (it & 3) * EN_B_STAGE;
        const uint32_t bLoB = bHiB + TILE_A;

        #pragma unroll
        for (int ks = 0; ks < 2; ks++) {
            uint32_t Ahi[4][4], Alo[4][4];
            #pragma unroll
            for (int mt = 0; mt < 4; mt++) {
                uint32_t off = (uint32_t)((mw * 64 + mt * 16 + a_l) * ROWB + (ks * 16 + a_kh) * 2);
                ldmx4(Ahi[mt], aHiB + off);
                ldmx4(Alo[mt], aLoB + off);
            }
            uint32_t Bhi[2][4], Blo[2][4];
            #pragma unroll
            for (int np = 0; np < 2; np++) {
                uint32_t off = (uint32_t)((nw * 32 + np * 16 + b_nb) * ROWB + (ks * 16 + b_kh) * 2);
                ldmx4(Bhi[np], bHiB + off);
                ldmx4(Blo[np], bLoB + off);
            }
            #pragma unroll
            for (int mt = 0; mt < 4; mt++)
                #pragma unroll
                for (int nt = 0; nt < 4; nt++) {
                    const int np = nt >> 1, pr = (nt & 1) * 2;
                    mma16816(acc[mt][nt], Ahi[mt], Bhi[np][pr], Bhi[np][pr + 1]);
                    mma16816(acc[mt][nt], Ahi[mt], Blo[np][pr], Blo[np][pr + 1]);
                    mma16816(acc[mt][nt], Alo[mt], Bhi[np][pr], Bhi[np][pr + 1]);
                }
        }

        if (kt == 31) {
            #pragma unroll
            for (int nt = 0; nt < 4; nt++) {
                const int col0 = chunk * 128 + nw * 32 + nt * 8 + t2;
                const float v0 = __ldg(&v[col0]);
                const float v1 = __ldg(&v[col0 + 1]);
                #pragma unroll
                for (int mt = 0; mt < 4; mt++) {
                    #pragma unroll
                    for (int i = 0; i < 2; i++) {
                        const int row = mw * 64 + mt * 16 + g + i * 8;
                        const int b = row & (B_ - 1);
                        float e0 = acc[mt][nt][i * 2 + 0] + __ldg(&biasT[(size_t)col0 * B_ + b]);
                        float e1 = acc[mt][nt][i * 2 + 1] + __ldg(&biasT[(size_t)(col0 + 1) * B_ + b]);
                        rowsum[mt * 2 + i] += fmaxf(e0, 0.f) * v0 + fmaxf(e1, 0.f) * v1;
                    }
                }
            }
        }
    }

    #pragma unroll
    for (int k = 0; k < 8; k++) {
        rowsum[k] += __shfl_xor_sync(0xFFFFFFFF, rowsum[k], 1);
        rowsum[k] += __shfl_xor_sync(0xFFFFFFFF, rowsum[k], 2);
    }
    __syncthreads();
    if ((lane & 3) == 0) {
        #pragma unroll
        for (int mt = 0; mt < 4; mt++)
            #pragma unroll
            for (int i = 0; i < 2; i++)
                red[nw * 128 + mw * 64 + mt * 16 + g + i * 8] = rowsum[mt * 2 + i];
    }
    __syncthreads();
    if (tid < 128) {
        float s = red[tid] + red[128 + tid] + red[256 + tid] + red[384 + tid];
        scores[m0 + tid] = s;
    }
    #undef EN_LDGA
    #undef EN_STSA
    #undef EN_CPB
}

// ---------------- fc GEMM: BN=64, inline fp32->bf16, occ 3 ----------------
__global__ void __launch_bounds__(256, 3)
fc_mma_k(const float* __restrict__ cat2, const float* __restrict__ fcW,
         const float* __restrict__ fcb, float* __restrict__ logits) {
    extern __shared__ char sm[];
    const uint32_t sb = smem_u32(sm);

    const int tid = threadIdx.x;
    const int wid = tid >> 5;
    const int lane = tid & 31;
    const int n0 = blockIdx.x * 64;
    const int mw = wid >> 2;       // 0..1: rows mw*32
    const int nw = wid & 3;        // 0..3: cols nw*16

    const int a_l = lane & 15;
    const int a_kh = (lane >> 4) << 3;
    const int b_nb = (lane & 7) + ((lane >> 4) << 3);
    const int b_kh = ((lane >> 3) & 1) << 3;
    const int g = lane >> 2;
    const int t2 = (lane & 3) << 1;

    float acc[2][2][4];
    #pragma unroll
    for (int mt = 0; mt < 2; mt++)
        #pragma unroll
        for (int nt = 0; nt < 2; nt++)
            #pragma unroll
            for (int k = 0; k < 4; k++) acc[mt][nt][k] = 0.f;

    // A and B each: 64 rows x 8 fp32-quads = 512 chunks, 2 per thread
    const int ro[2] = {tid >> 3, (tid + 256) >> 3};
    const int qc = tid & 7;
    float4 Ar[2], Br[2];

    #define FC_LDG(it_) do {                                                        \
        int kb_ = (it_) * KSTEP;                                                    \
        _Pragma("unroll")                                                           \
        for (int j = 0; j < 2; j++) {                                               \
            Ar[j] = *(const float4*)&cat2[(size_t)ro[j] * (2 * H_) + kb_ + qc * 4]; \
            Br[j] = *(const float4*)&fcW[(size_t)(n0 + ro[j]) * (2 * H_) + kb_ + qc * 4]; \
        }                                                                           \
    } while (0)

    #define FC_STS(it_) do {                                                        \
        char* st_ = sm + ((it_) & 1) * FC_STAGE;                                    \
        _Pragma("unroll")                                                           \
        for (int j = 0; j < 2; j++) {                                               \
            uint2 hq_, lq_;                                                         \
            cvt_hl(Ar[j], &hq_, &lq_);                                              \
            *reinterpret_cast<uint2*>(st_ + FC_AHI + ro[j] * ROWB + qc * 8) = hq_;  \
            *reinterpret_cast<uint2*>(st_ + FC_ALO + ro[j] * ROWB + qc * 8) = lq_;  \
            cvt_hl(Br[j], &hq_, &lq_);                                              \
            *reinterpret_cast<uint2*>(st_ + FC_BHI + ro[j] * ROWB + qc * 8) = hq_;  \
            *reinterpret_cast<uint2*>(st_ + FC_BLO + ro[j] * ROWB + qc * 8) = lq_;  \
        }                                                                           \
    } while (0)

    const int total_it = 64;
    FC_LDG(0);

    for (int it = 0; it < total_it; it++) {
        __syncthreads();
        FC_STS(it);
        if (it + 1 < total_it) FC_LDG(it + 1);
        __syncthreads();

        const uint32_t stg = sb + (it & 1) * FC_STAGE;
        #pragma unroll
        for (int ks = 0; ks < 2; ks++) {
            uint32_t Ahi[2][4], Alo[2][4];
            #pragma unroll
            for (int mt = 0; mt < 2; mt++) {
                uint32_t off = (uint32_t)((mw * 32 + mt * 16 + a_l) * ROWB + (ks * 16 + a_kh) * 2);
                ldmx4(Ahi[mt], stg + FC_AHI + off);
                ldmx4(Alo[mt], stg + FC_ALO + off);
            }
            uint32_t Bhi[4], Blo[4];
            {
                uint32_t off = (uint32_t)((nw * 16 + b_nb) * ROWB + (ks * 16 + b_kh) * 2);
                ldmx4(Bhi, stg + FC_BHI + off);
                ldmx4(Blo, stg + FC_BLO + off);
            }
            #pragma unroll
            for (int mt = 0; mt < 2; mt++)
                #pragma unroll
                for (int nt = 0; nt < 2; nt++) {
                    const int pr = nt * 2;
                    mma16816(acc[mt][nt], Ahi[mt], Bhi[pr], Bhi[pr + 1]);
                    mma16816(acc[mt][nt], Ahi[mt], Blo[pr], Blo[pr + 1]);
                    mma16816(acc[mt][nt], Alo[mt], Bhi[pr], Bhi[pr + 1]);
                }
        }
    }

    #pragma unroll
    for (int nt = 0; nt < 2; nt++) {
        const int col0 = n0 + nw * 16 + nt * 8 + t2;
        const float c0 = __ldg(&fcb[col0]);
        const float c1 = __ldg(&fcb[col0 + 1]);
        #pragma unroll
        for (int mt = 0; mt < 2; mt++) {
            #pragma unroll
            for (int i = 0; i < 2; i++) {
                const int row = mw * 32 + mt * 16 + g + i * 8;
                float2 o;
                o.x = acc[mt][nt][i * 2 + 0] + c0;
                o.y = acc[mt][nt][i * 2 + 1] + c1;
                *reinterpret_cast<float2*>(&logits[(size_t)row * V_ + col0]) = o;
            }
        }
    }
    #undef FC_LDG
    #undef FC_STS
}

// ---------------- softmax over T ----------------
__global__ void softmax_k(const float* __restrict__ scores,
                          float* __restrict__ attn_w_out) {
    int b = blockIdx.x;
    int t = threadIdx.x;
    __shared__ float sh[512];
    float s = scores[t * B_ + b];
    sh[t] = s;
    __syncthreads();
    for (int off = 256; off > 0; off >>= 1) {
        if (t < off) sh[t] = fmaxf(sh[t], sh[t + off]);
        __syncthreads();
    }
    float mx = sh[0];
    __syncthreads();
    float e = expf(s - mx);
    sh[t] = e;
    __syncthreads();
    for (int off = 256; off > 0; off >>= 1) {
        if (t < off) sh[t] += sh[t + off];
        __syncthreads();
    }
    attn_w_out[b * T_ + t] = e / sh[0];
}

// ---------------- context = attn_w @ enc (float4, unroll 8) ----------------
__global__ void context_k(const float4* __restrict__ enc4,
                          const float* __restrict__ attn_w,
                          float* __restrict__ rnn_in,
                          float* __restrict__ cat2) {
    int b = blockIdx.y;
    int h4 = blockIdx.x * 128 + threadIdx.x;
    __shared__ float w[T_];
    for (int t = threadIdx.x; t < T_; t += 128) w[t] = attn_w[b * T_ + t];
    __syncthreads();
    float4 acc = {0.f, 0.f, 0.f, 0.f};
    #pragma unroll 8
    for (int t = 0; t < T_; t++) {
        float4 e = enc4[(size_t)(t * B_ + b) * (H_ / 4) + h4];
        float wt = w[t];
        acc.x = fmaf(wt, e.x, acc.x);
        acc.y = fmaf(wt, e.y, acc.y);
        acc.z = fmaf(wt, e.z, acc.z);
        acc.w = fmaf(wt, e.w, acc.w);
    }
    int h = h4 * 4;
    *reinterpret_cast<float4*>(&rnn_in[b * (E_ + H_) + E_ + h]) = acc;
    *reinterpret_cast<float4*>(&cat2[b * (2 * H_) + H_ + h]) = acc;
}

// ---------------- GRU gates (reduce 8 k-split partials) ----------------
__global__ void gates_k(const float* __restrict__ pgi,
                        const float* __restrict__ pgh,
                        const float* __restrict__ bih,
                        const float* __restrict__ bhh,
                        const float* __restrict__ lh,
                        float* __restrict__ hnew_out,
                        float* __restrict__ cat2) {
    int b = blockIdx.x;
    for (int h = threadIdx.x; h < H_; h += blockDim.x) {
        float gi0 = bih[h], gi1 = bih[H_ + h], gi2 = bih[2 * H_ + h];
        float gh0 = bhh[h], gh1 = bhh[H_ + h], gh2 = bhh[2 * H_ + h];
        #pragma unroll
        for (int ks = 0; ks < 8; ks++) {
            size_t base = (size_t)((ks << 6) + b) * 3 * H_;
            gi0 += pgi[base + h]; gi1 += pgi[base + H_ + h]; gi2 += pgi[base + 2 * H_ + h];
            gh0 += pgh[base + h]; gh1 += pgh[base + H_ + h]; gh2 += pgh[base + 2 * H_ + h];
        }
        float r = 1.f / (1.f + expf(-(gi0 + gh0)));
        float z = 1.f / (1.f + expf(-(gi1 + gh1)));
        float n = tanhf(gi2 + r * gh2);
        float hp = lh[b * H_ + h];
        float hn = (1.f - z) * n + z * hp;
        hnew_out[b * H_ + h] = hn;
        cat2[b * (2 * H_) + h] = hn;
    }
}

// ---------------- log_softmax in-place ----------------
__global__ void logsoftmax_k(float* __restrict__ logits) {
    int b = blockIdx.x;
    int tid = threadIdx.x;
    __shared__ float sh[1024];
    float* row = logits + (size_t)b * V_;
    float mx = -1e30f;
    for (int n = tid; n < V_; n += 1024) mx = fmaxf(mx, row[n]);
    sh[tid] = mx;
    __syncthreads();
    for (int off = 512; off > 0; off >>= 1) {
        if (tid < off) sh[tid] = fmaxf(sh[tid], sh[tid + off]);
        __syncthreads();
    }
    mx = sh[0];
    __syncthreads();
    float sum = 0.f;
    for (int n = tid; n < V_; n += 1024) sum += expf(row[n] - mx);
    sh[tid] = sum;
    __syncthreads();
    for (int off = 512; off > 0; off >>= 1) {
        if (tid < off) sh[tid] += sh[tid + off];
        __syncthreads();
    }
    float lse = mx + logf(sh[0]);
    for (int n = tid; n < V_; n += 1024) row[n] -= lse;
}

// ---------------- launch ----------------
extern "C" void kernel_launch(void* const* d_in, const int* in_sizes, int n_in,
                              void* d_out, int out_size) {
    const int*   x    = (const int*)d_in[0];
    const float* lh   = (const float*)d_in[1];
    const float* enc  = (const float*)d_in[2];
    const float* embW = (const float*)d_in[3];
    const float* attW = (const float*)d_in[4];
    const float* attb = (const float*)d_in[5];
    const float* v    = (const float*)d_in[6];
    const float* Wih  = (const float*)d_in[7];
    const float* Whh  = (const float*)d_in[8];
    const float* bih  = (const float*)d_in[9];
    const float* bhh  = (const float*)d_in[10];
    const float* fcW  = (const float*)d_in[11];
    const float* fcb  = (const float*)d_in[12];

    float* out      = (float*)d_out;
    float* out_logp = out;
    float* out_h    = out + (size_t)B_ * V_;
    float* out_w    = out_h + (size_t)B_ * H_;

    float *rnn_in, *bias_aT, *scoresp, *cat2, *pbias, *pgi, *pgh;
    __nv_bfloat16 *whi, *wlo;
    cudaGetSymbolAddress((void**)&rnn_in,  g_rnn_in);
    cudaGetSymbolAddress((void**)&bias_aT, g_bias_aT);
    cudaGetSymbolAddress((void**)&scoresp, g_scores);
    cudaGetSymbolAddress((void**)&cat2,    g_cat2);
    cudaGetSymbolAddress((void**)&pbias,   g_part_bias);
    cudaGetSymbolAddress((void**)&pgi,     g_part_gi);
    cudaGetSymbolAddress((void**)&pgh,     g_part_gh);
    cudaGetSymbolAddress((void**)&whi,     g_w_hi);
    cudaGetSymbolAddress((void**)&wlo,     g_w_lo);

    cudaFuncSetAttribute(energy_mma_k, cudaFuncAttributeMaxDynamicSharedMemorySize, SMEM_ENERGY);
    cudaFuncSetAttribute(fc_mma_k, cudaFuncAttributeMaxDynamicSharedMemorySize, SMEM_FC);

    // launch order arranged so energy_mma_k is launch #4 (ncu captures the 4th launch)
    split_w_k<<<(H_ * H_ / 4) / 256, 256>>>(attW, whi, wlo);                          // 1
    gemm_m64_ks<<<dim3(H_ / 64, 8), 256>>>(lh, H_, attW, 2 * H_, pbias, H_, 128);     // 2
    bias_redT_k<<<(B_ * H_) / 256, 256>>>(pbias, attb, bias_aT);                      // 3
    energy_mma_k<<<M_BT / 128, 256, SMEM_ENERGY>>>(enc, whi, wlo, bias_aT, v, scoresp); // 4
    gather_emb_k<<<B_, 128>>>(x, embW, rnn_in);                                       // 5 (independent)
    softmax_k<<<B_, 512>>>(scoresp, out_w);
    context_k<<<dim3(2, B_), 128>>>((const float4*)enc, out_w, rnn_in, cat2);
    gemm_m64_ks<<<dim3(3 * H_ / 64, 8), 256>>>(rnn_in, E_ + H_, Wih, E_ + H_, pgi, 3 * H_, 192);
    gemm_m64_ks<<<dim3(3 * H_ / 64, 8), 256>>>(lh, H_, Whh, H_, pgh, 3 * H_, 128);
    gates_k<<<B_, 256>>>(pgi, pgh, bih, bhh, lh, out_h, cat2);
    fc_mma_k<<<V_ / 64, 256, SMEM_FC>>>(cat2, fcW, fcb, out_logp);
    logsoftmax_k<<<B_, 1024>>>(out_logp);
}

// round 10
// speedup vs baseline: 1.0197x; 1.0197x over previous
#include <cuda_runtime.h>
#include <cuda_bf16.h>
#include <math.h>
#include <stdint.h>

#define B_ 64
#define T_ 512
#define H_ 1024
#define E_ 512
#define V_ 32000
#define M_BT (B_ * T_)        // 32768

// ---------------- scratch (device globals; no allocation allowed) ----------------
__device__ float g_rnn_in[B_ * (E_ + H_)];        // [64, 1536]
__device__ float g_bias_aT[H_ * B_];              // [1024, 64]
__device__ float g_scores[M_BT];
__device__ float g_cat2[B_ * 2 * H_];             // [h_new | context]
__device__ float g_part_bias[8 * B_ * H_];
__device__ float g_part_gi[8 * B_ * 3 * H_];
__device__ float g_part_gh[8 * B_ * 3 * H_];
__device__ __nv_bfloat16 g_w_hi[H_ * H_];         // 2 MB
__device__ __nv_bfloat16 g_w_lo[H_ * H_];         // 2 MB

// ======================= helpers =======================
__device__ __forceinline__ uint32_t smem_u32(const void* p) {
    uint32_t a;
    asm("{ .reg .u64 t; cvta.to.shared.u64 t, %1; cvt.u32.u64 %0, t; }" : "=r"(a) : "l"(p));
    return a;
}
#define CP_ASYNC16(dst, src) \
    asm volatile("cp.async.cg.shared.global [%0], [%1], 16;" :: "r"(dst), "l"(src))
#define CP_COMMIT() asm volatile("cp.async.commit_group;" ::: "memory")
#define CP_WAIT2() asm volatile("cp.async.wait_group 2;" ::: "memory")
#define CP_WAIT1() asm volatile("cp.async.wait_group 1;" ::: "memory")
#define CP_WAIT0() asm volatile("cp.async.wait_group 0;" ::: "memory")

__device__ __forceinline__ void ldmx4(uint32_t* r, uint32_t addr) {
    asm volatile("ldmatrix.sync.aligned.m8n8.x4.shared.b16 {%0,%1,%2,%3}, [%4];"
                 : "=r"(r[0]), "=r"(r[1]), "=r"(r[2]), "=r"(r[3]) : "r"(addr));
}
__device__ __forceinline__ void mma16816(float* d, const uint32_t* a, uint32_t b0, uint32_t b1) {
    asm volatile("mma.sync.aligned.m16n8k16.row.col.f32.bf16.bf16.f32 "
                 "{%0,%1,%2,%3}, {%4,%5,%6,%7}, {%8,%9}, {%0,%1,%2,%3};"
                 : "+f"(d[0]), "+f"(d[1]), "+f"(d[2]), "+f"(d[3])
                 : "r"(a[0]), "r"(a[1]), "r"(a[2]), "r"(a[3]), "r"(b0), "r"(b1));
}
// fp32 quad -> bf16 hi/lo quads (8 bytes each)
__device__ __forceinline__ void cvt_hl(float4 x, uint2* hq, uint2* lq) {
    __align__(8) __nv_bfloat16 h[4];
    __align__(8) __nv_bfloat16 l[4];
    float xs[4] = {x.x, x.y, x.z, x.w};
    #pragma unroll
    for (int j = 0; j < 4; j++) {
        h[j] = __float2bfloat16(xs[j]);
        l[j] = __float2bfloat16(xs[j] - __bfloat162float(h[j]));
    }
    *hq = *reinterpret_cast<uint2*>(h);
    *lq = *reinterpret_cast<uint2*>(l);
}

// ======================= tiling constants =======================
#define KSTEP 32
#define ROWB 80
#define TILE_A (128 * ROWB)           // 10240
// energy v2: chunk=64 cols, 2 CTAs/SM. B: 3-stage ring of 64-row tiles; A: 2-stage convert buf
#define EN_BT (64 * ROWB)             // 5120 per operand tile
#define EN_B_STAGE (2 * EN_BT)        // 10240 (whi|wlo)
#define EN_NSTAGE 3
#define EN_ABUF_OFF (EN_NSTAGE * EN_B_STAGE)        // 30720
#define EN_ABUF_SZ (2 * TILE_A)                     // 20480 (ahi|alo)
#define EN_RED_OFF (EN_ABUF_OFF + 2 * EN_ABUF_SZ)   // 71680
#define SMEM_ENERGY (EN_RED_OFF + 512 * 4)          // 73728  (x2 CTAs = 147456)
// fc (round-7 proven version): BN=128, inline fp32->bf16, 2 stages, occ 2
#define FC_TA (64 * ROWB)             // 5120
#define FC_TB (128 * ROWB)            // 10240
#define FC_AHI 0
#define FC_ALO FC_TA
#define FC_BHI (2 * FC_TA)
#define FC_BLO (2 * FC_TA + FC_TB)
#define FC_STAGE (2 * FC_TA + 2 * FC_TB)   // 30720
#define SMEM_FC (2 * FC_STAGE)             // 61440

// ---------------- split attn_W[:, H:] -> bf16 hi/lo (2 MB, cheap) ----------------
__global__ void split_w_k(const float* __restrict__ attnW,
                          __nv_bfloat16* __restrict__ hi,
                          __nv_bfloat16* __restrict__ lo) {
    int i = blockIdx.x * blockDim.x + threadIdx.x;   // < H_*H_/4
    int r = i >> 8;
    int k4 = i & 255;
    const float4* src = reinterpret_cast<const float4*>(attnW + (size_t)r * (2 * H_) + H_) + k4;
    uint2 h, l;
    cvt_hl(*src, &h, &l);
    *reinterpret_cast<uint2*>(hi + 4 * (size_t)i) = h;
    *reinterpret_cast<uint2*>(lo + 4 * (size_t)i) = l;
}

// ---------------- embedding gather ----------------
__global__ void gather_emb_k(const int* __restrict__ x,
                             const float* __restrict__ embW,
                             float* __restrict__ rnn_in) {
    int b = blockIdx.x;
    int row = x[b];
    for (int e = threadIdx.x; e < E_; e += blockDim.x)
        rnn_in[b * (E_ + H_) + e] = embW[(size_t)row * E_ + e];
}

// ---------------- K-split M=64 GEMM ----------------
__global__ void gemm_m64_ks(const float* __restrict__ A, int lda,
                            const float* __restrict__ W, int ldw,
                            float* __restrict__ Cp, int ldc, int kc) {
    __shared__ float As[16][64];
    __shared__ float Ws[16][64];
    const int tid = threadIdx.x;
    const int n0 = blockIdx.x * 64;
    const int kk0 = blockIdx.y * kc;
    const int lrow = tid >> 2;
    const int kq = (tid & 3) * 4;
    const int ty = tid >> 4;
    const int tx = tid & 15;

    float acc[4][4] = {};
    for (int kk = kk0; kk < kk0 + kc; kk += 16) {
        float4 av = *(const float4*)&A[lrow * lda + kk + kq];
        float4 wv = *(const float4*)&W[(size_t)(n0 + lrow) * ldw + kk + kq];
        __syncthreads();
        As[kq + 0][lrow] = av.x; As[kq + 1][lrow] = av.y;
        As[kq + 2][lrow] = av.z; As[kq + 3][lrow] = av.w;
        Ws[kq + 0][lrow] = wv.x; Ws[kq + 1][lrow] = wv.y;
        Ws[kq + 2][lrow] = wv.z; Ws[kq + 3][lrow] = wv.w;
        __syncthreads();
        #pragma unroll
        for (int k = 0; k < 16; k++) {
            float4 a = *(const float4*)&As[k][ty * 4];
            float4 w = *(const float4*)&Ws[k][tx * 4];
            float af[4] = {a.x, a.y, a.z, a.w};
            float wf[4] = {w.x, w.y, w.z, w.w};
            #pragma unroll
            for (int i = 0; i < 4; i++)
                #pragma unroll
                for (int j = 0; j < 4; j++)
                    acc[i][j] = fmaf(af[i], wf[j], acc[i][j]);
        }
    }
    #pragma unroll
    for (int i = 0; i < 4; i++) {
        int m = blockIdx.y * 64 + ty * 4 + i;
        #pragma unroll
        for (int j = 0; j < 4; j++)
            Cp[(size_t)m * ldc + n0 + tx * 4 + j] = acc[i][j];
    }
}

// ---------------- bias partial reduce + transpose ----------------
__global__ void bias_redT_k(const float* __restrict__ part,
                            const float* __restrict__ attb,
                            float* __restrict__ biasT) {
    int idx = blockIdx.x * 256 + threadIdx.x;
    int b = idx >> 10, h = idx & 1023;
    float s = attb[h];
    #pragma unroll
    for (int ks = 0; ks < 8; ks++)
        s += part[(size_t)((ks << 6) + b) * H_ + h];
    biasT[h * B_ + b] = s;
}

// ---------------- energy GEMM v2: chunk=64, 2 CTAs/SM ----------------
__global__ void __launch_bounds__(256, 2)
energy_mma_k(const float* __restrict__ enc,
             const __nv_bfloat16* __restrict__ whi, const __nv_bfloat16* __restrict__ wlo,
             const float* __restrict__ biasT, const float* __restrict__ v,
             float* __restrict__ scores) {
    extern __shared__ char sm[];
    const uint32_t sb = smem_u32(sm);
    float* red = (float*)(sm + EN_RED_OFF);

    const int tid = threadIdx.x;
    const int wid = tid >> 5;
    const int lane = tid & 31;
    const int m0 = blockIdx.x * 128;
    const int mw = wid >> 2;       // 0..1: rows mw*64..+63
    const int nw = wid & 3;        // 0..3: cols nw*16..+15 within 64-col chunk

    const int a_l = lane & 15;
    const int a_kh = (lane >> 4) << 3;
    const int b_nb = (lane & 7) + ((lane >> 4) << 3);
    const int b_kh = ((lane >> 3) & 1) << 3;
    const int g = lane >> 2;
    const int t2 = (lane & 3) << 1;

    float acc[4][2][4];            // 32 regs: 4 m-tiles x 2 n-tiles
    float rowsum[8];
    #pragma unroll
    for (int i = 0; i < 8; i++) rowsum[i] = 0.f;

    const int total_it = 16 * 32;  // 16 chunks of 64 cols, 32 k-tiles each
    // A (enc fp32) load map: 128 rows x 8 fp32-quads = 1024 chunks, 4 per thread
    const int ar[4] = {tid >> 3, (tid + 256) >> 3, (tid + 512) >> 3, (tid + 768) >> 3};
    const int ac = tid & 7;
    float4 Ar[4];

    #define EN_LDGA(it_) do {                                                       \
        int kb_ = ((it_) & 31) * KSTEP;                                             \
        _Pragma("unroll")                                                           \
        for (int j = 0; j < 4; j++)                                                 \
            Ar[j] = *(const float4*)&enc[(size_t)(m0 + ar[j]) * H_ + kb_ + ac * 4]; \
    } while (0)

    #define EN_STSA(it_) do {                                                       \
        char* ab_ = sm + EN_ABUF_OFF + ((it_) & 1) * EN_ABUF_SZ;                    \
        _Pragma("unroll")                                                           \
        for (int j = 0; j < 4; j++) {                                               \
            uint2 hq_, lq_;                                                         \
            cvt_hl(Ar[j], &hq_, &lq_);                                              \
            *reinterpret_cast<uint2*>(ab_ + ar[j] * ROWB + ac * 8) = hq_;           \
            *reinterpret_cast<uint2*>(ab_ + TILE_A + ar[j] * ROWB + ac * 8) = lq_;  \
        }                                                                           \
    } while (0)

    // B: 64 rows x 32k x {hi,lo} = 512 x 16B, 2 per thread
    #define EN_CPB(it_) do {                                                        \
        int chunk_ = (it_) >> 5;                                                    \
        int kb_ = ((it_) & 31) * KSTEP;                                             \
        uint32_t stg_ = sb + ((it_) % EN_NSTAGE) * EN_B_STAGE;                      \
        _Pragma("unroll")                                                           \
        for (int j = 0; j < 2; j++) {                                               \
            int id = tid + (j << 8);                                                \
            int tl = id >> 8; int cc = id & 255; int r = cc >> 2; int c = cc & 3;   \
            const __nv_bfloat16* gw = tl ? wlo : whi;                               \
            CP_ASYNC16(stg_ + tl * EN_BT + r * ROWB + c * 16,                       \
                       gw + (size_t)(chunk_ * 64 + r) * H_ + kb_ + c * 8);          \
        }                                                                           \
        CP_COMMIT();                                                                \
    } while (0)

    EN_LDGA(0);
    EN_CPB(0);
    EN_CPB(1);

    for (int it = 0; it < total_it; it++) {
        const int kt = it & 31;
        const int chunk = it >> 5;
        if (kt == 0) {
            #pragma unroll
            for (int mt = 0; mt < 4; mt++)
                #pragma unroll
                for (int nt = 0; nt < 2; nt++)
                    #pragma unroll
                    for (int k = 0; k < 4; k++) acc[mt][nt][k] = 0.f;
        }
        __syncthreads();            // all reads of Abuf[it&1] (iter it-2) + B stage (it-1) done
        EN_STSA(it);
        if (it + 1 < total_it) EN_LDGA(it + 1);
        if (it + 2 < total_it) { EN_CPB(it + 2); CP_WAIT2(); }
        else if (it + 1 < total_it) { CP_WAIT1(); }
        else { CP_WAIT0(); }
        __syncthreads();            // A STS + B arrival visible to all warps

        const uint32_t aHiB = sb + EN_ABUF_OFF + (it & 1) * EN_ABUF_SZ;
        const uint32_t aLoB = aHiB + TILE_A;
        const uint32_t bHiB = sb + (it % EN_NSTAGE) * EN_B_STAGE;
        const uint32_t bLoB = bHiB + EN_BT;

        #pragma unroll
        for (int ks = 0; ks < 2; ks++) {
            uint32_t Ahi[4][4], Alo[4][4];
            #pragma unroll
            for (int mt = 0; mt < 4; mt++) {
                uint32_t off = (uint32_t)((mw * 64 + mt * 16 + a_l) * ROWB + (ks * 16 + a_kh) * 2);
                ldmx4(Ahi[mt], aHiB + off);
                ldmx4(Alo[mt], aLoB + off);
            }
            uint32_t Bhi[4], Blo[4];
            {
                uint32_t off = (uint32_t)((nw * 16 + b_nb) * ROWB + (ks * 16 + b_kh) * 2);
                ldmx4(Bhi, bHiB + off);
                ldmx4(Blo, bLoB + off);
            }
            #pragma unroll
            for (int mt = 0; mt < 4; mt++)
                #pragma unroll
                for (int nt = 0; nt < 2; nt++) {
                    const int pr = nt * 2;
                    mma16816(acc[mt][nt], Ahi[mt], Bhi[pr], Bhi[pr + 1]);
                    mma16816(acc[mt][nt], Ahi[mt], Blo[pr], Blo[pr + 1]);
                    mma16816(acc[mt][nt], Alo[mt], Bhi[pr], Bhi[pr + 1]);
                }
        }

        if (kt == 31) {
            #pragma unroll
            for (int nt = 0; nt < 2; nt++) {
                const int col0 = chunk * 64 + nw * 16 + nt * 8 + t2;
                const float v0 = __ldg(&v[col0]);
                const float v1 = __ldg(&v[col0 + 1]);
                #pragma unroll
                for (int mt = 0; mt < 4; mt++) {
                    #pragma unroll
                    for (int i = 0; i < 2; i++) {
                        const int row = mw * 64 + mt * 16 + g + i * 8;
                        const int b = row & (B_ - 1);
                        float e0 = acc[mt][nt][i * 2 + 0] + __ldg(&biasT[(size_t)col0 * B_ + b]);
                        float e1 = acc[mt][nt][i * 2 + 1] + __ldg(&biasT[(size_t)(col0 + 1) * B_ + b]);
                        rowsum[mt * 2 + i] += fmaxf(e0, 0.f) * v0 + fmaxf(e1, 0.f) * v1;
                    }
                }
            }
        }
    }

    #pragma unroll
    for (int k = 0; k < 8; k++) {
        rowsum[k] += __shfl_xor_sync(0xFFFFFFFF, rowsum[k], 1);
        rowsum[k] += __shfl_xor_sync(0xFFFFFFFF, rowsum[k], 2);
    }
    __syncthreads();
    if ((lane & 3) == 0) {
        #pragma unroll
        for (int mt = 0; mt < 4; mt++)
            #pragma unroll
            for (int i = 0; i < 2; i++)
                red[nw * 128 + mw * 64 + mt * 16 + g + i * 8] = rowsum[mt * 2 + i];
    }
    __syncthreads();
    if (tid < 128) {
        float s = red[tid] + red[128 + tid] + red[256 + tid] + red[384 + tid];
        scores[m0 + tid] = s;
    }
    #undef EN_LDGA
    #undef EN_STSA
    #undef EN_CPB
}

// ---------------- fc GEMM (round-7 proven): BN=128, inline fp32->bf16, occ 2 ----------------
__global__ void __launch_bounds__(256, 2)
fc_mma_k(const float* __restrict__ cat2, const float* __restrict__ fcW,
         const float* __restrict__ fcb, float* __restrict__ logits) {
    extern __shared__ char sm[];
    const uint32_t sb = smem_u32(sm);

    const int tid = threadIdx.x;
    const int wid = tid >> 5;
    const int lane = tid & 31;
    const int n0 = blockIdx.x * 128;
    const int mw = wid >> 2;
    const int nw = wid & 3;

    const int a_l = lane & 15;
    const int a_kh = (lane >> 4) << 3;
    const int b_nb = (lane & 7) + ((lane >> 4) << 3);
    const int b_kh = ((lane >> 3) & 1) << 3;
    const int g = lane >> 2;
    const int t2 = (lane & 3) << 1;

    float acc[2][4][4];
    #pragma unroll
    for (int mt = 0; mt < 2; mt++)
        #pragma unroll
        for (int nt = 0; nt < 4; nt++)
            #pragma unroll
            for (int k = 0; k < 4; k++) acc[mt][nt][k] = 0.f;

    const int aro[2] = {tid >> 3, (tid + 256) >> 3};
    const int bro[4] = {tid >> 3, (tid + 256) >> 3, (tid + 512) >> 3, (tid + 768) >> 3};
    const int qc = tid & 7;
    float4 Ar[2], Br[4];

    #define FC_LDG(it_) do {                                                        \
        int kb_ = (it_) * KSTEP;                                                    \
        _Pragma("unroll")                                                           \
        for (int j = 0; j < 2; j++)                                                 \
            Ar[j] = *(const float4*)&cat2[(size_t)aro[j] * (2 * H_) + kb_ + qc * 4];\
        _Pragma("unroll")                                                           \
        for (int j = 0; j < 4; j++)                                                 \
            Br[j] = *(const float4*)&fcW[(size_t)(n0 + bro[j]) * (2 * H_) + kb_ + qc * 4]; \
    } while (0)

    #define FC_STS(it_) do {                                                        \
        char* st_ = sm + ((it_) & 1) * FC_STAGE;                                    \
        _Pragma("unroll")                                                           \
        for (int j = 0; j < 2; j++) {                                               \
            uint2 hq_, lq_;                                                         \
            cvt_hl(Ar[j], &hq_, &lq_);                                              \
            *reinterpret_cast<uint2*>(st_ + FC_AHI + aro[j] * ROWB + qc * 8) = hq_; \
            *reinterpret_cast<uint2*>(st_ + FC_ALO + aro[j] * ROWB + qc * 8) = lq_; \
        }                                                                           \
        _Pragma("unroll")                                                           \
        for (int j = 0; j < 4; j++) {                                               \
            uint2 hq_, lq_;                                                         \
            cvt_hl(Br[j], &hq_, &lq_);                                              \
            *reinterpret_cast<uint2*>(st_ + FC_BHI + bro[j] * ROWB + qc * 8) = hq_; \
            *reinterpret_cast<uint2*>(st_ + FC_BLO + bro[j] * ROWB + qc * 8) = lq_; \
        }                                                                           \
    } while (0)

    const int total_it = 64;
    FC_LDG(0);

    for (int it = 0; it < total_it; it++) {
        __syncthreads();
        FC_STS(it);
        if (it + 1 < total_it) FC_LDG(it + 1);
        __syncthreads();

        const uint32_t stg = sb + (it & 1) * FC_STAGE;
        #pragma unroll
        for (int ks = 0; ks < 2; ks++) {
            uint32_t Ahi[2][4], Alo[2][4];
            #pragma unroll
            for (int mt = 0; mt < 2; mt++) {
                uint32_t off = (uint32_t)((mw * 32 + mt * 16 + a_l) * ROWB + (ks * 16 + a_kh) * 2);
                ldmx4(Ahi[mt], stg + FC_AHI + off);
                ldmx4(Alo[mt], stg + FC_ALO + off);
            }
            uint32_t Bhi[2][4], Blo[2][4];
            #pragma unroll
            for (int np = 0; np < 2; np++) {
                uint32_t off = (uint32_t)((nw * 32 + np * 16 + b_nb) * ROWB + (ks * 16 + b_kh) * 2);
                ldmx4(Bhi[np], stg + FC_BHI + off);
                ldmx4(Blo[np], stg + FC_BLO + off);
            }
            #pragma unroll
            for (int mt = 0; mt < 2; mt++)
                #pragma unroll
                for (int nt = 0; nt < 4; nt++) {
                    const int np = nt >> 1, pr = (nt & 1) * 2;
                    mma16816(acc[mt][nt], Ahi[mt], Bhi[np][pr], Bhi[np][pr + 1]);
                    mma16816(acc[mt][nt], Ahi[mt], Blo[np][pr], Blo[np][pr + 1]);
                    mma16816(acc[mt][nt], Alo[mt], Bhi[np][pr], Bhi[np][pr + 1]);
                }
        }
    }

    #pragma unroll
    for (int nt = 0; nt < 4; nt++) {
        const int col0 = n0 + nw * 32 + nt * 8 + t2;
        const float c0 = __ldg(&fcb[col0]);
        const float c1 = __ldg(&fcb[col0 + 1]);
        #pragma unroll
        for (int mt = 0; mt < 2; mt++) {
            #pragma unroll
            for (int i = 0; i < 2; i++) {
                const int row = mw * 32 + mt * 16 + g + i * 8;
                float2 o;
                o.x = acc[mt][nt][i * 2 + 0] + c0;
                o.y = acc[mt][nt][i * 2 + 1] + c1;
                *reinterpret_cast<float2*>(&logits[(size_t)row * V_ + col0]) = o;
            }
        }
    }
    #undef FC_LDG
    #undef FC_STS
}

// ---------------- softmax over T ----------------
__global__ void softmax_k(const float* __restrict__ scores,
                          float* __restrict__ attn_w_out) {
    int b = blockIdx.x;
    int t = threadIdx.x;
    __shared__ float sh[512];
    float s = scores[t * B_ + b];
    sh[t] = s;
    __syncthreads();
    for (int off = 256; off > 0; off >>= 1) {
        if (t < off) sh[t] = fmaxf(sh[t], sh[t + off]);
        __syncthreads();
    }
    float mx = sh[0];
    __syncthreads();
    float e = expf(s - mx);
    sh[t] = e;
    __syncthreads();
    for (int off = 256; off > 0; off >>= 1) {
        if (t < off) sh[t] += sh[t + off];
        __syncthreads();
    }
    attn_w_out[b * T_ + t] = e / sh[0];
}

// ---------------- context = attn_w @ enc (float4, unroll 8) ----------------
__global__ void context_k(const float4* __restrict__ enc4,
                          const float* __restrict__ attn_w,
                          float* __restrict__ rnn_in,
                          float* __restrict__ cat2) {
    int b = blockIdx.y;
    int h4 = blockIdx.x * 128 + threadIdx.x;
    __shared__ float w[T_];
    for (int t = threadIdx.x; t < T_; t += 128) w[t] = attn_w[b * T_ + t];
    __syncthreads();
    float4 acc = {0.f, 0.f, 0.f, 0.f};
    #pragma unroll 8
    for (int t = 0; t < T_; t++) {
        float4 e = enc4[(size_t)(t * B_ + b) * (H_ / 4) + h4];
        float wt = w[t];
        acc.x = fmaf(wt, e.x, acc.x);
        acc.y = fmaf(wt, e.y, acc.y);
        acc.z = fmaf(wt, e.z, acc.z);
        acc.w = fmaf(wt, e.w, acc.w);
    }
    int h = h4 * 4;
    *reinterpret_cast<float4*>(&rnn_in[b * (E_ + H_) + E_ + h]) = acc;
    *reinterpret_cast<float4*>(&cat2[b * (2 * H_) + H_ + h]) = acc;
}

// ---------------- GRU gates (reduce 8 k-split partials) ----------------
__global__ void gates_k(const float* __restrict__ pgi,
                        const float* __restrict__ pgh,
                        const float* __restrict__ bih,
                        const float* __restrict__ bhh,
                        const float* __restrict__ lh,
                        float* __restrict__ hnew_out,
                        float* __restrict__ cat2) {
    int b = blockIdx.x;
    for (int h = threadIdx.x; h < H_; h += blockDim.x) {
        float gi0 = bih[h], gi1 = bih[H_ + h], gi2 = bih[2 * H_ + h];
        float gh0 = bhh[h], gh1 = bhh[H_ + h], gh2 = bhh[2 * H_ + h];
        #pragma unroll
        for (int ks = 0; ks < 8; ks++) {
            size_t base = (size_t)((ks << 6) + b) * 3 * H_;
            gi0 += pgi[base + h]; gi1 += pgi[base + H_ + h]; gi2 += pgi[base + 2 * H_ + h];
            gh0 += pgh[base + h]; gh1 += pgh[base + H_ + h]; gh2 += pgh[base + 2 * H_ + h];
        }
        float r = 1.f / (1.f + expf(-(gi0 + gh0)));
        float z = 1.f / (1.f + expf(-(gi1 + gh1)));
        float n = tanhf(gi2 + r * gh2);
        float hp = lh[b * H_ + h];
        float hn = (1.f - z) * n + z * hp;
        hnew_out[b * H_ + h] = hn;
        cat2[b * (2 * H_) + h] = hn;
    }
}

// ---------------- log_softmax in-place ----------------
__global__ void logsoftmax_k(float* __restrict__ logits) {
    int b = blockIdx.x;
    int tid = threadIdx.x;
    __shared__ float sh[1024];
    float* row = logits + (size_t)b * V_;
    float mx = -1e30f;
    for (int n = tid; n < V_; n += 1024) mx = fmaxf(mx, row[n]);
    sh[tid] = mx;
    __syncthreads();
    for (int off = 512; off > 0; off >>= 1) {
        if (tid < off) sh[tid] = fmaxf(sh[tid], sh[tid + off]);
        __syncthreads();
    }
    mx = sh[0];
    __syncthreads();
    float sum = 0.f;
    for (int n = tid; n < V_; n += 1024) sum += expf(row[n] - mx);
    sh[tid] = sum;
    __syncthreads();
    for (int off = 512; off > 0; off >>= 1) {
        if (tid < off) sh[tid] += sh[tid + off];
        __syncthreads();
    }
    float lse = mx + logf(sh[0]);
    for (int n = tid; n < V_; n += 1024) row[n] -= lse;
}

// ---------------- launch ----------------
extern "C" void kernel_launch(void* const* d_in, const int* in_sizes, int n_in,
                              void* d_out, int out_size) {
    const int*   x    = (const int*)d_in[0];
    const float* lh   = (const float*)d_in[1];
    const float* enc  = (const float*)d_in[2];
    const float* embW = (const float*)d_in[3];
    const float* attW = (const float*)d_in[4];
    const float* attb = (const float*)d_in[5];
    const float* v    = (const float*)d_in[6];
    const float* Wih  = (const float*)d_in[7];
    const float* Whh  = (const float*)d_in[8];
    const float* bih  = (const float*)d_in[9];
    const float* bhh  = (const float*)d_in[10];
    const float* fcW  = (const float*)d_in[11];
    const float* fcb  = (const float*)d_in[12];

    float* out      = (float*)d_out;
    float* out_logp = out;
    float* out_h    = out + (size_t)B_ * V_;
    float* out_w    = out_h + (size_t)B_ * H_;

    float *rnn_in, *bias_aT, *scoresp, *cat2, *pbias, *pgi, *pgh;
    __nv_bfloat16 *whi, *wlo;
    cudaGetSymbolAddress((void**)&rnn_in,  g_rnn_in);
    cudaGetSymbolAddress((void**)&bias_aT, g_bias_aT);
    cudaGetSymbolAddress((void**)&scoresp, g_scores);
    cudaGetSymbolAddress((void**)&cat2,    g_cat2);
    cudaGetSymbolAddress((void**)&pbias,   g_part_bias);
    cudaGetSymbolAddress((void**)&pgi,     g_part_gi);
    cudaGetSymbolAddress((void**)&pgh,     g_part_gh);
    cudaGetSymbolAddress((void**)&whi,     g_w_hi);
    cudaGetSymbolAddress((void**)&wlo,     g_w_lo);

    cudaFuncSetAttribute(energy_mma_k, cudaFuncAttributeMaxDynamicSharedMemorySize, SMEM_ENERGY);
    cudaFuncSetAttribute(fc_mma_k, cudaFuncAttributeMaxDynamicSharedMemorySize, SMEM_FC);

    // launch order arranged so energy_mma_k is launch #4 (ncu captures the 4th launch)
    split_w_k<<<(H_ * H_ / 4) / 256, 256>>>(attW, whi, wlo);                          // 1
    gemm_m64_ks<<<dim3(H_ / 64, 8), 256>>>(lh, H_, attW, 2 * H_, pbias, H_, 128);     // 2
    bias_redT_k<<<(B_ * H_) / 256, 256>>>(pbias, attb, bias_aT);                      // 3
    energy_mma_k<<<M_BT / 128, 256, SMEM_ENERGY>>>(enc, whi, wlo, bias_aT, v, scoresp); // 4
    gather_emb_k<<<B_, 128>>>(x, embW, rnn_in);                                       // 5 (independent)
    softmax_k<<<B_, 512>>>(scoresp, out_w);
    context_k<<<dim3(2, B_), 128>>>((const float4*)enc, out_w, rnn_in, cat2);
    gemm_m64_ks<<<dim3(3 * H_ / 64, 8), 256>>>(rnn_in, E_ + H_, Wih, E_ + H_, pgi, 3 * H_, 192);
    gemm_m64_ks<<<dim3(3 * H_ / 64, 8), 256>>>(lh, H_, Whh, H_, pgh, 3 * H_, 128);
    gates_k<<<B_, 256>>>(pgi, pgh, bih, bhh, lh, out_h, cat2);
    fc_mma_k<<<V_ / 128, 256, SMEM_FC>>>(cat2, fcW, fcb, out_logp);
    logsoftmax_k<<<B_, 1024>>>(out_logp);
}

// round 11
// speedup vs baseline: 1.1522x; 1.1299x over previous
#include <cuda_runtime.h>
#include <cuda_bf16.h>
#include <math.h>
#include <stdint.h>

#define B_ 64
#define T_ 512
#define H_ 1024
#define E_ 512
#define V_ 32000
#define M_BT (B_ * T_)        // 32768

// ---------------- scratch (device globals; no allocation allowed) ----------------
__device__ float g_rnn_in[B_ * (E_ + H_)];        // [64, 1536]
__device__ float g_bias_aT[H_ * B_];              // [1024, 64]
__device__ float g_scores[M_BT];
__device__ float g_cat2[B_ * 2 * H_];             // [h_new | context]
__device__ float g_part_bias[8 * B_ * H_];
__device__ float g_part_gi[8 * B_ * 3 * H_];
__device__ float g_part_gh[8 * B_ * 3 * H_];
__device__ __nv_bfloat16 g_enc_hi[(size_t)M_BT * H_];   // 64 MB
__device__ __nv_bfloat16 g_enc_lo[(size_t)M_BT * H_];   // 64 MB
__device__ __nv_bfloat16 g_w_hi[H_ * H_];         // 2 MB
__device__ __nv_bfloat16 g_w_lo[H_ * H_];         // 2 MB

// ======================= helpers =======================
__device__ __forceinline__ uint32_t smem_u32(const void* p) {
    uint32_t a;
    asm("{ .reg .u64 t; cvta.to.shared.u64 t, %1; cvt.u32.u64 %0, t; }" : "=r"(a) : "l"(p));
    return a;
}
#define CP_ASYNC16(dst, src) \
    asm volatile("cp.async.cg.shared.global [%0], [%1], 16;" :: "r"(dst), "l"(src))
#define CP_COMMIT() asm volatile("cp.async.commit_group;" ::: "memory")
#define CP_WAIT2() asm volatile("cp.async.wait_group 2;" ::: "memory")
#define CP_WAIT1() asm volatile("cp.async.wait_group 1;" ::: "memory")
#define CP_WAIT0() asm volatile("cp.async.wait_group 0;" ::: "memory")

__device__ __forceinline__ void ldmx4(uint32_t* r, uint32_t addr) {
    asm volatile("ldmatrix.sync.aligned.m8n8.x4.shared.b16 {%0,%1,%2,%3}, [%4];"
                 : "=r"(r[0]), "=r"(r[1]), "=r"(r[2]), "=r"(r[3]) : "r"(addr));
}
__device__ __forceinline__ void mma16816(float* d, const uint32_t* a, uint32_t b0, uint32_t b1) {
    asm volatile("mma.sync.aligned.m16n8k16.row.col.f32.bf16.bf16.f32 "
                 "{%0,%1,%2,%3}, {%4,%5,%6,%7}, {%8,%9}, {%0,%1,%2,%3};"
                 : "+f"(d[0]), "+f"(d[1]), "+f"(d[2]), "+f"(d[3])
                 : "r"(a[0]), "r"(a[1]), "r"(a[2]), "r"(a[3]), "r"(b0), "r"(b1));
}
// fp32 quad -> bf16 hi/lo quads (8 bytes each)
__device__ __forceinline__ void cvt_hl(float4 x, uint2* hq, uint2* lq) {
    __align__(8) __nv_bfloat16 h[4];
    __align__(8) __nv_bfloat16 l[4];
    float xs[4] = {x.x, x.y, x.z, x.w};
    #pragma unroll
    for (int j = 0; j < 4; j++) {
        h[j] = __float2bfloat16(xs[j]);
        l[j] = __float2bfloat16(xs[j] - __bfloat162float(h[j]));
    }
    *hq = *reinterpret_cast<uint2*>(h);
    *lq = *reinterpret_cast<uint2*>(l);
}

// ======================= tiling constants =======================
#define KSTEP 32
#define ROWB 80
// energy v3: 512 threads, chunk=128, all operands via cp.async from pre-split bf16.
#define EN_OP_T (128 * ROWB)          // 10240 per operand tile
#define EN_STAGE (4 * EN_OP_T)        // 40960: Ahi|Alo|Bhi|Blo
#define EN_NSTAGE 4
#define EN_RED_OFF (EN_NSTAGE * EN_STAGE)     // 163840
#define SMEM_ENERGY (EN_RED_OFF + 512 * 4)    // 165888
// fc (round-7 proven): BN=128, inline fp32->bf16, 2 stages, occ 2
#define FC_TA (64 * ROWB)             // 5120
#define FC_TB (128 * ROWB)            // 10240
#define FC_AHI 0
#define FC_ALO FC_TA
#define FC_BHI (2 * FC_TA)
#define FC_BLO (2 * FC_TA + FC_TB)
#define FC_STAGE (2 * FC_TA + 2 * FC_TB)   // 30720
#define SMEM_FC (2 * FC_STAGE)             // 61440

#define ENC_BLOCKS ((M_BT * (H_ / 4)) / 256)   // 32768
#define W_BLOCKS ((H_ * (H_ / 4)) / 256)       // 1024

// ---------------- merged split: enc AND attn_W[:, H:] -> bf16 hi/lo ----------------
__global__ void split_all_k(const float* __restrict__ enc,
                            const float* __restrict__ attnW,
                            __nv_bfloat16* __restrict__ ehi, __nv_bfloat16* __restrict__ elo,
                            __nv_bfloat16* __restrict__ whi, __nv_bfloat16* __restrict__ wlo) {
    if (blockIdx.x < ENC_BLOCKS) {
        size_t i = (size_t)blockIdx.x * 256 + threadIdx.x;
        float4 x = reinterpret_cast<const float4*>(enc)[i];
        uint2 h, l;
        cvt_hl(x, &h, &l);
        *reinterpret_cast<uint2*>(ehi + 4 * i) = h;
        *reinterpret_cast<uint2*>(elo + 4 * i) = l;
    } else {
        int i = (blockIdx.x - ENC_BLOCKS) * 256 + threadIdx.x;   // < H_*H_/4
        int r = i >> 8;
        int k4 = i & 255;
        const float4* src = reinterpret_cast<const float4*>(attnW + (size_t)r * (2 * H_) + H_) + k4;
        uint2 h, l;
        cvt_hl(*src, &h, &l);
        *reinterpret_cast<uint2*>(whi + 4 * (size_t)i) = h;
        *reinterpret_cast<uint2*>(wlo + 4 * (size_t)i) = l;
    }
}

// ---------------- embedding gather ----------------
__global__ void gather_emb_k(const int* __restrict__ x,
                             const float* __restrict__ embW,
                             float* __restrict__ rnn_in) {
    int b = blockIdx.x;
    int row = x[b];
    for (int e = threadIdx.x; e < E_; e += blockDim.x)
        rnn_in[b * (E_ + H_) + e] = embW[(size_t)row * E_ + e];
}

// ---------------- K-split M=64 GEMM ----------------
__global__ void gemm_m64_ks(const float* __restrict__ A, int lda,
                            const float* __restrict__ W, int ldw,
                            float* __restrict__ Cp, int ldc, int kc) {
    __shared__ float As[16][64];
    __shared__ float Ws[16][64];
    const int tid = threadIdx.x;
    const int n0 = blockIdx.x * 64;
    const int kk0 = blockIdx.y * kc;
    const int lrow = tid >> 2;
    const int kq = (tid & 3) * 4;
    const int ty = tid >> 4;
    const int tx = tid & 15;

    float acc[4][4] = {};
    for (int kk = kk0; kk < kk0 + kc; kk += 16) {
        float4 av = *(const float4*)&A[lrow * lda + kk + kq];
        float4 wv = *(const float4*)&W[(size_t)(n0 + lrow) * ldw + kk + kq];
        __syncthreads();
        As[kq + 0][lrow] = av.x; As[kq + 1][lrow] = av.y;
        As[kq + 2][lrow] = av.z; As[kq + 3][lrow] = av.w;
        Ws[kq + 0][lrow] = wv.x; Ws[kq + 1][lrow] = wv.y;
        Ws[kq + 2][lrow] = wv.z; Ws[kq + 3][lrow] = wv.w;
        __syncthreads();
        #pragma unroll
        for (int k = 0; k < 16; k++) {
            float4 a = *(const float4*)&As[k][ty * 4];
            float4 w = *(const float4*)&Ws[k][tx * 4];
            float af[4] = {a.x, a.y, a.z, a.w};
            float wf[4] = {w.x, w.y, w.z, w.w};
            #pragma unroll
            for (int i = 0; i < 4; i++)
                #pragma unroll
                for (int j = 0; j < 4; j++)
                    acc[i][j] = fmaf(af[i], wf[j], acc[i][j]);
        }
    }
    #pragma unroll
    for (int i = 0; i < 4; i++) {
        int m = blockIdx.y * 64 + ty * 4 + i;
        #pragma unroll
        for (int j = 0; j < 4; j++)
            Cp[(size_t)m * ldc + n0 + tx * 4 + j] = acc[i][j];
    }
}

// ---------------- bias partial reduce + transpose ----------------
__global__ void bias_redT_k(const float* __restrict__ part,
                            const float* __restrict__ attb,
                            float* __restrict__ biasT) {
    int idx = blockIdx.x * 256 + threadIdx.x;
    int b = idx >> 10, h = idx & 1023;
    float s = attb[h];
    #pragma unroll
    for (int ks = 0; ks < 8; ks++)
        s += part[(size_t)((ks << 6) + b) * H_ + h];
    biasT[h * B_ + b] = s;
}

// ---------------- energy GEMM v3: 512 threads, chunk=128, pure cp.async ----------------
__global__ void __launch_bounds__(512, 1)
energy_mma_k(const __nv_bfloat16* __restrict__ ehi, const __nv_bfloat16* __restrict__ elo,
             const __nv_bfloat16* __restrict__ whi, const __nv_bfloat16* __restrict__ wlo,
             const float* __restrict__ biasT, const float* __restrict__ v,
             float* __restrict__ scores) {
    extern __shared__ char sm[];
    const uint32_t sb = smem_u32(sm);
    float* red = (float*)(sm + EN_RED_OFF);

    const int tid = threadIdx.x;
    const int wid = tid >> 5;
    const int lane = tid & 31;
    const int m0 = blockIdx.x * 128;
    const int mw = wid >> 2;       // 0..3: rows mw*32..+31
    const int nw = wid & 3;        // 0..3: cols nw*32..+31 within 128-col chunk

    const int a_l = lane & 15;
    const int a_kh = (lane >> 4) << 3;
    const int b_nb = (lane & 7) + ((lane >> 4) << 3);
    const int b_kh = ((lane >> 3) & 1) << 3;
    const int g = lane >> 2;
    const int t2 = (lane & 3) << 1;

    float acc[2][4][4];            // 32 regs: 2 m-tiles x 4 n-octets
    float rowsum[4];
    #pragma unroll
    for (int i = 0; i < 4; i++) rowsum[i] = 0.f;

    const int total_it = 8 * 32;   // 8 chunks of 128 cols, 32 k-tiles each
    // cp.async map: each thread loads one 16B chunk per operand (4 ops)
    const int cp_r = tid >> 2;     // 0..127
    const int cp_c = tid & 3;      // 0..3 (16B within 64B row)

    #define EN_CP(it_) do {                                                          \
        int chunk_ = (it_) >> 5;                                                     \
        int kb_ = ((it_) & 31) * KSTEP;                                              \
        uint32_t stg_ = sb + ((it_) & 3) * EN_STAGE;                                 \
        uint32_t d_ = stg_ + (uint32_t)(cp_r * ROWB + cp_c * 16);                    \
        size_t aoff_ = (size_t)(m0 + cp_r) * H_ + kb_ + cp_c * 8;                    \
        size_t boff_ = (size_t)(chunk_ * 128 + cp_r) * H_ + kb_ + cp_c * 8;          \
        CP_ASYNC16(d_ + 0 * EN_OP_T, ehi + aoff_);                                   \
        CP_ASYNC16(d_ + 1 * EN_OP_T, elo + aoff_);                                   \
        CP_ASYNC16(d_ + 2 * EN_OP_T, whi + boff_);                                   \
        CP_ASYNC16(d_ + 3 * EN_OP_T, wlo + boff_);                                   \
        CP_COMMIT();                                                                 \
    } while (0)

    EN_CP(0);
    EN_CP(1);

    for (int it = 0; it < total_it; it++) {
        const int kt = it & 31;
        const int chunk = it >> 5;
        if (kt == 0) {
            #pragma unroll
            for (int mt = 0; mt < 2; mt++)
                #pragma unroll
                for (int nt = 0; nt < 4; nt++)
                    #pragma unroll
                    for (int k = 0; k < 4; k++) acc[mt][nt][k] = 0.f;
        }
        // write stage (it+2)&3: last read at iter it-2, fenced by barrier of iter it-1
        if (it + 2 < total_it) { EN_CP(it + 2); CP_WAIT2(); }
        else if (it + 1 < total_it) { CP_WAIT1(); }
        else { CP_WAIT0(); }
        __syncthreads();           // cross-warp visibility of stage it&3

        const uint32_t stg = sb + (it & 3) * EN_STAGE;
        #pragma unroll
        for (int ks = 0; ks < 2; ks++) {
            uint32_t Ahi[2][4], Alo[2][4];
            #pragma unroll
            for (int mt = 0; mt < 2; mt++) {
                uint32_t off = (uint32_t)((mw * 32 + mt * 16 + a_l) * ROWB + (ks * 16 + a_kh) * 2);
                ldmx4(Ahi[mt], stg + 0 * EN_OP_T + off);
                ldmx4(Alo[mt], stg + 1 * EN_OP_T + off);
            }
            uint32_t Bhi[2][4], Blo[2][4];
            #pragma unroll
            for (int np = 0; np < 2; np++) {
                uint32_t off = (uint32_t)((nw * 32 + np * 16 + b_nb) * ROWB + (ks * 16 + b_kh) * 2);
                ldmx4(Bhi[np], stg + 2 * EN_OP_T + off);
                ldmx4(Blo[np], stg + 3 * EN_OP_T + off);
            }
            #pragma unroll
            for (int mt = 0; mt < 2; mt++)
                #pragma unroll
                for (int nt = 0; nt < 4; nt++) {
                    const int np = nt >> 1, pr = (nt & 1) * 2;
                    mma16816(acc[mt][nt], Ahi[mt], Bhi[np][pr], Bhi[np][pr + 1]);
                    mma16816(acc[mt][nt], Ahi[mt], Blo[np][pr], Blo[np][pr + 1]);
                    mma16816(acc[mt][nt], Alo[mt], Bhi[np][pr], Bhi[np][pr + 1]);
                }
        }

        if (kt == 31) {
            #pragma unroll
            for (int nt = 0; nt < 4; nt++) {
                const int col0 = chunk * 128 + nw * 32 + nt * 8 + t2;
                const float v0 = __ldg(&v[col0]);
                const float v1 = __ldg(&v[col0 + 1]);
                #pragma unroll
                for (int mt = 0; mt < 2; mt++) {
                    #pragma unroll
                    for (int i = 0; i < 2; i++) {
                        const int row = mw * 32 + mt * 16 + g + i * 8;
                        const int b = row & (B_ - 1);
                        float e0 = acc[mt][nt][i * 2 + 0] + __ldg(&biasT[(size_t)col0 * B_ + b]);
                        float e1 = acc[mt][nt][i * 2 + 1] + __ldg(&biasT[(size_t)(col0 + 1) * B_ + b]);
                        rowsum[mt * 2 + i] += fmaxf(e0, 0.f) * v0 + fmaxf(e1, 0.f) * v1;
                    }
                }
            }
        }
    }

    #pragma unroll
    for (int k = 0; k < 4; k++) {
        rowsum[k] += __shfl_xor_sync(0xFFFFFFFF, rowsum[k], 1);
        rowsum[k] += __shfl_xor_sync(0xFFFFFFFF, rowsum[k], 2);
    }
    __syncthreads();
    if ((lane & 3) == 0) {
        #pragma unroll
        for (int mt = 0; mt < 2; mt++)
            #pragma unroll
            for (int i = 0; i < 2; i++)
                red[nw * 128 + mw * 32 + mt * 16 + g + i * 8] = rowsum[mt * 2 + i];
    }
    __syncthreads();
    if (tid < 128) {
        float s = red[tid] + red[128 + tid] + red[256 + tid] + red[384 + tid];
        scores[m0 + tid] = s;
    }
    #undef EN_CP
}

// ---------------- fc GEMM (round-7 proven): BN=128, inline fp32->bf16, occ 2 ----------------
__global__ void __launch_bounds__(256, 2)
fc_mma_k(const float* __restrict__ cat2, const float* __restrict__ fcW,
         const float* __restrict__ fcb, float* __restrict__ logits) {
    extern __shared__ char sm[];
    const uint32_t sb = smem_u32(sm);

    const int tid = threadIdx.x;
    const int wid = tid >> 5;
    const int lane = tid & 31;
    const int n0 = blockIdx.x * 128;
    const int mw = wid >> 2;
    const int nw = wid & 3;

    const int a_l = lane & 15;
    const int a_kh = (lane >> 4) << 3;
    const int b_nb = (lane & 7) + ((lane >> 4) << 3);
    const int b_kh = ((lane >> 3) & 1) << 3;
    const int g = lane >> 2;
    const int t2 = (lane & 3) << 1;

    float acc[2][4][4];
    #pragma unroll
    for (int mt = 0; mt < 2; mt++)
        #pragma unroll
        for (int nt = 0; nt < 4; nt++)
            #pragma unroll
            for (int k = 0; k < 4; k++) acc[mt][nt][k] = 0.f;

    const int aro[2] = {tid >> 3, (tid + 256) >> 3};
    const int bro[4] = {tid >> 3, (tid + 256) >> 3, (tid + 512) >> 3, (tid + 768) >> 3};
    const int qc = tid & 7;
    float4 Ar[2], Br[4];

    #define FC_LDG(it_) do {                                                        \
        int kb_ = (it_) * KSTEP;                                                    \
        _Pragma("unroll")                                                           \
        for (int j = 0; j < 2; j++)                                                 \
            Ar[j] = *(const float4*)&cat2[(size_t)aro[j] * (2 * H_) + kb_ + qc * 4];\
        _Pragma("unroll")                                                           \
        for (int j = 0; j < 4; j++)                                                 \
            Br[j] = *(const float4*)&fcW[(size_t)(n0 + bro[j]) * (2 * H_) + kb_ + qc * 4]; \
    } while (0)

    #define FC_STS(it_) do {                                                        \
        char* st_ = sm + ((it_) & 1) * FC_STAGE;                                    \
        _Pragma("unroll")                                                           \
        for (int j = 0; j < 2; j++) {                                               \
            uint2 hq_, lq_;                                                         \
            cvt_hl(Ar[j], &hq_, &lq_);                                              \
            *reinterpret_cast<uint2*>(st_ + FC_AHI + aro[j] * ROWB + qc * 8) = hq_; \
            *reinterpret_cast<uint2*>(st_ + FC_ALO + aro[j] * ROWB + qc * 8) = lq_; \
        }                                                                           \
        _Pragma("unroll")                                                           \
        for (int j = 0; j < 4; j++) {                                               \
            uint2 hq_, lq_;                                                         \
            cvt_hl(Br[j], &hq_, &lq_);                                              \
            *reinterpret_cast<uint2*>(st_ + FC_BHI + bro[j] * ROWB + qc * 8) = hq_; \
            *reinterpret_cast<uint2*>(st_ + FC_BLO + bro[j] * ROWB + qc * 8) = lq_; \
        }                                                                           \
    } while (0)

    const int total_it = 64;
    FC_LDG(0);

    for (int it = 0; it < total_it; it++) {
        __syncthreads();
        FC_STS(it);
        if (it + 1 < total_it) FC_LDG(it + 1);
        __syncthreads();

        const uint32_t stg = sb + (it & 1) * FC_STAGE;
        #pragma unroll
        for (int ks = 0; ks < 2; ks++) {
            uint32_t Ahi[2][4], Alo[2][4];
            #pragma unroll
            for (int mt = 0; mt < 2; mt++) {
                uint32_t off = (uint32_t)((mw * 32 + mt * 16 + a_l) * ROWB + (ks * 16 + a_kh) * 2);
                ldmx4(Ahi[mt], stg + FC_AHI + off);
                ldmx4(Alo[mt], stg + FC_ALO + off);
            }
            uint32_t Bhi[2][4], Blo[2][4];
            #pragma unroll
            for (int np = 0; np < 2; np++) {
                uint32_t off = (uint32_t)((nw * 32 + np * 16 + b_nb) * ROWB + (ks * 16 + b_kh) * 2);
                ldmx4(Bhi[np], stg + FC_BHI + off);
                ldmx4(Blo[np], stg + FC_BLO + off);
            }
            #pragma unroll
            for (int mt = 0; mt < 2; mt++)
                #pragma unroll
                for (int nt = 0; nt < 4; nt++) {
                    const int np = nt >> 1, pr = (nt & 1) * 2;
                    mma16816(acc[mt][nt], Ahi[mt], Bhi[np][pr], Bhi[np][pr + 1]);
                    mma16816(acc[mt][nt], Ahi[mt], Blo[np][pr], Blo[np][pr + 1]);
                    mma16816(acc[mt][nt], Alo[mt], Bhi[np][pr], Bhi[np][pr + 1]);
                }
        }
    }

    #pragma unroll
    for (int nt = 0; nt < 4; nt++) {
        const int col0 = n0 + nw * 32 + nt * 8 + t2;
        const float c0 = __ldg(&fcb[col0]);
        const float c1 = __ldg(&fcb[col0 + 1]);
        #pragma unroll
        for (int mt = 0; mt < 2; mt++) {
            #pragma unroll
            for (int i = 0; i < 2; i++) {
                const int row = mw * 32 + mt * 16 + g + i * 8;
                float2 o;
                o.x = acc[mt][nt][i * 2 + 0] + c0;
                o.y = acc[mt][nt][i * 2 + 1] + c1;
                *reinterpret_cast<float2*>(&logits[(size_t)row * V_ + col0]) = o;
            }
        }
    }
    #undef FC_LDG
    #undef FC_STS
}

// ---------------- softmax over T ----------------
__global__ void softmax_k(const float* __restrict__ scores,
                          float* __restrict__ attn_w_out) {
    int b = blockIdx.x;
    int t = threadIdx.x;
    __shared__ float sh[512];
    float s = scores[t * B_ + b];
    sh[t] = s;
    __syncthreads();
    for (int off = 256; off > 0; off >>= 1) {
        if (t < off) sh[t] = fmaxf(sh[t], sh[t + off]);
        __syncthreads();
    }
    float mx = sh[0];
    __syncthreads();
    float e = expf(s - mx);
    sh[t] = e;
    __syncthreads();
    for (int off = 256; off > 0; off >>= 1) {
        if (t < off) sh[t] += sh[t + off];
        __syncthreads();
    }
    attn_w_out[b * T_ + t] = e / sh[0];
}

// ---------------- context = attn_w @ enc (float4, unroll 8) ----------------
__global__ void context_k(const float4* __restrict__ enc4,
                          const float* __restrict__ attn_w,
                          float* __restrict__ rnn_in,
                          float* __restrict__ cat2) {
    int b = blockIdx.y;
    int h4 = blockIdx.x * 128 + threadIdx.x;
    __shared__ float w[T_];
    for (int t = threadIdx.x; t < T_; t += 128) w[t] = attn_w[b * T_ + t];
    __syncthreads();
    float4 acc = {0.f, 0.f, 0.f, 0.f};
    #pragma unroll 8
    for (int t = 0; t < T_; t++) {
        float4 e = enc4[(size_t)(t * B_ + b) * (H_ / 4) + h4];
        float wt = w[t];
        acc.x = fmaf(wt, e.x, acc.x);
        acc.y = fmaf(wt, e.y, acc.y);
        acc.z = fmaf(wt, e.z, acc.z);
        acc.w = fmaf(wt, e.w, acc.w);
    }
    int h = h4 * 4;
    *reinterpret_cast<float4*>(&rnn_in[b * (E_ + H_) + E_ + h]) = acc;
    *reinterpret_cast<float4*>(&cat2[b * (2 * H_) + H_ + h]) = acc;
}

// ---------------- GRU gates (reduce 8 k-split partials) ----------------
__global__ void gates_k(const float* __restrict__ pgi,
                        const float* __restrict__ pgh,
                        const float* __restrict__ bih,
                        const float* __restrict__ bhh,
                        const float* __restrict__ lh,
                        float* __restrict__ hnew_out,
                        float* __restrict__ cat2) {
    int b = blockIdx.x;
    for (int h = threadIdx.x; h < H_; h += blockDim.x) {
        float gi0 = bih[h], gi1 = bih[H_ + h], gi2 = bih[2 * H_ + h];
        float gh0 = bhh[h], gh1 = bhh[H_ + h], gh2 = bhh[2 * H_ + h];
        #pragma unroll
        for (int ks = 0; ks < 8; ks++) {
            size_t base = (size_t)((ks << 6) + b) * 3 * H_;
            gi0 += pgi[base + h]; gi1 += pgi[base + H_ + h]; gi2 += pgi[base + 2 * H_ + h];
            gh0 += pgh[base + h]; gh1 += pgh[base + H_ + h]; gh2 += pgh[base + 2 * H_ + h];
        }
        float r = 1.f / (1.f + expf(-(gi0 + gh0)));
        float z = 1.f / (1.f + expf(-(gi1 + gh1)));
        float n = tanhf(gi2 + r * gh2);
        float hp = lh[b * H_ + h];
        float hn = (1.f - z) * n + z * hp;
        hnew_out[b * H_ + h] = hn;
        cat2[b * (2 * H_) + h] = hn;
    }
}

// ---------------- log_softmax in-place ----------------
__global__ void logsoftmax_k(float* __restrict__ logits) {
    int b = blockIdx.x;
    int tid = threadIdx.x;
    __shared__ float sh[1024];
    float* row = logits + (size_t)b * V_;
    float mx = -1e30f;
    for (int n = tid; n < V_; n += 1024) mx = fmaxf(mx, row[n]);
    sh[tid] = mx;
    __syncthreads();
    for (int off = 512; off > 0; off >>= 1) {
        if (tid < off) sh[tid] = fmaxf(sh[tid], sh[tid + off]);
        __syncthreads();
    }
    mx = sh[0];
    __syncthreads();
    float sum = 0.f;
    for (int n = tid; n < V_; n += 1024) sum += expf(row[n] - mx);
    sh[tid] = sum;
    __syncthreads();
    for (int off = 512; off > 0; off >>= 1) {
        if (tid < off) sh[tid] += sh[tid + off];
        __syncthreads();
    }
    float lse = mx + logf(sh[0]);
    for (int n = tid; n < V_; n += 1024) row[n] -= lse;
}

// ---------------- launch ----------------
extern "C" void kernel_launch(void* const* d_in, const int* in_sizes, int n_in,
                              void* d_out, int out_size) {
    const int*   x    = (const int*)d_in[0];
    const float* lh   = (const float*)d_in[1];
    const float* enc  = (const float*)d_in[2];
    const float* embW = (const float*)d_in[3];
    const float* attW = (const float*)d_in[4];
    const float* attb = (const float*)d_in[5];
    const float* v    = (const float*)d_in[6];
    const float* Wih  = (const float*)d_in[7];
    const float* Whh  = (const float*)d_in[8];
    const float* bih  = (const float*)d_in[9];
    const float* bhh  = (const float*)d_in[10];
    const float* fcW  = (const float*)d_in[11];
    const float* fcb  = (const float*)d_in[12];

    float* out      = (float*)d_out;
    float* out_logp = out;
    float* out_h    = out + (size_t)B_ * V_;
    float* out_w    = out_h + (size_t)B_ * H_;

    float *rnn_in, *bias_aT, *scoresp, *cat2, *pbias, *pgi, *pgh;
    __nv_bfloat16 *ehi, *elo, *whi, *wlo;
    cudaGetSymbolAddress((void**)&rnn_in,  g_rnn_in);
    cudaGetSymbolAddress((void**)&bias_aT, g_bias_aT);
    cudaGetSymbolAddress((void**)&scoresp, g_scores);
    cudaGetSymbolAddress((void**)&cat2,    g_cat2);
    cudaGetSymbolAddress((void**)&pbias,   g_part_bias);
    cudaGetSymbolAddress((void**)&pgi,     g_part_gi);
    cudaGetSymbolAddress((void**)&pgh,     g_part_gh);
    cudaGetSymbolAddress((void**)&ehi,     g_enc_hi);
    cudaGetSymbolAddress((void**)&elo,     g_enc_lo);
    cudaGetSymbolAddress((void**)&whi,     g_w_hi);
    cudaGetSymbolAddress((void**)&wlo,     g_w_lo);

    cudaFuncSetAttribute(energy_mma_k, cudaFuncAttributeMaxDynamicSharedMemorySize, SMEM_ENERGY);
    cudaFuncSetAttribute(fc_mma_k, cudaFuncAttributeMaxDynamicSharedMemorySize, SMEM_FC);

    // launch order arranged so energy_mma_k is launch #4 (ncu captures the 4th launch)
    split_all_k<<<ENC_BLOCKS + W_BLOCKS, 256>>>(enc, attW, ehi, elo, whi, wlo);       // 1
    gemm_m64_ks<<<dim3(H_ / 64, 8), 256>>>(lh, H_, attW, 2 * H_, pbias, H_, 128);     // 2
    bias_redT_k<<<(B_ * H_) / 256, 256>>>(pbias, attb, bias_aT);                      // 3
    energy_mma_k<<<M_BT / 128, 512, SMEM_ENERGY>>>(ehi, elo, whi, wlo, bias_aT, v, scoresp); // 4
    gather_emb_k<<<B_, 128>>>(x, embW, rnn_in);                                       // 5 (independent)
    softmax_k<<<B_, 512>>>(scoresp, out_w);
    context_k<<<dim3(2, B_), 128>>>((const float4*)enc, out_w, rnn_in, cat2);
    gemm_m64_ks<<<dim3(3 * H_ / 64, 8), 256>>>(rnn_in, E_ + H_, Wih, E_ + H_, pgi, 3 * H_, 192);
    gemm_m64_ks<<<dim3(3 * H_ / 64, 8), 256>>>(lh, H_, Whh, H_, pgh, 3 * H_, 128);
    gates_k<<<B_, 256>>>(pgi, pgh, bih, bhh, lh, out_h, cat2);
    fc_mma_k<<<V_ / 128, 256, SMEM_FC>>>(cat2, fcW, fcb, out_logp);
    logsoftmax_k<<<B_, 1024>>>(out_logp);
}

// round 12
// speedup vs baseline: 1.3356x; 1.1592x over previous
#include <cuda_runtime.h>
#include <cuda_bf16.h>
#include <cuda_fp16.h>
#include <math.h>
#include <stdint.h>

#define B_ 64
#define T_ 512
#define H_ 1024
#define E_ 512
#define V_ 32000
#define M_BT (B_ * T_)        // 32768

// ---------------- scratch (device globals; no allocation allowed) ----------------
__device__ float g_rnn_in[B_ * (E_ + H_)];
__device__ float g_bias_aT[H_ * B_];
__device__ float g_scores[M_BT];
__device__ float g_cat2[B_ * 2 * H_];
__device__ float g_part_bias[8 * B_ * H_];
__device__ float g_part_gi[8 * B_ * 3 * H_];
__device__ float g_part_gh[8 * B_ * 3 * H_];
__device__ __half g_enc_hi[(size_t)M_BT * H_];   // 64 MB fp16
__device__ __half g_enc_lo[(size_t)M_BT * H_];   // 64 MB fp16
__device__ __half g_w_h[H_ * H_];                // 2 MB fp16 (single precision-level for W)

// ======================= helpers =======================
__device__ __forceinline__ uint32_t smem_u32(const void* p) {
    uint32_t a;
    asm("{ .reg .u64 t; cvta.to.shared.u64 t, %1; cvt.u32.u64 %0, t; }" : "=r"(a) : "l"(p));
    return a;
}
#define CP_ASYNC16(dst, src) \
    asm volatile("cp.async.cg.shared.global [%0], [%1], 16;" :: "r"(dst), "l"(src))
#define CP_COMMIT() asm volatile("cp.async.commit_group;" ::: "memory")
#define CP_WAIT1() asm volatile("cp.async.wait_group 1;" ::: "memory")
#define CP_WAIT0() asm volatile("cp.async.wait_group 0;" ::: "memory")

__device__ __forceinline__ void ldmx4(uint32_t* r, uint32_t addr) {
    asm volatile("ldmatrix.sync.aligned.m8n8.x4.shared.b16 {%0,%1,%2,%3}, [%4];"
                 : "=r"(r[0]), "=r"(r[1]), "=r"(r[2]), "=r"(r[3]) : "r"(addr));
}
// bf16 mma (fc path)
__device__ __forceinline__ void mma16816(float* d, const uint32_t* a, uint32_t b0, uint32_t b1) {
    asm volatile("mma.sync.aligned.m16n8k16.row.col.f32.bf16.bf16.f32 "
                 "{%0,%1,%2,%3}, {%4,%5,%6,%7}, {%8,%9}, {%0,%1,%2,%3};"
                 : "+f"(d[0]), "+f"(d[1]), "+f"(d[2]), "+f"(d[3])
                 : "r"(a[0]), "r"(a[1]), "r"(a[2]), "r"(a[3]), "r"(b0), "r"(b1));
}
// fp16 mma (energy path)
__device__ __forceinline__ void mma16816h(float* d, const uint32_t* a, uint32_t b0, uint32_t b1) {
    asm volatile("mma.sync.aligned.m16n8k16.row.col.f32.f16.f16.f32 "
                 "{%0,%1,%2,%3}, {%4,%5,%6,%7}, {%8,%9}, {%0,%1,%2,%3};"
                 : "+f"(d[0]), "+f"(d[1]), "+f"(d[2]), "+f"(d[3])
                 : "r"(a[0]), "r"(a[1]), "r"(a[2]), "r"(a[3]), "r"(b0), "r"(b1));
}
// fp32 quad -> bf16 hi/lo quads
__device__ __forceinline__ void cvt_hl(float4 x, uint2* hq, uint2* lq) {
    __align__(8) __nv_bfloat16 h[4];
    __align__(8) __nv_bfloat16 l[4];
    float xs[4] = {x.x, x.y, x.z, x.w};
    #pragma unroll
    for (int j = 0; j < 4; j++) {
        h[j] = __float2bfloat16(xs[j]);
        l[j] = __float2bfloat16(xs[j] - __bfloat162float(h[j]));
    }
    *hq = *reinterpret_cast<uint2*>(h);
    *lq = *reinterpret_cast<uint2*>(l);
}
// fp32 quad -> fp16 hi/lo quads
__device__ __forceinline__ void cvt_hl16(float4 x, uint2* hq, uint2* lq) {
    __align__(8) __half h[4];
    __align__(8) __half l[4];
    float xs[4] = {x.x, x.y, x.z, x.w};
    #pragma unroll
    for (int j = 0; j < 4; j++) {
        h[j] = __float2half_rn(xs[j]);
        l[j] = __float2half_rn(xs[j] - __half2float(h[j]));
    }
    *hq = *reinterpret_cast<uint2*>(h);
    *lq = *reinterpret_cast<uint2*>(l);
}

// ======================= tiling constants =======================
#define KSTEP 32
#define ROWB 80
// energy v4: fp16 2-pass, KSTEP=64, 512 threads, 2-stage 2-barrier, 3 operand tiles
#define EN_K 64
#define EN_ROWB 144                    // 64 fp16 = 128B + 16B pad
#define EN_OP_T (128 * EN_ROWB)        // 18432
#define EN_STAGE (3 * EN_OP_T)         // 55296: Ahi|Alo|Bh
#define EN_RED_OFF (2 * EN_STAGE)      // 110592
#define SMEM_ENERGY (EN_RED_OFF + 512 * 4)   // 112640
// fc (proven): BN=128, inline fp32->bf16 3-pass, 2 stages, occ 2
#define FC_TA (64 * ROWB)
#define FC_TB (128 * ROWB)
#define FC_AHI 0
#define FC_ALO FC_TA
#define FC_BHI (2 * FC_TA)
#define FC_BLO (2 * FC_TA + FC_TB)
#define FC_STAGE (2 * FC_TA + 2 * FC_TB)
#define SMEM_FC (2 * FC_STAGE)

#define ENC_BLOCKS ((M_BT * (H_ / 4)) / 256)   // 32768
#define W_BLOCKS ((H_ * (H_ / 4)) / 256)       // 1024

// ---------------- merged split: enc -> fp16 hi/lo, attn_W[:, H:] -> fp16 ----------------
__global__ void split_all_k(const float* __restrict__ enc,
                            const float* __restrict__ attnW,
                            __half* __restrict__ ehi, __half* __restrict__ elo,
                            __half* __restrict__ wh) {
    if (blockIdx.x < ENC_BLOCKS) {
        size_t i = (size_t)blockIdx.x * 256 + threadIdx.x;
        float4 x = reinterpret_cast<const float4*>(enc)[i];
        uint2 h, l;
        cvt_hl16(x, &h, &l);
        *reinterpret_cast<uint2*>(ehi + 4 * i) = h;
        *reinterpret_cast<uint2*>(elo + 4 * i) = l;
    } else {
        int i = (blockIdx.x - ENC_BLOCKS) * 256 + threadIdx.x;
        int r = i >> 8;
        int k4 = i & 255;
        float4 x = *(reinterpret_cast<const float4*>(attnW + (size_t)r * (2 * H_) + H_) + k4);
        __align__(8) __half h[4];
        h[0] = __float2half_rn(x.x); h[1] = __float2half_rn(x.y);
        h[2] = __float2half_rn(x.z); h[3] = __float2half_rn(x.w);
        *reinterpret_cast<uint2*>(wh + 4 * (size_t)i) = *reinterpret_cast<uint2*>(h);
    }
}

// ---------------- embedding gather ----------------
__global__ void gather_emb_k(const int* __restrict__ x,
                             const float* __restrict__ embW,
                             float* __restrict__ rnn_in) {
    int b = blockIdx.x;
    int row = x[b];
    for (int e = threadIdx.x; e < E_; e += blockDim.x)
        rnn_in[b * (E_ + H_) + e] = embW[(size_t)row * E_ + e];
}

// ---------------- K-split M=64 GEMM ----------------
__global__ void gemm_m64_ks(const float* __restrict__ A, int lda,
                            const float* __restrict__ W, int ldw,
                            float* __restrict__ Cp, int ldc, int kc) {
    __shared__ float As[16][64];
    __shared__ float Ws[16][64];
    const int tid = threadIdx.x;
    const int n0 = blockIdx.x * 64;
    const int kk0 = blockIdx.y * kc;
    const int lrow = tid >> 2;
    const int kq = (tid & 3) * 4;
    const int ty = tid >> 4;
    const int tx = tid & 15;

    float acc[4][4] = {};
    for (int kk = kk0; kk < kk0 + kc; kk += 16) {
        float4 av = *(const float4*)&A[lrow * lda + kk + kq];
        float4 wv = *(const float4*)&W[(size_t)(n0 + lrow) * ldw + kk + kq];
        __syncthreads();
        As[kq + 0][lrow] = av.x; As[kq + 1][lrow] = av.y;
        As[kq + 2][lrow] = av.z; As[kq + 3][lrow] = av.w;
        Ws[kq + 0][lrow] = wv.x; Ws[kq + 1][lrow] = wv.y;
        Ws[kq + 2][lrow] = wv.z; Ws[kq + 3][lrow] = wv.w;
        __syncthreads();
        #pragma unroll
        for (int k = 0; k < 16; k++) {
            float4 a = *(const float4*)&As[k][ty * 4];
            float4 w = *(const float4*)&Ws[k][tx * 4];
            float af[4] = {a.x, a.y, a.z, a.w};
            float wf[4] = {w.x, w.y, w.z, w.w};
            #pragma unroll
            for (int i = 0; i < 4; i++)
                #pragma unroll
                for (int j = 0; j < 4; j++)
                    acc[i][j] = fmaf(af[i], wf[j], acc[i][j]);
        }
    }
    #pragma unroll
    for (int i = 0; i < 4; i++) {
        int m = blockIdx.y * 64 + ty * 4 + i;
        #pragma unroll
        for (int j = 0; j < 4; j++)
            Cp[(size_t)m * ldc + n0 + tx * 4 + j] = acc[i][j];
    }
}

// ---------------- bias partial reduce + transpose ----------------
__global__ void bias_redT_k(const float* __restrict__ part,
                            const float* __restrict__ attb,
                            float* __restrict__ biasT) {
    int idx = blockIdx.x * 256 + threadIdx.x;
    int b = idx >> 10, h = idx & 1023;
    float s = attb[h];
    #pragma unroll
    for (int ks = 0; ks < 8; ks++)
        s += part[(size_t)((ks << 6) + b) * H_ + h];
    biasT[h * B_ + b] = s;
}

// ---------------- energy GEMM v4: fp16 2-pass, KSTEP=64, 2-stage 2-barrier ----------------
__global__ void __launch_bounds__(512, 1)
energy_mma_k(const __half* __restrict__ ehi, const __half* __restrict__ elo,
             const __half* __restrict__ wh,
             const float* __restrict__ biasT, const float* __restrict__ v,
             float* __restrict__ scores) {
    extern __shared__ char sm[];
    const uint32_t sb = smem_u32(sm);
    float* red = (float*)(sm + EN_RED_OFF);

    const int tid = threadIdx.x;
    const int wid = tid >> 5;
    const int lane = tid & 31;
    const int m0 = blockIdx.x * 128;
    const int mw = wid >> 2;       // 0..3: rows mw*32..+31
    const int nw = wid & 3;        // 0..3: cols nw*32..+31 within 128-col chunk

    const int a_l = lane & 15;
    const int a_kh = (lane >> 4) << 3;
    const int b_nb = (lane & 7) + ((lane >> 4) << 3);
    const int b_kh = ((lane >> 3) & 1) << 3;
    const int g = lane >> 2;
    const int t2 = (lane & 3) << 1;

    float acc[2][4][4];            // 32 regs
    float rowsum[4];
    #pragma unroll
    for (int i = 0; i < 4; i++) rowsum[i] = 0.f;

    const int total_it = 8 * 16;   // 8 chunks of 128 cols, 16 k-tiles of 64
    // cp.async map: per op 128 rows x 8 x 16B = 1024 chunks, 2 per thread
    const int cp_r[2] = {tid >> 3, (tid + 512) >> 3};
    const int cp_c = tid & 7;

    #define EN_CP(it_) do {                                                          \
        int chunk_ = (it_) >> 4;                                                     \
        int kb_ = ((it_) & 15) * EN_K;                                               \
        uint32_t stg_ = sb + ((it_) & 1) * EN_STAGE;                                 \
        _Pragma("unroll")                                                            \
        for (int j = 0; j < 2; j++) {                                                \
            uint32_t d_ = stg_ + (uint32_t)(cp_r[j] * EN_ROWB + cp_c * 16);          \
            size_t aoff_ = (size_t)(m0 + cp_r[j]) * H_ + kb_ + cp_c * 8;             \
            size_t boff_ = (size_t)(chunk_ * 128 + cp_r[j]) * H_ + kb_ + cp_c * 8;   \
            CP_ASYNC16(d_ + 0 * EN_OP_T, ehi + aoff_);                               \
            CP_ASYNC16(d_ + 1 * EN_OP_T, elo + aoff_);                               \
            CP_ASYNC16(d_ + 2 * EN_OP_T, wh + boff_);                                \
        }                                                                            \
        CP_COMMIT();                                                                 \
    } while (0)

    EN_CP(0);

    for (int it = 0; it < total_it; it++) {
        const int kt = it & 15;
        const int chunk = it >> 4;
        if (kt == 0) {
            #pragma unroll
            for (int mt = 0; mt < 2; mt++)
                #pragma unroll
                for (int nt = 0; nt < 4; nt++)
                    #pragma unroll
                    for (int k = 0; k < 4; k++) acc[mt][nt][k] = 0.f;
        }
        __syncthreads();           // A-barrier: all reads of stage (it+1)&1 (iter it-1) done
        if (it + 1 < total_it) { EN_CP(it + 1); CP_WAIT1(); }
        else { CP_WAIT0(); }
        __syncthreads();           // B-barrier: stage it&1 complete + visible

        const uint32_t stg = sb + (it & 1) * EN_STAGE;
        #pragma unroll
        for (int ks = 0; ks < 4; ks++) {
            uint32_t Ahi[2][4], Alo[2][4];
            #pragma unroll
            for (int mt = 0; mt < 2; mt++) {
                uint32_t off = (uint32_t)((mw * 32 + mt * 16 + a_l) * EN_ROWB + (ks * 16 + a_kh) * 2);
                ldmx4(Ahi[mt], stg + 0 * EN_OP_T + off);
                ldmx4(Alo[mt], stg + 1 * EN_OP_T + off);
            }
            uint32_t Bh[2][4];
            #pragma unroll
            for (int np = 0; np < 2; np++) {
                uint32_t off = (uint32_t)((nw * 32 + np * 16 + b_nb) * EN_ROWB + (ks * 16 + b_kh) * 2);
                ldmx4(Bh[np], stg + 2 * EN_OP_T + off);
            }
            #pragma unroll
            for (int mt = 0; mt < 2; mt++)
                #pragma unroll
                for (int nt = 0; nt < 4; nt++) {
                    const int np = nt >> 1, pr = (nt & 1) * 2;
                    mma16816h(acc[mt][nt], Ahi[mt], Bh[np][pr], Bh[np][pr + 1]);
                    mma16816h(acc[mt][nt], Alo[mt], Bh[np][pr], Bh[np][pr + 1]);
                }
        }

        if (kt == 15) {
            #pragma unroll
            for (int nt = 0; nt < 4; nt++) {
                const int col0 = chunk * 128 + nw * 32 + nt * 8 + t2;
                const float v0 = __ldg(&v[col0]);
                const float v1 = __ldg(&v[col0 + 1]);
                #pragma unroll
                for (int mt = 0; mt < 2; mt++) {
                    #pragma unroll
                    for (int i = 0; i < 2; i++) {
                        const int row = mw * 32 + mt * 16 + g + i * 8;
                        const int b = row & (B_ - 1);
                        float e0 = acc[mt][nt][i * 2 + 0] + __ldg(&biasT[(size_t)col0 * B_ + b]);
                        float e1 = acc[mt][nt][i * 2 + 1] + __ldg(&biasT[(size_t)(col0 + 1) * B_ + b]);
                        rowsum[mt * 2 + i] += fmaxf(e0, 0.f) * v0 + fmaxf(e1, 0.f) * v1;
                    }
                }
            }
        }
    }

    #pragma unroll
    for (int k = 0; k < 4; k++) {
        rowsum[k] += __shfl_xor_sync(0xFFFFFFFF, rowsum[k], 1);
        rowsum[k] += __shfl_xor_sync(0xFFFFFFFF, rowsum[k], 2);
    }
    __syncthreads();
    if ((lane & 3) == 0) {
        #pragma unroll
        for (int mt = 0; mt < 2; mt++)
            #pragma unroll
            for (int i = 0; i < 2; i++)
                red[nw * 128 + mw * 32 + mt * 16 + g + i * 8] = rowsum[mt * 2 + i];
    }
    __syncthreads();
    if (tid < 128) {
        float s = red[tid] + red[128 + tid] + red[256 + tid] + red[384 + tid];
        scores[m0 + tid] = s;
    }
    #undef EN_CP
}

// ---------------- fc GEMM (proven): BN=128, inline fp32->bf16 3-pass, occ 2 ----------------
__global__ void __launch_bounds__(256, 2)
fc_mma_k(const float* __restrict__ cat2, const float* __restrict__ fcW,
         const float* __restrict__ fcb, float* __restrict__ logits) {
    extern __shared__ char sm[];
    const uint32_t sb = smem_u32(sm);

    const int tid = threadIdx.x;
    const int wid = tid >> 5;
    const int lane = tid & 31;
    const int n0 = blockIdx.x * 128;
    const int mw = wid >> 2;
    const int nw = wid & 3;

    const int a_l = lane & 15;
    const int a_kh = (lane >> 4) << 3;
    const int b_nb = (lane & 7) + ((lane >> 4) << 3);
    const int b_kh = ((lane >> 3) & 1) << 3;
    const int g = lane >> 2;
    const int t2 = (lane & 3) << 1;

    float acc[2][4][4];
    #pragma unroll
    for (int mt = 0; mt < 2; mt++)
        #pragma unroll
        for (int nt = 0; nt < 4; nt++)
            #pragma unroll
            for (int k = 0; k < 4; k++) acc[mt][nt][k] = 0.f;

    const int aro[2] = {tid >> 3, (tid + 256) >> 3};
    const int bro[4] = {tid >> 3, (tid + 256) >> 3, (tid + 512) >> 3, (tid + 768) >> 3};
    const int qc = tid & 7;
    float4 Ar[2], Br[4];

    #define FC_LDG(it_) do {                                                        \
        int kb_ = (it_) * KSTEP;                                                    \
        _Pragma("unroll")                                                           \
        for (int j = 0; j < 2; j++)                                                 \
            Ar[j] = *(const float4*)&cat2[(size_t)aro[j] * (2 * H_) + kb_ + qc * 4];\
        _Pragma("unroll")                                                           \
        for (int j = 0; j < 4; j++)                                                 \
            Br[j] = *(const float4*)&fcW[(size_t)(n0 + bro[j]) * (2 * H_) + kb_ + qc * 4]; \
    } while (0)

    #define FC_STS(it_) do {                                                        \
        char* st_ = sm + ((it_) & 1) * FC_STAGE;                                    \
        _Pragma("unroll")                                                           \
        for (int j = 0; j < 2; j++) {                                               \
            uint2 hq_, lq_;                                                         \
            cvt_hl(Ar[j], &hq_, &lq_);                                              \
            *reinterpret_cast<uint2*>(st_ + FC_AHI + aro[j] * ROWB + qc * 8) = hq_; \
            *reinterpret_cast<uint2*>(st_ + FC_ALO + aro[j] * ROWB + qc * 8) = lq_; \
        }                                                                           \
        _Pragma("unroll")                                                           \
        for (int j = 0; j < 4; j++) {                                               \
            uint2 hq_, lq_;                                                         \
            cvt_hl(Br[j], &hq_, &lq_);                                              \
            *reinterpret_cast<uint2*>(st_ + FC_BHI + bro[j] * ROWB + qc * 8) = hq_; \
            *reinterpret_cast<uint2*>(st_ + FC_BLO + bro[j] * ROWB + qc * 8) = lq_; \
        }                                                                           \
    } while (0)

    const int total_it = 64;
    FC_LDG(0);

    for (int it = 0; it < total_it; it++) {
        __syncthreads();
        FC_STS(it);
        if (it + 1 < total_it) FC_LDG(it + 1);
        __syncthreads();

        const uint32_t stg = sb + (it & 1) * FC_STAGE;
        #pragma unroll
        for (int ks = 0; ks < 2; ks++) {
            uint32_t Ahi[2][4], Alo[2][4];
            #pragma unroll
            for (int mt = 0; mt < 2; mt++) {
                uint32_t off = (uint32_t)((mw * 32 + mt * 16 + a_l) * ROWB + (ks * 16 + a_kh) * 2);
                ldmx4(Ahi[mt], stg + FC_AHI + off);
                ldmx4(Alo[mt], stg + FC_ALO + off);
            }
            uint32_t Bhi[2][4], Blo[2][4];
            #pragma unroll
            for (int np = 0; np < 2; np++) {
                uint32_t off = (uint32_t)((nw * 32 + np * 16 + b_nb) * ROWB + (ks * 16 + b_kh) * 2);
                ldmx4(Bhi[np], stg + FC_BHI + off);
                ldmx4(Blo[np], stg + FC_BLO + off);
            }
            #pragma unroll
            for (int mt = 0; mt < 2; mt++)
                #pragma unroll
                for (int nt = 0; nt < 4; nt++) {
                    const int np = nt >> 1, pr = (nt & 1) * 2;
                    mma16816(acc[mt][nt], Ahi[mt], Bhi[np][pr], Bhi[np][pr + 1]);
                    mma16816(acc[mt][nt], Ahi[mt], Blo[np][pr], Blo[np][pr + 1]);
                    mma16816(acc[mt][nt], Alo[mt], Bhi[np][pr], Bhi[np][pr + 1]);
                }
        }
    }

    #pragma unroll
    for (int nt = 0; nt < 4; nt++) {
        const int col0 = n0 + nw * 32 + nt * 8 + t2;
        const float c0 = __ldg(&fcb[col0]);
        const float c1 = __ldg(&fcb[col0 + 1]);
        #pragma unroll
        for (int mt = 0; mt < 2; mt++) {
            #pragma unroll
            for (int i = 0; i < 2; i++) {
                const int row = mw * 32 + mt * 16 + g + i * 8;
                float2 o;
                o.x = acc[mt][nt][i * 2 + 0] + c0;
                o.y = acc[mt][nt][i * 2 + 1] + c1;
                *reinterpret_cast<float2*>(&logits[(size_t)row * V_ + col0]) = o;
            }
        }
    }
    #undef FC_LDG
    #undef FC_STS
}

// ---------------- softmax over T ----------------
__global__ void softmax_k(const float* __restrict__ scores,
                          float* __restrict__ attn_w_out) {
    int b = blockIdx.x;
    int t = threadIdx.x;
    __shared__ float sh[512];
    float s = scores[t * B_ + b];
    sh[t] = s;
    __syncthreads();
    for (int off = 256; off > 0; off >>= 1) {
        if (t < off) sh[t] = fmaxf(sh[t], sh[t + off]);
        __syncthreads();
    }
    float mx = sh[0];
    __syncthreads();
    float e = expf(s - mx);
    sh[t] = e;
    __syncthreads();
    for (int off = 256; off > 0; off >>= 1) {
        if (t < off) sh[t] += sh[t + off];
        __syncthreads();
    }
    attn_w_out[b * T_ + t] = e / sh[0];
}

// ---------------- context = attn_w @ enc (float4, unroll 8) ----------------
__global__ void context_k(const float4* __restrict__ enc4,
                          const float* __restrict__ attn_w,
                          float* __restrict__ rnn_in,
                          float* __restrict__ cat2) {
    int b = blockIdx.y;
    int h4 = blockIdx.x * 128 + threadIdx.x;
    __shared__ float w[T_];
    for (int t = threadIdx.x; t < T_; t += 128) w[t] = attn_w[b * T_ + t];
    __syncthreads();
    float4 acc = {0.f, 0.f, 0.f, 0.f};
    #pragma unroll 8
    for (int t = 0; t < T_; t++) {
        float4 e = enc4[(size_t)(t * B_ + b) * (H_ / 4) + h4];
        float wt = w[t];
        acc.x = fmaf(wt, e.x, acc.x);
        acc.y = fmaf(wt, e.y, acc.y);
        acc.z = fmaf(wt, e.z, acc.z);
        acc.w = fmaf(wt, e.w, acc.w);
    }
    int h = h4 * 4;
    *reinterpret_cast<float4*>(&rnn_in[b * (E_ + H_) + E_ + h]) = acc;
    *reinterpret_cast<float4*>(&cat2[b * (2 * H_) + H_ + h]) = acc;
}

// ---------------- GRU gates (reduce 8 k-split partials) ----------------
__global__ void gates_k(const float* __restrict__ pgi,
                        const float* __restrict__ pgh,
                        const float* __restrict__ bih,
                        const float* __restrict__ bhh,
                        const float* __restrict__ lh,
                        float* __restrict__ hnew_out,
                        float* __restrict__ cat2) {
    int b = blockIdx.x;
    for (int h = threadIdx.x; h < H_; h += blockDim.x) {
        float gi0 = bih[h], gi1 = bih[H_ + h], gi2 = bih[2 * H_ + h];
        float gh0 = bhh[h], gh1 = bhh[H_ + h], gh2 = bhh[2 * H_ + h];
        #pragma unroll
        for (int ks = 0; ks < 8; ks++) {
            size_t base = (size_t)((ks << 6) + b) * 3 * H_;
            gi0 += pgi[base + h]; gi1 += pgi[base + H_ + h]; gi2 += pgi[base + 2 * H_ + h];
            gh0 += pgh[base + h]; gh1 += pgh[base + H_ + h]; gh2 += pgh[base + 2 * H_ + h];
        }
        float r = 1.f / (1.f + expf(-(gi0 + gh0)));
        float z = 1.f / (1.f + expf(-(gi1 + gh1)));
        float n = tanhf(gi2 + r * gh2);
        float hp = lh[b * H_ + h];
        float hn = (1.f - z) * n + z * hp;
        hnew_out[b * H_ + h] = hn;
        cat2[b * (2 * H_) + h] = hn;
    }
}

// ---------------- log_softmax in-place ----------------
__global__ void logsoftmax_k(float* __restrict__ logits) {
    int b = blockIdx.x;
    int tid = threadIdx.x;
    __shared__ float sh[1024];
    float* row = logits + (size_t)b * V_;
    float mx = -1e30f;
    for (int n = tid; n < V_; n += 1024) mx = fmaxf(mx, row[n]);
    sh[tid] = mx;
    __syncthreads();
    for (int off = 512; off > 0; off >>= 1) {
        if (tid < off) sh[tid] = fmaxf(sh[tid], sh[tid + off]);
        __syncthreads();
    }
    mx = sh[0];
    __syncthreads();
    float sum = 0.f;
    for (int n = tid; n < V_; n += 1024) sum += expf(row[n] - mx);
    sh[tid] = sum;
    __syncthreads();
    for (int off = 512; off > 0; off >>= 1) {
        if (tid < off) sh[tid] += sh[tid + off];
        __syncthreads();
    }
    float lse = mx + logf(sh[0]);
    for (int n = tid; n < V_; n += 1024) row[n] -= lse;
}

// ---------------- launch ----------------
extern "C" void kernel_launch(void* const* d_in, const int* in_sizes, int n_in,
                              void* d_out, int out_size) {
    const int*   x    = (const int*)d_in[0];
    const float* lh   = (const float*)d_in[1];
    const float* enc  = (const float*)d_in[2];
    const float* embW = (const float*)d_in[3];
    const float* attW = (const float*)d_in[4];
    const float* attb = (const float*)d_in[5];
    const float* v    = (const float*)d_in[6];
    const float* Wih  = (const float*)d_in[7];
    const float* Whh  = (const float*)d_in[8];
    const float* bih  = (const float*)d_in[9];
    const float* bhh  = (const float*)d_in[10];
    const float* fcW  = (const float*)d_in[11];
    const float* fcb  = (const float*)d_in[12];

    float* out      = (float*)d_out;
    float* out_logp = out;
    float* out_h    = out + (size_t)B_ * V_;
    float* out_w    = out_h + (size_t)B_ * H_;

    float *rnn_in, *bias_aT, *scoresp, *cat2, *pbias, *pgi, *pgh;
    __half *ehi, *elo, *wh;
    cudaGetSymbolAddress((void**)&rnn_in,  g_rnn_in);
    cudaGetSymbolAddress((void**)&bias_aT, g_bias_aT);
    cudaGetSymbolAddress((void**)&scoresp, g_scores);
    cudaGetSymbolAddress((void**)&cat2,    g_cat2);
    cudaGetSymbolAddress((void**)&pbias,   g_part_bias);
    cudaGetSymbolAddress((void**)&pgi,     g_part_gi);
    cudaGetSymbolAddress((void**)&pgh,     g_part_gh);
    cudaGetSymbolAddress((void**)&ehi,     g_enc_hi);
    cudaGetSymbolAddress((void**)&elo,     g_enc_lo);
    cudaGetSymbolAddress((void**)&wh,      g_w_h);

    cudaFuncSetAttribute(energy_mma_k, cudaFuncAttributeMaxDynamicSharedMemorySize, SMEM_ENERGY);
    cudaFuncSetAttribute(fc_mma_k, cudaFuncAttributeMaxDynamicSharedMemorySize, SMEM_FC);

    // launch order: energy_mma_k stays launch #4 (ncu captures the 4th launch)
    split_all_k<<<ENC_BLOCKS + W_BLOCKS, 256>>>(enc, attW, ehi, elo, wh);             // 1
    gemm_m64_ks<<<dim3(H_ / 64, 8), 256>>>(lh, H_, attW, 2 * H_, pbias, H_, 128);     // 2
    bias_redT_k<<<(B_ * H_) / 256, 256>>>(pbias, attb, bias_aT);                      // 3
    energy_mma_k<<<M_BT / 128, 512, SMEM_ENERGY>>>(ehi, elo, wh, bias_aT, v, scoresp); // 4
    gather_emb_k<<<B_, 128>>>(x, embW, rnn_in);                                       // 5
    softmax_k<<<B_, 512>>>(scoresp, out_w);
    context_k<<<dim3(2, B_), 128>>>((const float4*)enc, out_w, rnn_in, cat2);
    gemm_m64_ks<<<dim3(3 * H_ / 64, 8), 256>>>(rnn_in, E_ + H_, Wih, E_ + H_, pgi, 3 * H_, 192);
    gemm_m64_ks<<<dim3(3 * H_ / 64, 8), 256>>>(lh, H_, Whh, H_, pgh, 3 * H_, 128);
    gates_k<<<B_, 256>>>(pgi, pgh, bih, bhh, lh, out_h, cat2);
    fc_mma_k<<<V_ / 128, 256, SMEM_FC>>>(cat2, fcW, fcb, out_logp);
    logsoftmax_k<<<B_, 1024>>>(out_logp);
}

// round 13
// speedup vs baseline: 1.7262x; 1.2924x over previous
#include <cuda_runtime.h>
#include <cuda_bf16.h>
#include <cuda_fp16.h>
#include <math.h>
#include <stdint.h>

#define B_ 64
#define T_ 512
#define H_ 1024
#define E_ 512
#define V_ 32000
#define M_BT (B_ * T_)        // 32768

// ---------------- scratch (device globals; no allocation allowed) ----------------
__device__ float g_rnn_in[B_ * (E_ + H_)];
__device__ float g_bias_aT[H_ * B_];
__device__ float g_scores[M_BT];
__device__ float g_cat2[B_ * 2 * H_];
__device__ float g_part_bias[8 * B_ * H_];
__device__ float g_part_gi[8 * B_ * 3 * H_];
__device__ float g_part_gh[8 * B_ * 3 * H_];
__device__ __half g_enc_h[(size_t)M_BT * H_];    // 64 MB fp16
__device__ __half g_w_h[H_ * H_];                // 2 MB fp16

// ======================= helpers =======================
__device__ __forceinline__ uint32_t smem_u32(const void* p) {
    uint32_t a;
    asm("{ .reg .u64 t; cvta.to.shared.u64 t, %1; cvt.u32.u64 %0, t; }" : "=r"(a) : "l"(p));
    return a;
}
#define CP_ASYNC16(dst, src) \
    asm volatile("cp.async.cg.shared.global [%0], [%1], 16;" :: "r"(dst), "l"(src))
#define CP_COMMIT() asm volatile("cp.async.commit_group;" ::: "memory")
#define CP_WAIT1() asm volatile("cp.async.wait_group 1;" ::: "memory")
#define CP_WAIT0() asm volatile("cp.async.wait_group 0;" ::: "memory")

__device__ __forceinline__ void ldmx4(uint32_t* r, uint32_t addr) {
    asm volatile("ldmatrix.sync.aligned.m8n8.x4.shared.b16 {%0,%1,%2,%3}, [%4];"
                 : "=r"(r[0]), "=r"(r[1]), "=r"(r[2]), "=r"(r[3]) : "r"(addr));
}
// bf16 mma (fc path)
__device__ __forceinline__ void mma16816(float* d, const uint32_t* a, uint32_t b0, uint32_t b1) {
    asm volatile("mma.sync.aligned.m16n8k16.row.col.f32.bf16.bf16.f32 "
                 "{%0,%1,%2,%3}, {%4,%5,%6,%7}, {%8,%9}, {%0,%1,%2,%3};"
                 : "+f"(d[0]), "+f"(d[1]), "+f"(d[2]), "+f"(d[3])
                 : "r"(a[0]), "r"(a[1]), "r"(a[2]), "r"(a[3]), "r"(b0), "r"(b1));
}
// fp16 mma (energy path)
__device__ __forceinline__ void mma16816h(float* d, const uint32_t* a, uint32_t b0, uint32_t b1) {
    asm volatile("mma.sync.aligned.m16n8k16.row.col.f32.f16.f16.f32 "
                 "{%0,%1,%2,%3}, {%4,%5,%6,%7}, {%8,%9}, {%0,%1,%2,%3};"
                 : "+f"(d[0]), "+f"(d[1]), "+f"(d[2]), "+f"(d[3])
                 : "r"(a[0]), "r"(a[1]), "r"(a[2]), "r"(a[3]), "r"(b0), "r"(b1));
}
// fp32 quad -> bf16 hi/lo quads
__device__ __forceinline__ void cvt_hl(float4 x, uint2* hq, uint2* lq) {
    __align__(8) __nv_bfloat16 h[4];
    __align__(8) __nv_bfloat16 l[4];
    float xs[4] = {x.x, x.y, x.z, x.w};
    #pragma unroll
    for (int j = 0; j < 4; j++) {
        h[j] = __float2bfloat16(xs[j]);
        l[j] = __float2bfloat16(xs[j] - __bfloat162float(h[j]));
    }
    *hq = *reinterpret_cast<uint2*>(h);
    *lq = *reinterpret_cast<uint2*>(l);
}
// fp32 quad -> fp16 quad
__device__ __forceinline__ uint2 cvt_h16(float4 x) {
    __align__(8) __half h[4];
    h[0] = __float2half_rn(x.x); h[1] = __float2half_rn(x.y);
    h[2] = __float2half_rn(x.z); h[3] = __float2half_rn(x.w);
    return *reinterpret_cast<uint2*>(h);
}

// ======================= tiling constants =======================
#define KSTEP 32
#define ROWB 80
// energy v5: fp16 1-pass, KSTEP=64, 512 threads, 2-stage 2-barrier, 2 operand tiles
#define EN_K 64
#define EN_ROWB 144                    // 64 fp16 = 128B + 16B pad
#define EN_OP_T (128 * EN_ROWB)        // 18432
#define EN_STAGE (2 * EN_OP_T)         // 36864: A|B
#define EN_RED_OFF (2 * EN_STAGE)      // 73728
#define SMEM_ENERGY (EN_RED_OFF + 512 * 4)   // 75776
// fc (proven): BN=128, inline fp32->bf16 3-pass, 2 stages, occ 2
#define FC_TA (64 * ROWB)
#define FC_TB (128 * ROWB)
#define FC_AHI 0
#define FC_ALO FC_TA
#define FC_BHI (2 * FC_TA)
#define FC_BLO (2 * FC_TA + FC_TB)
#define FC_STAGE (2 * FC_TA + 2 * FC_TB)
#define SMEM_FC (2 * FC_STAGE)

#define ENC_BLOCKS ((M_BT * (H_ / 4)) / 256)   // 32768
#define W_BLOCKS ((H_ * (H_ / 4)) / 256)       // 1024

// ---------------- merged split: enc -> fp16, attn_W[:, H:] -> fp16 ----------------
__global__ void split_all_k(const float* __restrict__ enc,
                            const float* __restrict__ attnW,
                            __half* __restrict__ eh, __half* __restrict__ wh) {
    if (blockIdx.x < ENC_BLOCKS) {
        size_t i = (size_t)blockIdx.x * 256 + threadIdx.x;
        float4 x = reinterpret_cast<const float4*>(enc)[i];
        *reinterpret_cast<uint2*>(eh + 4 * i) = cvt_h16(x);
    } else {
        int i = (blockIdx.x - ENC_BLOCKS) * 256 + threadIdx.x;
        int r = i >> 8;
        int k4 = i & 255;
        float4 x = *(reinterpret_cast<const float4*>(attnW + (size_t)r * (2 * H_) + H_) + k4);
        *reinterpret_cast<uint2*>(wh + 4 * (size_t)i) = cvt_h16(x);
    }
}

// ---------------- embedding gather ----------------
__global__ void gather_emb_k(const int* __restrict__ x,
                             const float* __restrict__ embW,
                             float* __restrict__ rnn_in) {
    int b = blockIdx.x;
    int row = x[b];
    for (int e = threadIdx.x; e < E_; e += blockDim.x)
        rnn_in[b * (E_ + H_) + e] = embW[(size_t)row * E_ + e];
}

// ---------------- K-split M=64 GEMM ----------------
__global__ void gemm_m64_ks(const float* __restrict__ A, int lda,
                            const float* __restrict__ W, int ldw,
                            float* __restrict__ Cp, int ldc, int kc) {
    __shared__ float As[16][64];
    __shared__ float Ws[16][64];
    const int tid = threadIdx.x;
    const int n0 = blockIdx.x * 64;
    const int kk0 = blockIdx.y * kc;
    const int lrow = tid >> 2;
    const int kq = (tid & 3) * 4;
    const int ty = tid >> 4;
    const int tx = tid & 15;

    float acc[4][4] = {};
    for (int kk = kk0; kk < kk0 + kc; kk += 16) {
        float4 av = *(const float4*)&A[lrow * lda + kk + kq];
        float4 wv = *(const float4*)&W[(size_t)(n0 + lrow) * ldw + kk + kq];
        __syncthreads();
        As[kq + 0][lrow] = av.x; As[kq + 1][lrow] = av.y;
        As[kq + 2][lrow] = av.z; As[kq + 3][lrow] = av.w;
        Ws[kq + 0][lrow] = wv.x; Ws[kq + 1][lrow] = wv.y;
        Ws[kq + 2][lrow] = wv.z; Ws[kq + 3][lrow] = wv.w;
        __syncthreads();
        #pragma unroll
        for (int k = 0; k < 16; k++) {
            float4 a = *(const float4*)&As[k][ty * 4];
            float4 w = *(const float4*)&Ws[k][tx * 4];
            float af[4] = {a.x, a.y, a.z, a.w};
            float wf[4] = {w.x, w.y, w.z, w.w};
            #pragma unroll
            for (int i = 0; i < 4; i++)
                #pragma unroll
                for (int j = 0; j < 4; j++)
                    acc[i][j] = fmaf(af[i], wf[j], acc[i][j]);
        }
    }
    #pragma unroll
    for (int i = 0; i < 4; i++) {
        int m = blockIdx.y * 64 + ty * 4 + i;
        #pragma unroll
        for (int j = 0; j < 4; j++)
            Cp[(size_t)m * ldc + n0 + tx * 4 + j] = acc[i][j];
    }
}

// ---------------- bias partial reduce + transpose ----------------
__global__ void bias_redT_k(const float* __restrict__ part,
                            const float* __restrict__ attb,
                            float* __restrict__ biasT) {
    int idx = blockIdx.x * 256 + threadIdx.x;
    int b = idx >> 10, h = idx & 1023;
    float s = attb[h];
    #pragma unroll
    for (int ks = 0; ks < 8; ks++)
        s += part[(size_t)((ks << 6) + b) * H_ + h];
    biasT[h * B_ + b] = s;
}

// ---------------- energy GEMM v5: fp16 1-pass, KSTEP=64, 2-stage 2-barrier ----------------
__global__ void __launch_bounds__(512, 1)
energy_mma_k(const __half* __restrict__ eh, const __half* __restrict__ wh,
             const float* __restrict__ biasT, const float* __restrict__ v,
             float* __restrict__ scores) {
    extern __shared__ char sm[];
    const uint32_t sb = smem_u32(sm);
    float* red = (float*)(sm + EN_RED_OFF);

    const int tid = threadIdx.x;
    const int wid = tid >> 5;
    const int lane = tid & 31;
    const int m0 = blockIdx.x * 128;
    const int mw = wid >> 2;       // 0..3: rows mw*32..+31
    const int nw = wid & 3;        // 0..3: cols nw*32..+31 within 128-col chunk

    const int a_l = lane & 15;
    const int a_kh = (lane >> 4) << 3;
    const int b_nb = (lane & 7) + ((lane >> 4) << 3);
    const int b_kh = ((lane >> 3) & 1) << 3;
    const int g = lane >> 2;
    const int t2 = (lane & 3) << 1;

    float acc[2][4][4];
    float rowsum[4];
    #pragma unroll
    for (int i = 0; i < 4; i++) rowsum[i] = 0.f;

    const int total_it = 8 * 16;   // 8 chunks of 128 cols, 16 k-tiles of 64
    // cp.async: per op 128 rows x 8 x 16B = 1024 chunks, 2 per thread
    const int cp_r[2] = {tid >> 3, (tid + 512) >> 3};
    const int cp_c = tid & 7;

    #define EN_CP(it_) do {                                                          \
        int chunk_ = (it_) >> 4;                                                     \
        int kb_ = ((it_) & 15) * EN_K;                                               \
        uint32_t stg_ = sb + ((it_) & 1) * EN_STAGE;                                 \
        _Pragma("unroll")                                                            \
        for (int j = 0; j < 2; j++) {                                                \
            uint32_t d_ = stg_ + (uint32_t)(cp_r[j] * EN_ROWB + cp_c * 16);          \
            CP_ASYNC16(d_ + 0 * EN_OP_T, eh + (size_t)(m0 + cp_r[j]) * H_ + kb_ + cp_c * 8); \
            CP_ASYNC16(d_ + 1 * EN_OP_T, wh + (size_t)(chunk_ * 128 + cp_r[j]) * H_ + kb_ + cp_c * 8); \
        }                                                                            \
        CP_COMMIT();                                                                 \
    } while (0)

    EN_CP(0);

    for (int it = 0; it < total_it; it++) {
        const int kt = it & 15;
        const int chunk = it >> 4;
        if (kt == 0) {
            #pragma unroll
            for (int mt = 0; mt < 2; mt++)
                #pragma unroll
                for (int nt = 0; nt < 4; nt++)
                    #pragma unroll
                    for (int k = 0; k < 4; k++) acc[mt][nt][k] = 0.f;
        }
        __syncthreads();           // A-barrier: all reads of stage (it+1)&1 (iter it-1) done
        if (it + 1 < total_it) { EN_CP(it + 1); CP_WAIT1(); }
        else { CP_WAIT0(); }
        __syncthreads();           // B-barrier: stage it&1 complete + visible

        const uint32_t stg = sb + (it & 1) * EN_STAGE;
        #pragma unroll
        for (int ks = 0; ks < 4; ks++) {
            uint32_t Ah[2][4];
            #pragma unroll
            for (int mt = 0; mt < 2; mt++) {
                uint32_t off = (uint32_t)((mw * 32 + mt * 16 + a_l) * EN_ROWB + (ks * 16 + a_kh) * 2);
                ldmx4(Ah[mt], stg + 0 * EN_OP_T + off);
            }
            uint32_t Bh[2][4];
            #pragma unroll
            for (int np = 0; np < 2; np++) {
                uint32_t off = (uint32_t)((nw * 32 + np * 16 + b_nb) * EN_ROWB + (ks * 16 + b_kh) * 2);
                ldmx4(Bh[np], stg + 1 * EN_OP_T + off);
            }
            #pragma unroll
            for (int mt = 0; mt < 2; mt++)
                #pragma unroll
                for (int nt = 0; nt < 4; nt++) {
                    const int np = nt >> 1, pr = (nt & 1) * 2;
                    mma16816h(acc[mt][nt], Ah[mt], Bh[np][pr], Bh[np][pr + 1]);
                }
        }

        if (kt == 15) {
            #pragma unroll
            for (int nt = 0; nt < 4; nt++) {
                const int col0 = chunk * 128 + nw * 32 + nt * 8 + t2;
                const float v0 = __ldg(&v[col0]);
                const float v1 = __ldg(&v[col0 + 1]);
                #pragma unroll
                for (int mt = 0; mt < 2; mt++) {
                    #pragma unroll
                    for (int i = 0; i < 2; i++) {
                        const int row = mw * 32 + mt * 16 + g + i * 8;
                        const int b = row & (B_ - 1);
                        float e0 = acc[mt][nt][i * 2 + 0] + __ldg(&biasT[(size_t)col0 * B_ + b]);
                        float e1 = acc[mt][nt][i * 2 + 1] + __ldg(&biasT[(size_t)(col0 + 1) * B_ + b]);
                        rowsum[mt * 2 + i] += fmaxf(e0, 0.f) * v0 + fmaxf(e1, 0.f) * v1;
                    }
                }
            }
        }
    }

    #pragma unroll
    for (int k = 0; k < 4; k++) {
        rowsum[k] += __shfl_xor_sync(0xFFFFFFFF, rowsum[k], 1);
        rowsum[k] += __shfl_xor_sync(0xFFFFFFFF, rowsum[k], 2);
    }
    __syncthreads();
    if ((lane & 3) == 0) {
        #pragma unroll
        for (int mt = 0; mt < 2; mt++)
            #pragma unroll
            for (int i = 0; i < 2; i++)
                red[nw * 128 + mw * 32 + mt * 16 + g + i * 8] = rowsum[mt * 2 + i];
    }
    __syncthreads();
    if (tid < 128) {
        float s = red[tid] + red[128 + tid] + red[256 + tid] + red[384 + tid];
        scores[m0 + tid] = s;
    }
    #undef EN_CP
}

// ---------------- fc GEMM (proven): BN=128, inline fp32->bf16 3-pass, occ 2 ----------------
__global__ void __launch_bounds__(256, 2)
fc_mma_k(const float* __restrict__ cat2, const float* __restrict__ fcW,
         const float* __restrict__ fcb, float* __restrict__ logits) {
    extern __shared__ char sm[];
    const uint32_t sb = smem_u32(sm);

    const int tid = threadIdx.x;
    const int wid = tid >> 5;
    const int lane = tid & 31;
    const int n0 = blockIdx.x * 128;
    const int mw = wid >> 2;
    const int nw = wid & 3;

    const int a_l = lane & 15;
    const int a_kh = (lane >> 4) << 3;
    const int b_nb = (lane & 7) + ((lane >> 4) << 3);
    const int b_kh = ((lane >> 3) & 1) << 3;
    const int g = lane >> 2;
    const int t2 = (lane & 3) << 1;

    float acc[2][4][4];
    #pragma unroll
    for (int mt = 0; mt < 2; mt++)
        #pragma unroll
        for (int nt = 0; nt < 4; nt++)
            #pragma unroll
            for (int k = 0; k < 4; k++) acc[mt][nt][k] = 0.f;

    const int aro[2] = {tid >> 3, (tid + 256) >> 3};
    const int bro[4] = {tid >> 3, (tid + 256) >> 3, (tid + 512) >> 3, (tid + 768) >> 3};
    const int qc = tid & 7;
    float4 Ar[2], Br[4];

    #define FC_LDG(it_) do {                                                        \
        int kb_ = (it_) * KSTEP;                                                    \
        _Pragma("unroll")                                                           \
        for (int j = 0; j < 2; j++)                                                 \
            Ar[j] = *(const float4*)&cat2[(size_t)aro[j] * (2 * H_) + kb_ + qc * 4];\
        _Pragma("unroll")                                                           \
        for (int j = 0; j < 4; j++)                                                 \
            Br[j] = *(const float4*)&fcW[(size_t)(n0 + bro[j]) * (2 * H_) + kb_ + qc * 4]; \
    } while (0)

    #define FC_STS(it_) do {                                                        \
        char* st_ = sm + ((it_) & 1) * FC_STAGE;                                    \
        _Pragma("unroll")                                                           \
        for (int j = 0; j < 2; j++) {                                               \
            uint2 hq_, lq_;                                                         \
            cvt_hl(Ar[j], &hq_, &lq_);                                              \
            *reinterpret_cast<uint2*>(st_ + FC_AHI + aro[j] * ROWB + qc * 8) = hq_; \
            *reinterpret_cast<uint2*>(st_ + FC_ALO + aro[j] * ROWB + qc * 8) = lq_; \
        }                                                                           \
        _Pragma("unroll")                                                           \
        for (int j = 0; j < 4; j++) {                                               \
            uint2 hq_, lq_;                                                         \
            cvt_hl(Br[j], &hq_, &lq_);                                              \
            *reinterpret_cast<uint2*>(st_ + FC_BHI + bro[j] * ROWB + qc * 8) = hq_; \
            *reinterpret_cast<uint2*>(st_ + FC_BLO + bro[j] * ROWB + qc * 8) = lq_; \
        }                                                                           \
    } while (0)

    const int total_it = 64;
    FC_LDG(0);

    for (int it = 0; it < total_it; it++) {
        __syncthreads();
        FC_STS(it);
        if (it + 1 < total_it) FC_LDG(it + 1);
        __syncthreads();

        const uint32_t stg = sb + (it & 1) * FC_STAGE;
        #pragma unroll
        for (int ks = 0; ks < 2; ks++) {
            uint32_t Ahi[2][4], Alo[2][4];
            #pragma unroll
            for (int mt = 0; mt < 2; mt++) {
                uint32_t off = (uint32_t)((mw * 32 + mt * 16 + a_l) * ROWB + (ks * 16 + a_kh) * 2);
                ldmx4(Ahi[mt], stg + FC_AHI + off);
                ldmx4(Alo[mt], stg + FC_ALO + off);
            }
            uint32_t Bhi[2][4], Blo[2][4];
            #pragma unroll
            for (int np = 0; np < 2; np++) {
                uint32_t off = (uint32_t)((nw * 32 + np * 16 + b_nb) * ROWB + (ks * 16 + b_kh) * 2);
                ldmx4(Bhi[np], stg + FC_BHI + off);
                ldmx4(Blo[np], stg + FC_BLO + off);
            }
            #pragma unroll
            for (int mt = 0; mt < 2; mt++)
                #pragma unroll
                for (int nt = 0; nt < 4; nt++) {
                    const int np = nt >> 1, pr = (nt & 1) * 2;
                    mma16816(acc[mt][nt], Ahi[mt], Bhi[np][pr], Bhi[np][pr + 1]);
                    mma16816(acc[mt][nt], Ahi[mt], Blo[np][pr], Blo[np][pr + 1]);
                    mma16816(acc[mt][nt], Alo[mt], Bhi[np][pr], Bhi[np][pr + 1]);
                }
        }
    }

    #pragma unroll
    for (int nt = 0; nt < 4; nt++) {
        const int col0 = n0 + nw * 32 + nt * 8 + t2;
        const float c0 = __ldg(&fcb[col0]);
        const float c1 = __ldg(&fcb[col0 + 1]);
        #pragma unroll
        for (int mt = 0; mt < 2; mt++) {
            #pragma unroll
            for (int i = 0; i < 2; i++) {
                const int row = mw * 32 + mt * 16 + g + i * 8;
                float2 o;
                o.x = acc[mt][nt][i * 2 + 0] + c0;
                o.y = acc[mt][nt][i * 2 + 1] + c1;
                *reinterpret_cast<float2*>(&logits[(size_t)row * V_ + col0]) = o;
            }
        }
    }
    #undef FC_LDG
    #undef FC_STS
}

// ---------------- softmax over T ----------------
__global__ void softmax_k(const float* __restrict__ scores,
                          float* __restrict__ attn_w_out) {
    int b = blockIdx.x;
    int t = threadIdx.x;
    __shared__ float sh[512];
    float s = scores[t * B_ + b];
    sh[t] = s;
    __syncthreads();
    for (int off = 256; off > 0; off >>= 1) {
        if (t < off) sh[t] = fmaxf(sh[t], sh[t + off]);
        __syncthreads();
    }
    float mx = sh[0];
    __syncthreads();
    float e = expf(s - mx);
    sh[t] = e;
    __syncthreads();
    for (int off = 256; off > 0; off >>= 1) {
        if (t < off) sh[t] += sh[t + off];
        __syncthreads();
    }
    attn_w_out[b * T_ + t] = e / sh[0];
}

// ---------------- context = attn_w @ enc (float4, unroll 8) ----------------
__global__ void context_k(const float4* __restrict__ enc4,
                          const float* __restrict__ attn_w,
                          float* __restrict__ rnn_in,
                          float* __restrict__ cat2) {
    int b = blockIdx.y;
    int h4 = blockIdx.x * 128 + threadIdx.x;
    __shared__ float w[T_];
    for (int t = threadIdx.x; t < T_; t += 128) w[t] = attn_w[b * T_ + t];
    __syncthreads();
    float4 acc = {0.f, 0.f, 0.f, 0.f};
    #pragma unroll 8
    for (int t = 0; t < T_; t++) {
        float4 e = enc4[(size_t)(t * B_ + b) * (H_ / 4) + h4];
        float wt = w[t];
        acc.x = fmaf(wt, e.x, acc.x);
        acc.y = fmaf(wt, e.y, acc.y);
        acc.z = fmaf(wt, e.z, acc.z);
        acc.w = fmaf(wt, e.w, acc.w);
    }
    int h = h4 * 4;
    *reinterpret_cast<float4*>(&rnn_in[b * (E_ + H_) + E_ + h]) = acc;
    *reinterpret_cast<float4*>(&cat2[b * (2 * H_) + H_ + h]) = acc;
}

// ---------------- GRU gates (reduce 8 k-split partials) ----------------
__global__ void gates_k(const float* __restrict__ pgi,
                        const float* __restrict__ pgh,
                        const float* __restrict__ bih,
                        const float* __restrict__ bhh,
                        const float* __restrict__ lh,
                        float* __restrict__ hnew_out,
                        float* __restrict__ cat2) {
    int b = blockIdx.x;
    for (int h = threadIdx.x; h < H_; h += blockDim.x) {
        float gi0 = bih[h], gi1 = bih[H_ + h], gi2 = bih[2 * H_ + h];
        float gh0 = bhh[h], gh1 = bhh[H_ + h], gh2 = bhh[2 * H_ + h];
        #pragma unroll
        for (int ks = 0; ks < 8; ks++) {
            size_t base = (size_t)((ks << 6) + b) * 3 * H_;
            gi0 += pgi[base + h]; gi1 += pgi[base + H_ + h]; gi2 += pgi[base + 2 * H_ + h];
            gh0 += pgh[base + h]; gh1 += pgh[base + H_ + h]; gh2 += pgh[base + 2 * H_ + h];
        }
        float r = 1.f / (1.f + expf(-(gi0 + gh0)));
        float z = 1.f / (1.f + expf(-(gi1 + gh1)));
        float n = tanhf(gi2 + r * gh2);
        float hp = lh[b * H_ + h];
        float hn = (1.f - z) * n + z * hp;
        hnew_out[b * H_ + h] = hn;
        cat2[b * (2 * H_) + h] = hn;
    }
}

// ---------------- log_softmax in-place ----------------
__global__ void logsoftmax_k(float* __restrict__ logits) {
    int b = blockIdx.x;
    int tid = threadIdx.x;
    __shared__ float sh[1024];
    float* row = logits + (size_t)b * V_;
    float mx = -1e30f;
    for (int n = tid; n < V_; n += 1024) mx = fmaxf(mx, row[n]);
    sh[tid] = mx;
    __syncthreads();
    for (int off = 512; off > 0; off >>= 1) {
        if (tid < off) sh[tid] = fmaxf(sh[tid], sh[tid + off]);
        __syncthreads();
    }
    mx = sh[0];
    __syncthreads();
    float sum = 0.f;
    for (int n = tid; n < V_; n += 1024) sum += expf(row[n] - mx);
    sh[tid] = sum;
    __syncthreads();
    for (int off = 512; off > 0; off >>= 1) {
        if (tid < off) sh[tid] += sh[tid + off];
        __syncthreads();
    }
    float lse = mx + logf(sh[0]);
    for (int n = tid; n < V_; n += 1024) row[n] -= lse;
}

// ---------------- launch ----------------
extern "C" void kernel_launch(void* const* d_in, const int* in_sizes, int n_in,
                              void* d_out, int out_size) {
    const int*   x    = (const int*)d_in[0];
    const float* lh   = (const float*)d_in[1];
    const float* enc  = (const float*)d_in[2];
    const float* embW = (const float*)d_in[3];
    const float* attW = (const float*)d_in[4];
    const float* attb = (const float*)d_in[5];
    const float* v    = (const float*)d_in[6];
    const float* Wih  = (const float*)d_in[7];
    const float* Whh  = (const float*)d_in[8];
    const float* bih  = (const float*)d_in[9];
    const float* bhh  = (const float*)d_in[10];
    const float* fcW  = (const float*)d_in[11];
    const float* fcb  = (const float*)d_in[12];

    float* out      = (float*)d_out;
    float* out_logp = out;
    float* out_h    = out + (size_t)B_ * V_;
    float* out_w    = out_h + (size_t)B_ * H_;

    float *rnn_in, *bias_aT, *scoresp, *cat2, *pbias, *pgi, *pgh;
    __half *eh, *wh;
    cudaGetSymbolAddress((void**)&rnn_in,  g_rnn_in);
    cudaGetSymbolAddress((void**)&bias_aT, g_bias_aT);
    cudaGetSymbolAddress((void**)&scoresp, g_scores);
    cudaGetSymbolAddress((void**)&cat2,    g_cat2);
    cudaGetSymbolAddress((void**)&pbias,   g_part_bias);
    cudaGetSymbolAddress((void**)&pgi,     g_part_gi);
    cudaGetSymbolAddress((void**)&pgh,     g_part_gh);
    cudaGetSymbolAddress((void**)&eh,      g_enc_h);
    cudaGetSymbolAddress((void**)&wh,      g_w_h);

    cudaFuncSetAttribute(energy_mma_k, cudaFuncAttributeMaxDynamicSharedMemorySize, SMEM_ENERGY);
    cudaFuncSetAttribute(fc_mma_k, cudaFuncAttributeMaxDynamicSharedMemorySize, SMEM_FC);

    // launch order: energy_mma_k stays launch #4 (ncu captures the 4th launch)
    split_all_k<<<ENC_BLOCKS + W_BLOCKS, 256>>>(enc, attW, eh, wh);                   // 1
    gemm_m64_ks<<<dim3(H_ / 64, 8), 256>>>(lh, H_, attW, 2 * H_, pbias, H_, 128);     // 2
    bias_redT_k<<<(B_ * H_) / 256, 256>>>(pbias, attb, bias_aT);                      // 3
    energy_mma_k<<<M_BT / 128, 512, SMEM_ENERGY>>>(eh, wh, bias_aT, v, scoresp);      // 4
    gather_emb_k<<<B_, 128>>>(x, embW, rnn_in);                                       // 5
    softmax_k<<<B_, 512>>>(scoresp, out_w);
    context_k<<<dim3(2, B_), 128>>>((const float4*)enc, out_w, rnn_in, cat2);
    gemm_m64_ks<<<dim3(3 * H_ / 64, 8), 256>>>(rnn_in, E_ + H_, Wih, E_ + H_, pgi, 3 * H_, 192);
    gemm_m64_ks<<<dim3(3 * H_ / 64, 8), 256>>>(lh, H_, Whh, H_, pgh, 3 * H_, 128);
    gates_k<<<B_, 256>>>(pgi, pgh, bih, bhh, lh, out_h, cat2);
    fc_mma_k<<<V_ / 128, 256, SMEM_FC>>>(cat2, fcW, fcb, out_logp);
    logsoftmax_k<<<B_, 1024>>>(out_logp);
}

// round 14
// speedup vs baseline: 1.7901x; 1.0370x over previous
#include <cuda_runtime.h>
#include <cuda_bf16.h>
#include <cuda_fp16.h>
#include <math.h>
#include <stdint.h>

#define B_ 64
#define T_ 512
#define H_ 1024
#define E_ 512
#define V_ 32000
#define M_BT (B_ * T_)        // 32768

// ---------------- scratch (device globals; no allocation allowed) ----------------
__device__ float g_rnn_in[B_ * (E_ + H_)];
__device__ float g_bias_aT[H_ * B_];
__device__ float g_scores[M_BT];
__device__ float g_cat2[B_ * 2 * H_];
__device__ float g_part_bias[8 * B_ * H_];
__device__ float g_part_gi[8 * B_ * 3 * H_];
__device__ float g_part_gh[8 * B_ * 3 * H_];
__device__ __half g_enc_h[(size_t)M_BT * H_];    // 64 MB fp16
__device__ __half g_w_h[H_ * H_];                // 2 MB fp16

// ======================= helpers =======================
__device__ __forceinline__ uint32_t smem_u32(const void* p) {
    uint32_t a;
    asm("{ .reg .u64 t; cvta.to.shared.u64 t, %1; cvt.u32.u64 %0, t; }" : "=r"(a) : "l"(p));
    return a;
}
#define CP_ASYNC16(dst, src) \
    asm volatile("cp.async.cg.shared.global [%0], [%1], 16;" :: "r"(dst), "l"(src))
#define CP_COMMIT() asm volatile("cp.async.commit_group;" ::: "memory")
#define CP_WAIT3() asm volatile("cp.async.wait_group 3;" ::: "memory")
#define CP_WAIT2() asm volatile("cp.async.wait_group 2;" ::: "memory")
#define CP_WAIT1() asm volatile("cp.async.wait_group 1;" ::: "memory")
#define CP_WAIT0() asm volatile("cp.async.wait_group 0;" ::: "memory")

__device__ __forceinline__ void ldmx4(uint32_t* r, uint32_t addr) {
    asm volatile("ldmatrix.sync.aligned.m8n8.x4.shared.b16 {%0,%1,%2,%3}, [%4];"
                 : "=r"(r[0]), "=r"(r[1]), "=r"(r[2]), "=r"(r[3]) : "r"(addr));
}
// fp16 mma
__device__ __forceinline__ void mma16816h(float* d, const uint32_t* a, uint32_t b0, uint32_t b1) {
    asm volatile("mma.sync.aligned.m16n8k16.row.col.f32.f16.f16.f32 "
                 "{%0,%1,%2,%3}, {%4,%5,%6,%7}, {%8,%9}, {%0,%1,%2,%3};"
                 : "+f"(d[0]), "+f"(d[1]), "+f"(d[2]), "+f"(d[3])
                 : "r"(a[0]), "r"(a[1]), "r"(a[2]), "r"(a[3]), "r"(b0), "r"(b1));
}
// fp32 quad -> fp16 quad
__device__ __forceinline__ uint2 cvt_h16(float4 x) {
    __align__(8) __half h[4];
    h[0] = __float2half_rn(x.x); h[1] = __float2half_rn(x.y);
    h[2] = __float2half_rn(x.z); h[3] = __float2half_rn(x.w);
    return *reinterpret_cast<uint2*>(h);
}

// ======================= tiling constants =======================
#define KSTEP 32
#define ROWB 80
// energy v6: fp16 1-pass, KSTEP=64, 512 threads, 4-stage ring, prefetch depth 3
#define EN_K 64
#define EN_ROWB 144
#define EN_OP_T (128 * EN_ROWB)        // 18432
#define EN_STAGE (2 * EN_OP_T)         // 36864: A|B
#define EN_NSTAGE 4
#define EN_RED_OFF (EN_NSTAGE * EN_STAGE)     // 147456
#define SMEM_ENERGY (EN_RED_OFF + 512 * 4)    // 149504
// fc v2: fp16 1-pass, BN=128, inline fp32->fp16, 2 stages
#define FC_TA (64 * ROWB)              // 5120
#define FC_TB (128 * ROWB)             // 10240
#define FC_A 0
#define FC_B FC_TA
#define FC_STAGE (FC_TA + FC_TB)       // 15360
#define SMEM_FC (2 * FC_STAGE)         // 30720

#define ENC_BLOCKS ((M_BT * (H_ / 4)) / 256)   // 32768
#define W_BLOCKS ((H_ * (H_ / 4)) / 256)       // 1024

// ---------------- merged split: enc -> fp16, attn_W[:, H:] -> fp16 ----------------
__global__ void split_all_k(const float* __restrict__ enc,
                            const float* __restrict__ attnW,
                            __half* __restrict__ eh, __half* __restrict__ wh) {
    if (blockIdx.x < ENC_BLOCKS) {
        size_t i = (size_t)blockIdx.x * 256 + threadIdx.x;
        float4 x = reinterpret_cast<const float4*>(enc)[i];
        *reinterpret_cast<uint2*>(eh + 4 * i) = cvt_h16(x);
    } else {
        int i = (blockIdx.x - ENC_BLOCKS) * 256 + threadIdx.x;
        int r = i >> 8;
        int k4 = i & 255;
        float4 x = *(reinterpret_cast<const float4*>(attnW + (size_t)r * (2 * H_) + H_) + k4);
        *reinterpret_cast<uint2*>(wh + 4 * (size_t)i) = cvt_h16(x);
    }
}

// ---------------- embedding gather ----------------
__global__ void gather_emb_k(const int* __restrict__ x,
                             const float* __restrict__ embW,
                             float* __restrict__ rnn_in) {
    int b = blockIdx.x;
    int row = x[b];
    for (int e = threadIdx.x; e < E_; e += blockDim.x)
        rnn_in[b * (E_ + H_) + e] = embW[(size_t)row * E_ + e];
}

// ---------------- K-split M=64 GEMM ----------------
__global__ void gemm_m64_ks(const float* __restrict__ A, int lda,
                            const float* __restrict__ W, int ldw,
                            float* __restrict__ Cp, int ldc, int kc) {
    __shared__ float As[16][64];
    __shared__ float Ws[16][64];
    const int tid = threadIdx.x;
    const int n0 = blockIdx.x * 64;
    const int kk0 = blockIdx.y * kc;
    const int lrow = tid >> 2;
    const int kq = (tid & 3) * 4;
    const int ty = tid >> 4;
    const int tx = tid & 15;

    float acc[4][4] = {};
    for (int kk = kk0; kk < kk0 + kc; kk += 16) {
        float4 av = *(const float4*)&A[lrow * lda + kk + kq];
        float4 wv = *(const float4*)&W[(size_t)(n0 + lrow) * ldw + kk + kq];
        __syncthreads();
        As[kq + 0][lrow] = av.x; As[kq + 1][lrow] = av.y;
        As[kq + 2][lrow] = av.z; As[kq + 3][lrow] = av.w;
        Ws[kq + 0][lrow] = wv.x; Ws[kq + 1][lrow] = wv.y;
        Ws[kq + 2][lrow] = wv.z; Ws[kq + 3][lrow] = wv.w;
        __syncthreads();
        #pragma unroll
        for (int k = 0; k < 16; k++) {
            float4 a = *(const float4*)&As[k][ty * 4];
            float4 w = *(const float4*)&Ws[k][tx * 4];
            float af[4] = {a.x, a.y, a.z, a.w};
            float wf[4] = {w.x, w.y, w.z, w.w};
            #pragma unroll
            for (int i = 0; i < 4; i++)
                #pragma unroll
                for (int j = 0; j < 4; j++)
                    acc[i][j] = fmaf(af[i], wf[j], acc[i][j]);
        }
    }
    #pragma unroll
    for (int i = 0; i < 4; i++) {
        int m = blockIdx.y * 64 + ty * 4 + i;
        #pragma unroll
        for (int j = 0; j < 4; j++)
            Cp[(size_t)m * ldc + n0 + tx * 4 + j] = acc[i][j];
    }
}

// ---------------- bias partial reduce + transpose ----------------
__global__ void bias_redT_k(const float* __restrict__ part,
                            const float* __restrict__ attb,
                            float* __restrict__ biasT) {
    int idx = blockIdx.x * 256 + threadIdx.x;
    int b = idx >> 10, h = idx & 1023;
    float s = attb[h];
    #pragma unroll
    for (int ks = 0; ks < 8; ks++)
        s += part[(size_t)((ks << 6) + b) * H_ + h];
    biasT[h * B_ + b] = s;
}

// ---------------- energy GEMM v6: fp16 1-pass, 4-stage ring, depth-3 prefetch ----------------
__global__ void __launch_bounds__(512, 1)
energy_mma_k(const __half* __restrict__ eh, const __half* __restrict__ wh,
             const float* __restrict__ biasT, const float* __restrict__ v,
             float* __restrict__ scores) {
    extern __shared__ char sm[];
    const uint32_t sb = smem_u32(sm);
    float* red = (float*)(sm + EN_RED_OFF);

    const int tid = threadIdx.x;
    const int wid = tid >> 5;
    const int lane = tid & 31;
    const int m0 = blockIdx.x * 128;
    const int mw = wid >> 2;
    const int nw = wid & 3;

    const int a_l = lane & 15;
    const int a_kh = (lane >> 4) << 3;
    const int b_nb = (lane & 7) + ((lane >> 4) << 3);
    const int b_kh = ((lane >> 3) & 1) << 3;
    const int g = lane >> 2;
    const int t2 = (lane & 3) << 1;

    float acc[2][4][4];
    float rowsum[4];
    #pragma unroll
    for (int i = 0; i < 4; i++) rowsum[i] = 0.f;

    const int total_it = 8 * 16;
    const int cp_r[2] = {tid >> 3, (tid + 512) >> 3};
    const int cp_c = tid & 7;

    #define EN_CP(it_) do {                                                          \
        int chunk_ = (it_) >> 4;                                                     \
        int kb_ = ((it_) & 15) * EN_K;                                               \
        uint32_t stg_ = sb + ((it_) & 3) * EN_STAGE;                                 \
        _Pragma("unroll")                                                            \
        for (int j = 0; j < 2; j++) {                                                \
            uint32_t d_ = stg_ + (uint32_t)(cp_r[j] * EN_ROWB + cp_c * 16);          \
            CP_ASYNC16(d_ + 0 * EN_OP_T, eh + (size_t)(m0 + cp_r[j]) * H_ + kb_ + cp_c * 8); \
            CP_ASYNC16(d_ + 1 * EN_OP_T, wh + (size_t)(chunk_ * 128 + cp_r[j]) * H_ + kb_ + cp_c * 8); \
        }                                                                            \
        CP_COMMIT();                                                                 \
    } while (0)

    EN_CP(0);
    EN_CP(1);
    EN_CP(2);

    for (int it = 0; it < total_it; it++) {
        const int kt = it & 15;
        const int chunk = it >> 4;
        if (kt == 0) {
            #pragma unroll
            for (int mt = 0; mt < 2; mt++)
                #pragma unroll
                for (int nt = 0; nt < 4; nt++)
                    #pragma unroll
                    for (int k = 0; k < 4; k++) acc[mt][nt][k] = 0.f;
        }
        __syncthreads();           // A-barrier: reads of iter it-1 (stage (it+3)&3) done
        if (it + 3 < total_it) { EN_CP(it + 3); CP_WAIT3(); }
        else if (it + 2 < total_it) { CP_WAIT2(); }
        else if (it + 1 < total_it) { CP_WAIT1(); }
        else { CP_WAIT0(); }
        __syncthreads();           // B-barrier: stage it&3 complete + visible

        const uint32_t stg = sb + (it & 3) * EN_STAGE;
        #pragma unroll
        for (int ks = 0; ks < 4; ks++) {
            uint32_t Ah[2][4];
            #pragma unroll
            for (int mt = 0; mt < 2; mt++) {
                uint32_t off = (uint32_t)((mw * 32 + mt * 16 + a_l) * EN_ROWB + (ks * 16 + a_kh) * 2);
                ldmx4(Ah[mt], stg + 0 * EN_OP_T + off);
            }
            uint32_t Bh[2][4];
            #pragma unroll
            for (int np = 0; np < 2; np++) {
                uint32_t off = (uint32_t)((nw * 32 + np * 16 + b_nb) * EN_ROWB + (ks * 16 + b_kh) * 2);
                ldmx4(Bh[np], stg + 1 * EN_OP_T + off);
            }
            #pragma unroll
            for (int mt = 0; mt < 2; mt++)
                #pragma unroll
                for (int nt = 0; nt < 4; nt++) {
                    const int np = nt >> 1, pr = (nt & 1) * 2;
                    mma16816h(acc[mt][nt], Ah[mt], Bh[np][pr], Bh[np][pr + 1]);
                }
        }

        if (kt == 15) {
            #pragma unroll
            for (int nt = 0; nt < 4; nt++) {
                const int col0 = chunk * 128 + nw * 32 + nt * 8 + t2;
                const float v0 = __ldg(&v[col0]);
                const float v1 = __ldg(&v[col0 + 1]);
                #pragma unroll
                for (int mt = 0; mt < 2; mt++) {
                    #pragma unroll
                    for (int i = 0; i < 2; i++) {
                        const int row = mw * 32 + mt * 16 + g + i * 8;
                        const int b = row & (B_ - 1);
                        float e0 = acc[mt][nt][i * 2 + 0] + __ldg(&biasT[(size_t)col0 * B_ + b]);
                        float e1 = acc[mt][nt][i * 2 + 1] + __ldg(&biasT[(size_t)(col0 + 1) * B_ + b]);
                        rowsum[mt * 2 + i] += fmaxf(e0, 0.f) * v0 + fmaxf(e1, 0.f) * v1;
                    }
                }
            }
        }
    }

    #pragma unroll
    for (int k = 0; k < 4; k++) {
        rowsum[k] += __shfl_xor_sync(0xFFFFFFFF, rowsum[k], 1);
        rowsum[k] += __shfl_xor_sync(0xFFFFFFFF, rowsum[k], 2);
    }
    __syncthreads();
    if ((lane & 3) == 0) {
        #pragma unroll
        for (int mt = 0; mt < 2; mt++)
            #pragma unroll
            for (int i = 0; i < 2; i++)
                red[nw * 128 + mw * 32 + mt * 16 + g + i * 8] = rowsum[mt * 2 + i];
    }
    __syncthreads();
    if (tid < 128) {
        float s = red[tid] + red[128 + tid] + red[256 + tid] + red[384 + tid];
        scores[m0 + tid] = s;
    }
    #undef EN_CP
}

// ---------------- fc GEMM v2: fp16 1-pass, BN=128, inline fp32->fp16, occ 2 ----------------
__global__ void __launch_bounds__(256, 2)
fc_mma_k(const float* __restrict__ cat2, const float* __restrict__ fcW,
         const float* __restrict__ fcb, float* __restrict__ logits) {
    extern __shared__ char sm[];
    const uint32_t sb = smem_u32(sm);

    const int tid = threadIdx.x;
    const int wid = tid >> 5;
    const int lane = tid & 31;
    const int n0 = blockIdx.x * 128;
    const int mw = wid >> 2;
    const int nw = wid & 3;

    const int a_l = lane & 15;
    const int a_kh = (lane >> 4) << 3;
    const int b_nb = (lane & 7) + ((lane >> 4) << 3);
    const int b_kh = ((lane >> 3) & 1) << 3;
    const int g = lane >> 2;
    const int t2 = (lane & 3) << 1;

    float acc[2][4][4];
    #pragma unroll
    for (int mt = 0; mt < 2; mt++)
        #pragma unroll
        for (int nt = 0; nt < 4; nt++)
            #pragma unroll
            for (int k = 0; k < 4; k++) acc[mt][nt][k] = 0.f;

    const int aro[2] = {tid >> 3, (tid + 256) >> 3};
    const int bro[4] = {tid >> 3, (tid + 256) >> 3, (tid + 512) >> 3, (tid + 768) >> 3};
    const int qc = tid & 7;
    float4 Ar[2], Br[4];

    #define FC_LDG(it_) do {                                                        \
        int kb_ = (it_) * KSTEP;                                                    \
        _Pragma("unroll")                                                           \
        for (int j = 0; j < 2; j++)                                                 \
            Ar[j] = *(const float4*)&cat2[(size_t)aro[j] * (2 * H_) + kb_ + qc * 4];\
        _Pragma("unroll")                                                           \
        for (int j = 0; j < 4; j++)                                                 \
            Br[j] = *(const float4*)&fcW[(size_t)(n0 + bro[j]) * (2 * H_) + kb_ + qc * 4]; \
    } while (0)

    #define FC_STS(it_) do {                                                        \
        char* st_ = sm + ((it_) & 1) * FC_STAGE;                                    \
        _Pragma("unroll")                                                           \
        for (int j = 0; j < 2; j++)                                                 \
            *reinterpret_cast<uint2*>(st_ + FC_A + aro[j] * ROWB + qc * 8) = cvt_h16(Ar[j]); \
        _Pragma("unroll")                                                           \
        for (int j = 0; j < 4; j++)                                                 \
            *reinterpret_cast<uint2*>(st_ + FC_B + bro[j] * ROWB + qc * 8) = cvt_h16(Br[j]); \
    } while (0)

    const int total_it = 64;
    FC_LDG(0);

    for (int it = 0; it < total_it; it++) {
        __syncthreads();
        FC_STS(it);
        if (it + 1 < total_it) FC_LDG(it + 1);
        __syncthreads();

        const uint32_t stg = sb + (it & 1) * FC_STAGE;
        #pragma unroll
        for (int ks = 0; ks < 2; ks++) {
            uint32_t Ah[2][4];
            #pragma unroll
            for (int mt = 0; mt < 2; mt++) {
                uint32_t off = (uint32_t)((mw * 32 + mt * 16 + a_l) * ROWB + (ks * 16 + a_kh) * 2);
                ldmx4(Ah[mt], stg + FC_A + off);
            }
            uint32_t Bh[2][4];
            #pragma unroll
            for (int np = 0; np < 2; np++) {
                uint32_t off = (uint32_t)((nw * 32 + np * 16 + b_nb) * ROWB + (ks * 16 + b_kh) * 2);
                ldmx4(Bh[np], stg + FC_B + off);
            }
            #pragma unroll
            for (int mt = 0; mt < 2; mt++)
                #pragma unroll
                for (int nt = 0; nt < 4; nt++) {
                    const int np = nt >> 1, pr = (nt & 1) * 2;
                    mma16816h(acc[mt][nt], Ah[mt], Bh[np][pr], Bh[np][pr + 1]);
                }
        }
    }

    #pragma unroll
    for (int nt = 0; nt < 4; nt++) {
        const int col0 = n0 + nw * 32 + nt * 8 + t2;
        const float c0 = __ldg(&fcb[col0]);
        const float c1 = __ldg(&fcb[col0 + 1]);
        #pragma unroll
        for (int mt = 0; mt < 2; mt++) {
            #pragma unroll
            for (int i = 0; i < 2; i++) {
                const int row = mw * 32 + mt * 16 + g + i * 8;
                float2 o;
                o.x = acc[mt][nt][i * 2 + 0] + c0;
                o.y = acc[mt][nt][i * 2 + 1] + c1;
                *reinterpret_cast<float2*>(&logits[(size_t)row * V_ + col0]) = o;
            }
        }
    }
    #undef FC_LDG
    #undef FC_STS
}

// ---------------- softmax over T ----------------
__global__ void softmax_k(const float* __restrict__ scores,
                          float* __restrict__ attn_w_out) {
    int b = blockIdx.x;
    int t = threadIdx.x;
    __shared__ float sh[512];
    float s = scores[t * B_ + b];
    sh[t] = s;
    __syncthreads();
    for (int off = 256; off > 0; off >>= 1) {
        if (t < off) sh[t] = fmaxf(sh[t], sh[t + off]);
        __syncthreads();
    }
    float mx = sh[0];
    __syncthreads();
    float e = expf(s - mx);
    sh[t] = e;
    __syncthreads();
    for (int off = 256; off > 0; off >>= 1) {
        if (t < off) sh[t] += sh[t + off];
        __syncthreads();
    }
    attn_w_out[b * T_ + t] = e / sh[0];
}

// ---------------- context = attn_w @ enc (float4, unroll 8) ----------------
__global__ void context_k(const float4* __restrict__ enc4,
                          const float* __restrict__ attn_w,
                          float* __restrict__ rnn_in,
                          float* __restrict__ cat2) {
    int b = blockIdx.y;
    int h4 = blockIdx.x * 128 + threadIdx.x;
    __shared__ float w[T_];
    for (int t = threadIdx.x; t < T_; t += 128) w[t] = attn_w[b * T_ + t];
    __syncthreads();
    float4 acc = {0.f, 0.f, 0.f, 0.f};
    #pragma unroll 8
    for (int t = 0; t < T_; t++) {
        float4 e = enc4[(size_t)(t * B_ + b) * (H_ / 4) + h4];
        float wt = w[t];
        acc.x = fmaf(wt, e.x, acc.x);
        acc.y = fmaf(wt, e.y, acc.y);
        acc.z = fmaf(wt, e.z, acc.z);
        acc.w = fmaf(wt, e.w, acc.w);
    }
    int h = h4 * 4;
    *reinterpret_cast<float4*>(&rnn_in[b * (E_ + H_) + E_ + h]) = acc;
    *reinterpret_cast<float4*>(&cat2[b * (2 * H_) + H_ + h]) = acc;
}

// ---------------- GRU gates (reduce 8 k-split partials) ----------------
__global__ void gates_k(const float* __restrict__ pgi,
                        const float* __restrict__ pgh,
                        const float* __restrict__ bih,
                        const float* __restrict__ bhh,
                        const float* __restrict__ lh,
                        float* __restrict__ hnew_out,
                        float* __restrict__ cat2) {
    int b = blockIdx.x;
    for (int h = threadIdx.x; h < H_; h += blockDim.x) {
        float gi0 = bih[h], gi1 = bih[H_ + h], gi2 = bih[2 * H_ + h];
        float gh0 = bhh[h], gh1 = bhh[H_ + h], gh2 = bhh[2 * H_ + h];
        #pragma unroll
        for (int ks = 0; ks < 8; ks++) {
            size_t base = (size_t)((ks << 6) + b) * 3 * H_;
            gi0 += pgi[base + h]; gi1 += pgi[base + H_ + h]; gi2 += pgi[base + 2 * H_ + h];
            gh0 += pgh[base + h]; gh1 += pgh[base + H_ + h]; gh2 += pgh[base + 2 * H_ + h];
        }
        float r = 1.f / (1.f + expf(-(gi0 + gh0)));
        float z = 1.f / (1.f + expf(-(gi1 + gh1)));
        float n = tanhf(gi2 + r * gh2);
        float hp = lh[b * H_ + h];
        float hn = (1.f - z) * n + z * hp;
        hnew_out[b * H_ + h] = hn;
        cat2[b * (2 * H_) + h] = hn;
    }
}

// ---------------- log_softmax in-place ----------------
__global__ void logsoftmax_k(float* __restrict__ logits) {
    int b = blockIdx.x;
    int tid = threadIdx.x;
    __shared__ float sh[1024];
    float* row = logits + (size_t)b * V_;
    float mx = -1e30f;
    for (int n = tid; n < V_; n += 1024) mx = fmaxf(mx, row[n]);
    sh[tid] = mx;
    __syncthreads();
    for (int off = 512; off > 0; off >>= 1) {
        if (tid < off) sh[tid] = fmaxf(sh[tid], sh[tid + off]);
        __syncthreads();
    }
    mx = sh[0];
    __syncthreads();
    float sum = 0.f;
    for (int n = tid; n < V_; n += 1024) sum += expf(row[n] - mx);
    sh[tid] = sum;
    __syncthreads();
    for (int off = 512; off > 0; off >>= 1) {
        if (tid < off) sh[tid] += sh[tid + off];
        __syncthreads();
    }
    float lse = mx + logf(sh[0]);
    for (int n = tid; n < V_; n += 1024) row[n] -= lse;
}

// ---------------- launch ----------------
extern "C" void kernel_launch(void* const* d_in, const int* in_sizes, int n_in,
                              void* d_out, int out_size) {
    const int*   x    = (const int*)d_in[0];
    const float* lh   = (const float*)d_in[1];
    const float* enc  = (const float*)d_in[2];
    const float* embW = (const float*)d_in[3];
    const float* attW = (const float*)d_in[4];
    const float* attb = (const float*)d_in[5];
    const float* v    = (const float*)d_in[6];
    const float* Wih  = (const float*)d_in[7];
    const float* Whh  = (const float*)d_in[8];
    const float* bih  = (const float*)d_in[9];
    const float* bhh  = (const float*)d_in[10];
    const float* fcW  = (const float*)d_in[11];
    const float* fcb  = (const float*)d_in[12];

    float* out      = (float*)d_out;
    float* out_logp = out;
    float* out_h    = out + (size_t)B_ * V_;
    float* out_w    = out_h + (size_t)B_ * H_;

    float *rnn_in, *bias_aT, *scoresp, *cat2, *pbias, *pgi, *pgh;
    __half *eh, *wh;
    cudaGetSymbolAddress((void**)&rnn_in,  g_rnn_in);
    cudaGetSymbolAddress((void**)&bias_aT, g_bias_aT);
    cudaGetSymbolAddress((void**)&scoresp, g_scores);
    cudaGetSymbolAddress((void**)&cat2,    g_cat2);
    cudaGetSymbolAddress((void**)&pbias,   g_part_bias);
    cudaGetSymbolAddress((void**)&pgi,     g_part_gi);
    cudaGetSymbolAddress((void**)&pgh,     g_part_gh);
    cudaGetSymbolAddress((void**)&eh,      g_enc_h);
    cudaGetSymbolAddress((void**)&wh,      g_w_h);

    cudaFuncSetAttribute(energy_mma_k, cudaFuncAttributeMaxDynamicSharedMemorySize, SMEM_ENERGY);
    cudaFuncSetAttribute(fc_mma_k, cudaFuncAttributeMaxDynamicSharedMemorySize, SMEM_FC);

    // launch order: energy_mma_k stays launch #4 (ncu captures the 4th launch)
    split_all_k<<<ENC_BLOCKS + W_BLOCKS, 256>>>(enc, attW, eh, wh);                   // 1
    gemm_m64_ks<<<dim3(H_ / 64, 8), 256>>>(lh, H_, attW, 2 * H_, pbias, H_, 128);     // 2
    bias_redT_k<<<(B_ * H_) / 256, 256>>>(pbias, attb, bias_aT);                      // 3
    energy_mma_k<<<M_BT / 128, 512, SMEM_ENERGY>>>(eh, wh, bias_aT, v, scoresp);      // 4
    gather_emb_k<<<B_, 128>>>(x, embW, rnn_in);                                       // 5
    softmax_k<<<B_, 512>>>(scoresp, out_w);
    context_k<<<dim3(2, B_), 128>>>((const float4*)enc, out_w, rnn_in, cat2);
    gemm_m64_ks<<<dim3(3 * H_ / 64, 8), 256>>>(rnn_in, E_ + H_, Wih, E_ + H_, pgi, 3 * H_, 192);
    gemm_m64_ks<<<dim3(3 * H_ / 64, 8), 256>>>(lh, H_, Whh, H_, pgh, 3 * H_, 128);
    gates_k<<<B_, 256>>>(pgi, pgh, bih, bhh, lh, out_h, cat2);
    fc_mma_k<<<V_ / 128, 256, SMEM_FC>>>(cat2, fcW, fcb, out_logp);
    logsoftmax_k<<<B_, 1024>>>(out_logp);
}

// round 15
// speedup vs baseline: 2.0300x; 1.1340x over previous
#include <cuda_runtime.h>
#include <cuda_bf16.h>
#include <cuda_fp16.h>
#include <math.h>
#include <stdint.h>

#define B_ 64
#define T_ 512
#define H_ 1024
#define E_ 512
#define V_ 32000
#define M_BT (B_ * T_)        // 32768

// ---------------- scratch (device globals; no allocation allowed) ----------------
__device__ float g_rnn_in[B_ * (E_ + H_)];
__device__ float g_bias_aT[H_ * B_];
__device__ float g_scores[M_BT];
__device__ float g_cat2[B_ * 2 * H_];
__device__ float g_part_bias[8 * B_ * H_];
__device__ float g_part_gi[8 * B_ * 3 * H_];
__device__ float g_part_gh[8 * B_ * 3 * H_];
__device__ __half g_enc_h[(size_t)M_BT * H_];    // 64 MB fp16
__device__ __half g_w_h[H_ * H_];                // 2 MB fp16

// ======================= helpers =======================
__device__ __forceinline__ uint32_t smem_u32(const void* p) {
    uint32_t a;
    asm("{ .reg .u64 t; cvta.to.shared.u64 t, %1; cvt.u32.u64 %0, t; }" : "=r"(a) : "l"(p));
    return a;
}
#define CP_ASYNC16(dst, src) \
    asm volatile("cp.async.cg.shared.global [%0], [%1], 16;" :: "r"(dst), "l"(src))
#define CP_COMMIT() asm volatile("cp.async.commit_group;" ::: "memory")
#define CP_WAIT1() asm volatile("cp.async.wait_group 1;" ::: "memory")
#define CP_WAIT0() asm volatile("cp.async.wait_group 0;" ::: "memory")

__device__ __forceinline__ void ldmx4(uint32_t* r, uint32_t addr) {
    asm volatile("ldmatrix.sync.aligned.m8n8.x4.shared.b16 {%0,%1,%2,%3}, [%4];"
                 : "=r"(r[0]), "=r"(r[1]), "=r"(r[2]), "=r"(r[3]) : "r"(addr));
}
// fp16 mma
__device__ __forceinline__ void mma16816h(float* d, const uint32_t* a, uint32_t b0, uint32_t b1) {
    asm volatile("mma.sync.aligned.m16n8k16.row.col.f32.f16.f16.f32 "
                 "{%0,%1,%2,%3}, {%4,%5,%6,%7}, {%8,%9}, {%0,%1,%2,%3};"
                 : "+f"(d[0]), "+f"(d[1]), "+f"(d[2]), "+f"(d[3])
                 : "r"(a[0]), "r"(a[1]), "r"(a[2]), "r"(a[3]), "r"(b0), "r"(b1));
}
// fp32 quad -> fp16 quad
__device__ __forceinline__ uint2 cvt_h16(float4 x) {
    __align__(8) __half h[4];
    h[0] = __float2half_rn(x.x); h[1] = __float2half_rn(x.y);
    h[2] = __float2half_rn(x.z); h[3] = __float2half_rn(x.w);
    return *reinterpret_cast<uint2*>(h);
}

// ======================= tiling constants =======================
#define KSTEP 32
#define ROWB 80
// energy v7: fp16 1-pass, chunk=256 (32x64 warp tiles), KSTEP=64, 2-stage 2-barrier
#define EN_K 64
#define EN_ROWB 144
#define EN_A_T (128 * EN_ROWB)         // 18432
#define EN_B_T (256 * EN_ROWB)         // 36864
#define EN_STAGE (EN_A_T + EN_B_T)     // 55296
#define EN_RED_OFF (2 * EN_STAGE)      // 110592
#define SMEM_ENERGY (EN_RED_OFF + 512 * 4)   // 112640
// fc v2 (proven): fp16 1-pass, BN=128, inline fp32->fp16, 2 stages
#define FC_TA (64 * ROWB)              // 5120
#define FC_TB (128 * ROWB)             // 10240
#define FC_A 0
#define FC_B FC_TA
#define FC_STAGE (FC_TA + FC_TB)       // 15360
#define SMEM_FC (2 * FC_STAGE)         // 30720

#define ENC_BLOCKS ((M_BT * (H_ / 4)) / 256)   // 32768
#define W_BLOCKS ((H_ * (H_ / 4)) / 256)       // 1024

// ---------------- merged split: enc -> fp16, attn_W[:, H:] -> fp16 ----------------
__global__ void split_all_k(const float* __restrict__ enc,
                            const float* __restrict__ attnW,
                            __half* __restrict__ eh, __half* __restrict__ wh) {
    if (blockIdx.x < ENC_BLOCKS) {
        size_t i = (size_t)blockIdx.x * 256 + threadIdx.x;
        float4 x = reinterpret_cast<const float4*>(enc)[i];
        *reinterpret_cast<uint2*>(eh + 4 * i) = cvt_h16(x);
    } else {
        int i = (blockIdx.x - ENC_BLOCKS) * 256 + threadIdx.x;
        int r = i >> 8;
        int k4 = i & 255;
        float4 x = *(reinterpret_cast<const float4*>(attnW + (size_t)r * (2 * H_) + H_) + k4);
        *reinterpret_cast<uint2*>(wh + 4 * (size_t)i) = cvt_h16(x);
    }
}

// ---------------- embedding gather ----------------
__global__ void gather_emb_k(const int* __restrict__ x,
                             const float* __restrict__ embW,
                             float* __restrict__ rnn_in) {
    int b = blockIdx.x;
    int row = x[b];
    for (int e = threadIdx.x; e < E_; e += blockDim.x)
        rnn_in[b * (E_ + H_) + e] = embW[(size_t)row * E_ + e];
}

// ---------------- K-split M=64 GEMM ----------------
__global__ void gemm_m64_ks(const float* __restrict__ A, int lda,
                            const float* __restrict__ W, int ldw,
                            float* __restrict__ Cp, int ldc, int kc) {
    __shared__ float As[16][64];
    __shared__ float Ws[16][64];
    const int tid = threadIdx.x;
    const int n0 = blockIdx.x * 64;
    const int kk0 = blockIdx.y * kc;
    const int lrow = tid >> 2;
    const int kq = (tid & 3) * 4;
    const int ty = tid >> 4;
    const int tx = tid & 15;

    float acc[4][4] = {};
    for (int kk = kk0; kk < kk0 + kc; kk += 16) {
        float4 av = *(const float4*)&A[lrow * lda + kk + kq];
        float4 wv = *(const float4*)&W[(size_t)(n0 + lrow) * ldw + kk + kq];
        __syncthreads();
        As[kq + 0][lrow] = av.x; As[kq + 1][lrow] = av.y;
        As[kq + 2][lrow] = av.z; As[kq + 3][lrow] = av.w;
        Ws[kq + 0][lrow] = wv.x; Ws[kq + 1][lrow] = wv.y;
        Ws[kq + 2][lrow] = wv.z; Ws[kq + 3][lrow] = wv.w;
        __syncthreads();
        #pragma unroll
        for (int k = 0; k < 16; k++) {
            float4 a = *(const float4*)&As[k][ty * 4];
            float4 w = *(const float4*)&Ws[k][tx * 4];
            float af[4] = {a.x, a.y, a.z, a.w};
            float wf[4] = {w.x, w.y, w.z, w.w};
            #pragma unroll
            for (int i = 0; i < 4; i++)
                #pragma unroll
                for (int j = 0; j < 4; j++)
                    acc[i][j] = fmaf(af[i], wf[j], acc[i][j]);
        }
    }
    #pragma unroll
    for (int i = 0; i < 4; i++) {
        int m = blockIdx.y * 64 + ty * 4 + i;
        #pragma unroll
        for (int j = 0; j < 4; j++)
            Cp[(size_t)m * ldc + n0 + tx * 4 + j] = acc[i][j];
    }
}

// ---------------- bias partial reduce + transpose ----------------
__global__ void bias_redT_k(const float* __restrict__ part,
                            const float* __restrict__ attb,
                            float* __restrict__ biasT) {
    int idx = blockIdx.x * 256 + threadIdx.x;
    int b = idx >> 10, h = idx & 1023;
    float s = attb[h];
    #pragma unroll
    for (int ks = 0; ks < 8; ks++)
        s += part[(size_t)((ks << 6) + b) * H_ + h];
    biasT[h * B_ + b] = s;
}

// ---------------- energy GEMM v7: fp16 1-pass, chunk=256, 32x64 warp tiles ----------------
__global__ void __launch_bounds__(512, 1)
energy_mma_k(const __half* __restrict__ eh, const __half* __restrict__ wh,
             const float* __restrict__ biasT, const float* __restrict__ v,
             float* __restrict__ scores) {
    extern __shared__ char sm[];
    const uint32_t sb = smem_u32(sm);
    float* red = (float*)(sm + EN_RED_OFF);

    const int tid = threadIdx.x;
    const int wid = tid >> 5;
    const int lane = tid & 31;
    const int m0 = blockIdx.x * 128;
    const int mw = wid >> 2;       // 0..3: rows mw*32..+31
    const int nw = wid & 3;        // 0..3: cols nw*64..+63 within 256-col chunk

    const int a_l = lane & 15;
    const int a_kh = (lane >> 4) << 3;
    const int b_nb = (lane & 7) + ((lane >> 4) << 3);
    const int b_kh = ((lane >> 3) & 1) << 3;
    const int g = lane >> 2;
    const int t2 = (lane & 3) << 1;

    float acc[2][8][4];            // 64 regs: 2 m-tiles x 8 n-octets
    float rowsum[4];
    #pragma unroll
    for (int i = 0; i < 4; i++) rowsum[i] = 0.f;

    const int total_it = 4 * 16;   // 4 chunks of 256 cols, 16 k-tiles of 64
    // cp.async: A 1024 x 16B (2/thread), B 2048 x 16B (4/thread)
    const int ar[2] = {tid >> 3, (tid + 512) >> 3};
    const int br[4] = {tid >> 3, (tid + 512) >> 3, (tid + 1024) >> 3, (tid + 1536) >> 3};
    const int cp_c = tid & 7;

    #define EN_CP(it_) do {                                                          \
        int chunk_ = (it_) >> 4;                                                     \
        int kb_ = ((it_) & 15) * EN_K;                                               \
        uint32_t stg_ = sb + ((it_) & 1) * EN_STAGE;                                 \
        _Pragma("unroll")                                                            \
        for (int j = 0; j < 2; j++)                                                  \
            CP_ASYNC16(stg_ + (uint32_t)(ar[j] * EN_ROWB + cp_c * 16),               \
                       eh + (size_t)(m0 + ar[j]) * H_ + kb_ + cp_c * 8);             \
        _Pragma("unroll")                                                            \
        for (int j = 0; j < 4; j++)                                                  \
            CP_ASYNC16(stg_ + EN_A_T + (uint32_t)(br[j] * EN_ROWB + cp_c * 16),      \
                       wh + (size_t)(chunk_ * 256 + br[j]) * H_ + kb_ + cp_c * 8);   \
        CP_COMMIT();                                                                 \
    } while (0)

    EN_CP(0);

    for (int it = 0; it < total_it; it++) {
        const int kt = it & 15;
        const int chunk = it >> 4;
        if (kt == 0) {
            #pragma unroll
            for (int mt = 0; mt < 2; mt++)
                #pragma unroll
                for (int nt = 0; nt < 8; nt++)
                    #pragma unroll
                    for (int k = 0; k < 4; k++) acc[mt][nt][k] = 0.f;
        }
        __syncthreads();           // A-barrier: reads of stage (it+1)&1 (iter it-1) done
        if (it + 1 < total_it) { EN_CP(it + 1); CP_WAIT1(); }
        else { CP_WAIT0(); }
        __syncthreads();           // B-barrier: stage it&1 complete + visible

        const uint32_t stg = sb + (it & 1) * EN_STAGE;
        #pragma unroll
        for (int ks = 0; ks < 4; ks++) {
            uint32_t Ah[2][4];
            #pragma unroll
            for (int mt = 0; mt < 2; mt++) {
                uint32_t off = (uint32_t)((mw * 32 + mt * 16 + a_l) * EN_ROWB + (ks * 16 + a_kh) * 2);
                ldmx4(Ah[mt], stg + off);
            }
            uint32_t Bh[4][4];
            #pragma unroll
            for (int np = 0; np < 4; np++) {
                uint32_t off = (uint32_t)((nw * 64 + np * 16 + b_nb) * EN_ROWB + (ks * 16 + b_kh) * 2);
                ldmx4(Bh[np], stg + EN_A_T + off);
            }
            #pragma unroll
            for (int mt = 0; mt < 2; mt++)
                #pragma unroll
                for (int np = 0; np < 4; np++) {
                    mma16816h(acc[mt][np * 2 + 0], Ah[mt], Bh[np][0], Bh[np][1]);
                    mma16816h(acc[mt][np * 2 + 1], Ah[mt], Bh[np][2], Bh[np][3]);
                }
        }

        if (kt == 15) {
            #pragma unroll
            for (int nt = 0; nt < 8; nt++) {
                const int col0 = chunk * 256 + nw * 64 + nt * 8 + t2;
                const float v0 = __ldg(&v[col0]);
                const float v1 = __ldg(&v[col0 + 1]);
                #pragma unroll
                for (int mt = 0; mt < 2; mt++) {
                    #pragma unroll
                    for (int i = 0; i < 2; i++) {
                        const int row = mw * 32 + mt * 16 + g + i * 8;
                        const int b = row & (B_ - 1);
                        float e0 = acc[mt][nt][i * 2 + 0] + __ldg(&biasT[(size_t)col0 * B_ + b]);
                        float e1 = acc[mt][nt][i * 2 + 1] + __ldg(&biasT[(size_t)(col0 + 1) * B_ + b]);
                        rowsum[mt * 2 + i] += fmaxf(e0, 0.f) * v0 + fmaxf(e1, 0.f) * v1;
                    }
                }
            }
        }
    }

    #pragma unroll
    for (int k = 0; k < 4; k++) {
        rowsum[k] += __shfl_xor_sync(0xFFFFFFFF, rowsum[k], 1);
        rowsum[k] += __shfl_xor_sync(0xFFFFFFFF, rowsum[k], 2);
    }
    __syncthreads();
    if ((lane & 3) == 0) {
        #pragma unroll
        for (int mt = 0; mt < 2; mt++)
            #pragma unroll
            for (int i = 0; i < 2; i++)
                red[nw * 128 + mw * 32 + mt * 16 + g + i * 8] = rowsum[mt * 2 + i];
    }
    __syncthreads();
    if (tid < 128) {
        float s = red[tid] + red[128 + tid] + red[256 + tid] + red[384 + tid];
        scores[m0 + tid] = s;
    }
    #undef EN_CP
}

// ---------------- fc GEMM v2 (proven): fp16 1-pass, BN=128, occ 2 ----------------
__global__ void __launch_bounds__(256, 2)
fc_mma_k(const float* __restrict__ cat2, const float* __restrict__ fcW,
         const float* __restrict__ fcb, float* __restrict__ logits) {
    extern __shared__ char sm[];
    const uint32_t sb = smem_u32(sm);

    const int tid = threadIdx.x;
    const int wid = tid >> 5;
    const int lane = tid & 31;
    const int n0 = blockIdx.x * 128;
    const int mw = wid >> 2;
    const int nw = wid & 3;

    const int a_l = lane & 15;
    const int a_kh = (lane >> 4) << 3;
    const int b_nb = (lane & 7) + ((lane >> 4) << 3);
    const int b_kh = ((lane >> 3) & 1) << 3;
    const int g = lane >> 2;
    const int t2 = (lane & 3) << 1;

    float acc[2][4][4];
    #pragma unroll
    for (int mt = 0; mt < 2; mt++)
        #pragma unroll
        for (int nt = 0; nt < 4; nt++)
            #pragma unroll
            for (int k = 0; k < 4; k++) acc[mt][nt][k] = 0.f;

    const int aro[2] = {tid >> 3, (tid + 256) >> 3};
    const int bro[4] = {tid >> 3, (tid + 256) >> 3, (tid + 512) >> 3, (tid + 768) >> 3};
    const int qc = tid & 7;
    float4 Ar[2], Br[4];

    #define FC_LDG(it_) do {                                                        \
        int kb_ = (it_) * KSTEP;                                                    \
        _Pragma("unroll")                                                           \
        for (int j = 0; j < 2; j++)                                                 \
            Ar[j] = *(const float4*)&cat2[(size_t)aro[j] * (2 * H_) + kb_ + qc * 4];\
        _Pragma("unroll")                                                           \
        for (int j = 0; j < 4; j++)                                                 \
            Br[j] = *(const float4*)&fcW[(size_t)(n0 + bro[j]) * (2 * H_) + kb_ + qc * 4]; \
    } while (0)

    #define FC_STS(it_) do {                                                        \
        char* st_ = sm + ((it_) & 1) * FC_STAGE;                                    \
        _Pragma("unroll")                                                           \
        for (int j = 0; j < 2; j++)                                                 \
            *reinterpret_cast<uint2*>(st_ + FC_A + aro[j] * ROWB + qc * 8) = cvt_h16(Ar[j]); \
        _Pragma("unroll")                                                           \
        for (int j = 0; j < 4; j++)                                                 \
            *reinterpret_cast<uint2*>(st_ + FC_B + bro[j] * ROWB + qc * 8) = cvt_h16(Br[j]); \
    } while (0)

    const int total_it = 64;
    FC_LDG(0);

    for (int it = 0; it < total_it; it++) {
        __syncthreads();
        FC_STS(it);
        if (it + 1 < total_it) FC_LDG(it + 1);
        __syncthreads();

        const uint32_t stg = sb + (it & 1) * FC_STAGE;
        #pragma unroll
        for (int ks = 0; ks < 2; ks++) {
            uint32_t Ah[2][4];
            #pragma unroll
            for (int mt = 0; mt < 2; mt++) {
                uint32_t off = (uint32_t)((mw * 32 + mt * 16 + a_l) * ROWB + (ks * 16 + a_kh) * 2);
                ldmx4(Ah[mt], stg + FC_A + off);
            }
            uint32_t Bh[2][4];
            #pragma unroll
            for (int np = 0; np < 2; np++) {
                uint32_t off = (uint32_t)((nw * 32 + np * 16 + b_nb) * ROWB + (ks * 16 + b_kh) * 2);
                ldmx4(Bh[np], stg + FC_B + off);
            }
            #pragma unroll
            for (int mt = 0; mt < 2; mt++)
                #pragma unroll
                for (int nt = 0; nt < 4; nt++) {
                    const int np = nt >> 1, pr = (nt & 1) * 2;
                    mma16816h(acc[mt][nt], Ah[mt], Bh[np][pr], Bh[np][pr + 1]);
                }
        }
    }

    #pragma unroll
    for (int nt = 0; nt < 4; nt++) {
        const int col0 = n0 + nw * 32 + nt * 8 + t2;
        const float c0 = __ldg(&fcb[col0]);
        const float c1 = __ldg(&fcb[col0 + 1]);
        #pragma unroll
        for (int mt = 0; mt < 2; mt++) {
            #pragma unroll
            for (int i = 0; i < 2; i++) {
                const int row = mw * 32 + mt * 16 + g + i * 8;
                float2 o;
                o.x = acc[mt][nt][i * 2 + 0] + c0;
                o.y = acc[mt][nt][i * 2 + 1] + c1;
                *reinterpret_cast<float2*>(&logits[(size_t)row * V_ + col0]) = o;
            }
        }
    }
    #undef FC_LDG
    #undef FC_STS
}

// ---------------- softmax over T ----------------
__global__ void softmax_k(const float* __restrict__ scores,
                          float* __restrict__ attn_w_out) {
    int b = blockIdx.x;
    int t = threadIdx.x;
    __shared__ float sh[512];
    float s = scores[t * B_ + b];
    sh[t] = s;
    __syncthreads();
    for (int off = 256; off > 0; off >>= 1) {
        if (t < off) sh[t] = fmaxf(sh[t], sh[t + off]);
        __syncthreads();
    }
    float mx = sh[0];
    __syncthreads();
    float e = expf(s - mx);
    sh[t] = e;
    __syncthreads();
    for (int off = 256; off > 0; off >>= 1) {
        if (t < off) sh[t] += sh[t + off];
        __syncthreads();
    }
    attn_w_out[b * T_ + t] = e / sh[0];
}

// ---------------- context = attn_w @ enc (float4, unroll 8) ----------------
__global__ void context_k(const float4* __restrict__ enc4,
                          const float* __restrict__ attn_w,
                          float* __restrict__ rnn_in,
                          float* __restrict__ cat2) {
    int b = blockIdx.y;
    int h4 = blockIdx.x * 128 + threadIdx.x;
    __shared__ float w[T_];
    for (int t = threadIdx.x; t < T_; t += 128) w[t] = attn_w[b * T_ + t];
    __syncthreads();
    float4 acc = {0.f, 0.f, 0.f, 0.f};
    #pragma unroll 8
    for (int t = 0; t < T_; t++) {
        float4 e = enc4[(size_t)(t * B_ + b) * (H_ / 4) + h4];
        float wt = w[t];
        acc.x = fmaf(wt, e.x, acc.x);
        acc.y = fmaf(wt, e.y, acc.y);
        acc.z = fmaf(wt, e.z, acc.z);
        acc.w = fmaf(wt, e.w, acc.w);
    }
    int h = h4 * 4;
    *reinterpret_cast<float4*>(&rnn_in[b * (E_ + H_) + E_ + h]) = acc;
    *reinterpret_cast<float4*>(&cat2[b * (2 * H_) + H_ + h]) = acc;
}

// ---------------- GRU gates (reduce 8 k-split partials) ----------------
__global__ void gates_k(const float* __restrict__ pgi,
                        const float* __restrict__ pgh,
                        const float* __restrict__ bih,
                        const float* __restrict__ bhh,
                        const float* __restrict__ lh,
                        float* __restrict__ hnew_out,
                        float* __restrict__ cat2) {
    int b = blockIdx.x;
    for (int h = threadIdx.x; h < H_; h += blockDim.x) {
        float gi0 = bih[h], gi1 = bih[H_ + h], gi2 = bih[2 * H_ + h];
        float gh0 = bhh[h], gh1 = bhh[H_ + h], gh2 = bhh[2 * H_ + h];
        #pragma unroll
        for (int ks = 0; ks < 8; ks++) {
            size_t base = (size_t)((ks << 6) + b) * 3 * H_;
            gi0 += pgi[base + h]; gi1 += pgi[base + H_ + h]; gi2 += pgi[base + 2 * H_ + h];
            gh0 += pgh[base + h]; gh1 += pgh[base + H_ + h]; gh2 += pgh[base + 2 * H_ + h];
        }
        float r = 1.f / (1.f + expf(-(gi0 + gh0)));
        float z = 1.f / (1.f + expf(-(gi1 + gh1)));
        float n = tanhf(gi2 + r * gh2);
        float hp = lh[b * H_ + h];
        float hn = (1.f - z) * n + z * hp;
        hnew_out[b * H_ + h] = hn;
        cat2[b * (2 * H_) + h] = hn;
    }
}

// ---------------- log_softmax in-place ----------------
__global__ void logsoftmax_k(float* __restrict__ logits) {
    int b = blockIdx.x;
    int tid = threadIdx.x;
    __shared__ float sh[1024];
    float* row = logits + (size_t)b * V_;
    float mx = -1e30f;
    for (int n = tid; n < V_; n += 1024) mx = fmaxf(mx, row[n]);
    sh[tid] = mx;
    __syncthreads();
    for (int off = 512; off > 0; off >>= 1) {
        if (tid < off) sh[tid] = fmaxf(sh[tid], sh[tid + off]);
        __syncthreads();
    }
    mx = sh[0];
    __syncthreads();
    float sum = 0.f;
    for (int n = tid; n < V_; n += 1024) sum += expf(row[n] - mx);
    sh[tid] = sum;
    __syncthreads();
    for (int off = 512; off > 0; off >>= 1) {
        if (tid < off) sh[tid] += sh[tid + off];
        __syncthreads();
    }
    float lse = mx + logf(sh[0]);
    for (int n = tid; n < V_; n += 1024) row[n] -= lse;
}

// ---------------- launch ----------------
extern "C" void kernel_launch(void* const* d_in, const int* in_sizes, int n_in,
                              void* d_out, int out_size) {
    const int*   x    = (const int*)d_in[0];
    const float* lh   = (const float*)d_in[1];
    const float* enc  = (const float*)d_in[2];
    const float* embW = (const float*)d_in[3];
    const float* attW = (const float*)d_in[4];
    const float* attb = (const float*)d_in[5];
    const float* v    = (const float*)d_in[6];
    const float* Wih  = (const float*)d_in[7];
    const float* Whh  = (const float*)d_in[8];
    const float* bih  = (const float*)d_in[9];
    const float* bhh  = (const float*)d_in[10];
    const float* fcW  = (const float*)d_in[11];
    const float* fcb  = (const float*)d_in[12];

    float* out      = (float*)d_out;
    float* out_logp = out;
    float* out_h    = out + (size_t)B_ * V_;
    float* out_w    = out_h + (size_t)B_ * H_;

    float *rnn_in, *bias_aT, *scoresp, *cat2, *pbias, *pgi, *pgh;
    __half *eh, *wh;
    cudaGetSymbolAddress((void**)&rnn_in,  g_rnn_in);
    cudaGetSymbolAddress((void**)&bias_aT, g_bias_aT);
    cudaGetSymbolAddress((void**)&scoresp, g_scores);
    cudaGetSymbolAddress((void**)&cat2,    g_cat2);
    cudaGetSymbolAddress((void**)&pbias,   g_part_bias);
    cudaGetSymbolAddress((void**)&pgi,     g_part_gi);
    cudaGetSymbolAddress((void**)&pgh,     g_part_gh);
    cudaGetSymbolAddress((void**)&eh,      g_enc_h);
    cudaGetSymbolAddress((void**)&wh,      g_w_h);

    cudaFuncSetAttribute(energy_mma_k, cudaFuncAttributeMaxDynamicSharedMemorySize, SMEM_ENERGY);
    cudaFuncSetAttribute(fc_mma_k, cudaFuncAttributeMaxDynamicSharedMemorySize, SMEM_FC);

    // launch order: energy_mma_k stays launch #4 (ncu captures the 4th launch)
    split_all_k<<<ENC_BLOCKS + W_BLOCKS, 256>>>(enc, attW, eh, wh);                   // 1
    gemm_m64_ks<<<dim3(H_ / 64, 8), 256>>>(lh, H_, attW, 2 * H_, pbias, H_, 128);     // 2
    bias_redT_k<<<(B_ * H_) / 256, 256>>>(pbias, attb, bias_aT);                      // 3
    energy_mma_k<<<M_BT / 128, 512, SMEM_ENERGY>>>(eh, wh, bias_aT, v, scoresp);      // 4
    gather_emb_k<<<B_, 128>>>(x, embW, rnn_in);                                       // 5
    softmax_k<<<B_, 512>>>(scoresp, out_w);
    context_k<<<dim3(2, B_), 128>>>((const float4*)enc, out_w, rnn_in, cat2);
    gemm_m64_ks<<<dim3(3 * H_ / 64, 8), 256>>>(rnn_in, E_ + H_, Wih, E_ + H_, pgi, 3 * H_, 192);
    gemm_m64_ks<<<dim3(3 * H_ / 64, 8), 256>>>(lh, H_, Whh, H_, pgh, 3 * H_, 128);
    gates_k<<<B_, 256>>>(pgi, pgh, bih, bhh, lh, out_h, cat2);
    fc_mma_k<<<V_ / 128, 256, SMEM_FC>>>(cat2, fcW, fcb, out_logp);
    logsoftmax_k<<<B_, 1024>>>(out_logp);
}